// round 8
// baseline (speedup 1.0000x reference)
#include <cuda_runtime.h>
#include <cuda_fp16.h>
#include <cstdint>

#define BN_EPS 1e-5f

// ================= persistent scratch (device globals; no allocations) ==========
__device__ float d_h1[8192 * 64];
__device__ __half d_h1h[8192 * 64], d_h1l[8192 * 64];
__device__ float d_h2[8192 * 256];
__device__ __half d_h2h[8192 * 256], d_h2l[8192 * 256];
__device__ __half d_l0h[8192 * 512], d_l0l[8192 * 512];   // l0 fp16 pair
__device__ int   d_idx[8192 * 8];
__device__ float d_Q[8192 * 1024];
__device__ float d_R[8192 * 1024];
__device__ float d_mx[8192 * 1024];                   // raw max-over-k scratch
__device__ __half d_Ah[65536 * 1024];                 // fp16 hi (expanded)
__device__ __half d_Al[65536 * 1024];                 // fp16 lo (expanded; A-local_op only)
__device__ __half d_W2h[256 * 64],     d_W2l[256 * 64];
__device__ __half d_WA1h[512 * 512],   d_WA1l[512 * 512];
__device__ __half d_WA2h[512 * 512],   d_WA2l[512 * 512];
__device__ __half d_WB1h[1024 * 1024], d_WB1l[1024 * 1024];
__device__ __half d_WB2h[1024 * 1024], d_WB2l[1024 * 1024];
__device__ float d_sum[1024];
__device__ float d_ss[1024];

// ================= PTX helpers (arch-neutral, sm_80+) ===========================
__device__ __forceinline__ uint32_t smem_u32(const void* p) {
    uint32_t a;
    asm("{ .reg .u64 t; cvta.to.shared.u64 t, %1; cvt.u32.u64 %0, t; }" : "=r"(a) : "l"(p));
    return a;
}
__device__ __forceinline__ void cpa16(uint32_t s, const void* g) {
    asm volatile("cp.async.cg.shared.global [%0], [%1], 16;" :: "r"(s), "l"(g));
}
#define CP_COMMIT() asm volatile("cp.async.commit_group;" ::: "memory")
#define CP_WAIT0()  asm volatile("cp.async.wait_group 0;" ::: "memory")
#define CP_WAIT1()  asm volatile("cp.async.wait_group 1;" ::: "memory")

#define LDSM4(r0, r1, r2, r3, a) \
    asm volatile("ldmatrix.sync.aligned.m8n8.x4.shared.b16 {%0,%1,%2,%3}, [%4];" \
                 : "=r"(r0), "=r"(r1), "=r"(r2), "=r"(r3) : "r"(a))

#define MMA16816(c, a, b) \
    asm volatile("mma.sync.aligned.m16n8k16.row.col.f32.f16.f16.f32 " \
                 "{%0,%1,%2,%3}, {%4,%5,%6,%7}, {%8,%9}, {%0,%1,%2,%3};" \
                 : "+f"((c)[0]), "+f"((c)[1]), "+f"((c)[2]), "+f"((c)[3]) \
                 : "r"((a)[0]), "r"((a)[1]), "r"((a)[2]), "r"((a)[3]), \
                   "r"((b)[0]), "r"((b)[1]))

// ================= HMMA split-fp16 GEMM =========================================
// USE_ALO=true : C = Ah*Bh + Ah*Bl + Al*Bh   (3 products, ~1e-6 rel)
// USE_ALO=false: C = Ah*Bh + Ah*Bl           (2 products, ~2e-4 rel; Al never read)
// CTA tile 128(M) x 256(N), BK=32, 3-stage cp.async pipeline.
// 8 warps, 2(m) x 4(n) grid of 64x64 warp tiles.
// Modes: maxout != nullptr -> fused raw max over k=8 groups (no C write) + stats.
#define GBK 32
#define GA_LO  10240u                 // Al offset   (A: 128 * 80 B)
#define GB_HI  20480u                 // Bh offset
#define GB_LO  40960u                 // Bl offset   (B: 256 * 80 B)
#define GSTAGE 61440u
#define GSMEM_DYN 184320

template <bool USE_ALO>
__device__ __forceinline__ void g_load_stage(uint32_t st,
        const __half* __restrict__ Ah, const __half* __restrict__ Al, int lda,
        const __half* __restrict__ Bh, const __half* __restrict__ Bl, int ldb,
        int bm, int bn, int kc, int tid) {
#pragma unroll
    for (int t = 0; t < 2; t++) {                 // A: 512 chunks of 16B
        int i = tid + t * 256;
        int row = i >> 2, cg = i & 3;
        uint32_t off = (uint32_t)(row * 80 + cg * 16);
        size_t ga = (size_t)(bm + row) * lda + kc + cg * 8;
        cpa16(st + off, Ah + ga);
        if (USE_ALO) cpa16(st + GA_LO + off, Al + ga);
    }
#pragma unroll
    for (int t = 0; t < 4; t++) {                 // B: 1024 chunks of 16B (hi & lo)
        int i = tid + t * 256;
        int row = i >> 2, cg = i & 3;
        uint32_t off = (uint32_t)(row * 80 + cg * 16);
        size_t gb = (size_t)(bn + row) * ldb + kc + cg * 8;
        cpa16(st + GB_HI + off, Bh + gb);
        cpa16(st + GB_LO + off, Bl + gb);
    }
}

template <bool USE_ALO>
__global__ void __launch_bounds__(256, 1)
gemm_hmma_kernel(const __half* __restrict__ Ah, const __half* __restrict__ Al, int lda,
                 const __half* __restrict__ Bh, const __half* __restrict__ Bl, int ldb,
                 float* __restrict__ C, float* __restrict__ maxout, int ldc, int K,
                 float* __restrict__ gsum, float* __restrict__ gss) {
    extern __shared__ char smem[];
    __shared__ float s_sum[256], s_ss[256];
    const int tid = threadIdx.x;
    const int lane = tid & 31, wid = tid >> 5;
    const int wm = wid & 1, wn = wid >> 1;           // 2 x 4 warp grid, 64x64 tiles
    const int bm = blockIdx.y * 128, bn = blockIdx.x * 256;
    const uint32_t sb = smem_u32(smem);

    if (gsum) { s_sum[tid] = 0.f; s_ss[tid] = 0.f; }

    float acc[4][8][4];
#pragma unroll
    for (int i = 0; i < 4; i++)
#pragma unroll
        for (int j = 0; j < 8; j++)
#pragma unroll
            for (int v = 0; v < 4; v++) acc[i][j][v] = 0.f;

    // ldmatrix base addresses
    const uint32_t a_off = (uint32_t)((wm * 64 + (lane & 15)) * 80 + (lane >> 4) * 16);
    const int b_n = wn * 64 + (lane & 7) + ((lane >> 4) << 3);
    const uint32_t b_koff = (uint32_t)(((lane >> 3) & 1) * 16);

    const int NC = K / GBK;

    g_load_stage<USE_ALO>(sb, Ah, Al, lda, Bh, Bl, ldb, bm, bn, 0, tid);
    CP_COMMIT();
    if (NC > 1) {
        g_load_stage<USE_ALO>(sb + GSTAGE, Ah, Al, lda, Bh, Bl, ldb, bm, bn, GBK, tid);
        CP_COMMIT();
    }

    for (int c = 0; c < NC; c++) {
        if (c + 1 < NC) CP_WAIT1(); else CP_WAIT0();
        __syncthreads();
        if (c + 2 < NC) {
            g_load_stage<USE_ALO>(sb + (uint32_t)((c + 2) % 3) * GSTAGE, Ah, Al, lda,
                                  Bh, Bl, ldb, bm, bn, (c + 2) * GBK, tid);
            CP_COMMIT();
        }
        uint32_t st = sb + (uint32_t)(c % 3) * GSTAGE;
#pragma unroll
        for (int kk = 0; kk < 2; kk++) {              // two k16 steps in BK=32
            uint32_t kb = (uint32_t)(kk * 32);        // bytes
            uint32_t bh[8][2], bl[8][2];
#pragma unroll
            for (int p = 0; p < 4; p++) {
                uint32_t ba = st + GB_HI + (uint32_t)((b_n + p * 16) * 80) + b_koff + kb;
                LDSM4(bh[2 * p][0], bh[2 * p][1], bh[2 * p + 1][0], bh[2 * p + 1][1], ba);
                LDSM4(bl[2 * p][0], bl[2 * p][1], bl[2 * p + 1][0], bl[2 * p + 1][1],
                      ba + (GB_LO - GB_HI));
            }
#pragma unroll
            for (int mt = 0; mt < 4; mt++) {
                uint32_t ah[4], al[4];
                uint32_t aa = st + a_off + (uint32_t)(mt * 16 * 80) + kb;
                LDSM4(ah[0], ah[1], ah[2], ah[3], aa);
                if (USE_ALO) LDSM4(al[0], al[1], al[2], al[3], aa + GA_LO);
#pragma unroll
                for (int nt = 0; nt < 8; nt++) {
                    MMA16816(acc[mt][nt], ah, bh[nt]);
                    MMA16816(acc[mt][nt], ah, bl[nt]);
                    if (USE_ALO) MMA16816(acc[mt][nt], al, bh[nt]);
                }
            }
        }
    }

    // ---------------- epilogue -------------------------------------------------
    if (maxout) {
#pragma unroll
        for (int mt = 0; mt < 4; mt++) {
            int gA = (bm + wm * 64 + mt * 16) >> 3;   // output group rows gA, gA+1
#pragma unroll
            for (int nt = 0; nt < 8; nt++) {
                float m0 = acc[mt][nt][0], m1 = acc[mt][nt][1];
                float m2 = acc[mt][nt][2], m3 = acc[mt][nt][3];
#pragma unroll
                for (int off = 4; off < 32; off <<= 1) {
                    m0 = fmaxf(m0, __shfl_xor_sync(0xFFFFFFFFu, m0, off));
                    m1 = fmaxf(m1, __shfl_xor_sync(0xFFFFFFFFu, m1, off));
                    m2 = fmaxf(m2, __shfl_xor_sync(0xFFFFFFFFu, m2, off));
                    m3 = fmaxf(m3, __shfl_xor_sync(0xFFFFFFFFu, m3, off));
                }
                if (lane < 4) {
                    int col = bn + wn * 64 + nt * 8 + lane * 2;
                    float2 v0 = { m0, m1 }, v1 = { m2, m3 };
                    *(float2*)(maxout + (size_t)gA * ldc + col) = v0;
                    *(float2*)(maxout + (size_t)(gA + 1) * ldc + col) = v1;
                }
            }
        }
    } else {
#pragma unroll
        for (int mt = 0; mt < 4; mt++) {
            int row = bm + wm * 64 + mt * 16 + (lane >> 2);
#pragma unroll
            for (int nt = 0; nt < 8; nt++) {
                int col = bn + wn * 64 + nt * 8 + (lane & 3) * 2;
                float2 v0 = { acc[mt][nt][0], acc[mt][nt][1] };
                float2 v1 = { acc[mt][nt][2], acc[mt][nt][3] };
                *(float2*)(C + (size_t)row * ldc + col) = v0;
                *(float2*)(C + (size_t)(row + 8) * ldc + col) = v1;
            }
        }
    }
    if (gsum) {
#pragma unroll
        for (int nt = 0; nt < 8; nt++) {
            float se = 0.f, so = 0.f, qe = 0.f, qo = 0.f;
#pragma unroll
            for (int mt = 0; mt < 4; mt++) {
                float e0 = acc[mt][nt][0], e1 = acc[mt][nt][1];
                float e2 = acc[mt][nt][2], e3 = acc[mt][nt][3];
                se += e0 + e2; so += e1 + e3;
                qe += e0 * e0 + e2 * e2; qo += e1 * e1 + e3 * e3;
            }
#pragma unroll
            for (int off = 4; off < 32; off <<= 1) {
                se += __shfl_xor_sync(0xFFFFFFFFu, se, off);
                so += __shfl_xor_sync(0xFFFFFFFFu, so, off);
                qe += __shfl_xor_sync(0xFFFFFFFFu, qe, off);
                qo += __shfl_xor_sync(0xFFFFFFFFu, qo, off);
            }
            if (lane < 4) {
                int cl = wn * 64 + nt * 8 + lane * 2;
                atomicAdd(&s_sum[cl], se);     atomicAdd(&s_sum[cl + 1], so);
                atomicAdd(&s_ss[cl], qe);      atomicAdd(&s_ss[cl + 1], qo);
            }
        }
        __syncthreads();
        atomicAdd(&gsum[bn + tid], s_sum[tid]);
        atomicAdd(&gss[bn + tid], s_ss[tid]);
    }
}

// ================= small elementwise / stats kernels ============================
__global__ void lin1_kernel(const float* __restrict__ xyz, const float* __restrict__ W1,
                            float* __restrict__ out) {
    int t = blockIdx.x * blockDim.x + threadIdx.x;
    int r = t >> 6, o = t & 63;
    float x0 = xyz[r * 3 + 0], x1 = xyz[r * 3 + 1], x2 = xyz[r * 3 + 2];
    out[t] = x0 * W1[o * 3 + 0] + x1 * W1[o * 3 + 1] + x2 * W1[o * 3 + 2];
}

__global__ void zero_stats_kernel(float* __restrict__ s, float* __restrict__ q) {
    int t = blockIdx.x * blockDim.x + threadIdx.x;
    if (t < 1024) { s[t] = 0.f; q[t] = 0.f; }
}

__global__ void colstats_kernel(const float* __restrict__ x, int M, int C,
                                float* __restrict__ sum, float* __restrict__ ss) {
    int c = blockIdx.y * blockDim.x + threadIdx.x;
    if (c >= C) return;
    size_t r0 = (size_t)blockIdx.x * 512;
    const float* p = x + r0 * C + c;
    float s = 0.f, q = 0.f;
    for (int r = 0; r < 512; r++) { float v = p[(size_t)r * C]; s += v; q += v * v; }
    atomicAdd(&sum[c], s);
    atomicAdd(&ss[c], q);
}

__device__ __forceinline__ uint32_t pk_h2(float a, float b) {
    __half2 t = __floats2half2_rn(a, b);
    return *(uint32_t*)&t;
}

// BN + ReLU + hi/lo fp16 split (reads fp32 once, writes fp16 pair).
__global__ void bnrelu_split_kernel(const float* __restrict__ x,
                                    const float* __restrict__ sum, const float* __restrict__ ss,
                                    const float* __restrict__ g, const float* __restrict__ bta,
                                    __half* __restrict__ hi, __half* __restrict__ lo,
                                    int Mstat, int Mrows, int C) {
    int t = blockIdx.x * blockDim.x + threadIdx.x;
    int C4 = C >> 2;
    if (t >= Mrows * C4) return;
    int c = (t % C4) << 2;
    float invM = 1.0f / (float)Mstat;
    float4 v = ((const float4*)x)[t];
    float vv[4] = { v.x, v.y, v.z, v.w };
    float o[4];
#pragma unroll
    for (int i = 0; i < 4; i++) {
        float m = sum[c + i] * invM;
        float var = ss[c + i] * invM - m * m;
        float sc = g[c + i] * rsqrtf(var + BN_EPS);
        o[i] = fmaxf((vv[i] - m) * sc + bta[c + i], 0.f);
    }
    float h[4];
#pragma unroll
    for (int i = 0; i < 4; i++) h[i] = __half2float(__float2half_rn(o[i]));
    uint2 H = { pk_h2(o[0], o[1]), pk_h2(o[2], o[3]) };
    uint2 L = { pk_h2(o[0] - h[0], o[1] - h[1]), pk_h2(o[2] - h[2], o[3] - h[3]) };
    ((uint2*)hi)[t] = H;
    ((uint2*)lo)[t] = L;
}

// plain hi/lo split (weights)
__global__ void split_kernel(const float* __restrict__ x,
                             __half* __restrict__ hi, __half* __restrict__ lo, int n4) {
    int t = blockIdx.x * blockDim.x + threadIdx.x;
    if (t >= n4) return;
    float4 v = ((const float4*)x)[t];
    float o[4] = { v.x, v.y, v.z, v.w };
    float h[4];
#pragma unroll
    for (int i = 0; i < 4; i++) h[i] = __half2float(__float2half_rn(o[i]));
    uint2 H = { pk_h2(o[0], o[1]), pk_h2(o[2], o[3]) };
    uint2 L = { pk_h2(o[0] - h[0], o[1] - h[1]), pk_h2(o[2] - h[2], o[3] - h[3]) };
    ((uint2*)hi)[t] = H;
    ((uint2*)lo)[t] = L;
}

// kNN: k=8 smallest (stable ties, matches top_k(-d2))
__global__ void knn_kernel(const float* __restrict__ xyz, int* __restrict__ idx) {
    __shared__ float sx[1024], sy[1024], sz[1024], sq[1024];
    int b = blockIdx.y, tid = threadIdx.x;
    for (int i = tid; i < 1024; i += 256) {
        float x = xyz[((b << 10) + i) * 3 + 0];
        float y = xyz[((b << 10) + i) * 3 + 1];
        float z = xyz[((b << 10) + i) * 3 + 2];
        sx[i] = x; sy[i] = y; sz[i] = z;
        sq[i] = x * x + y * y + z * z;
    }
    __syncthreads();
    int n = blockIdx.x * 256 + tid;
    float qx = sx[n], qy = sy[n], qz = sz[n], qs = sq[n];
    float bd[8]; int bi[8];
#pragma unroll
    for (int j = 0; j < 8; j++) { bd[j] = 3.4e38f; bi[j] = 0; }
    for (int m = 0; m < 1024; m++) {
        float d2 = qs + sq[m] - 2.f * (qx * sx[m] + qy * sy[m] + qz * sz[m]);
        if (d2 < bd[7]) {
            bd[7] = d2; bi[7] = m;
#pragma unroll
            for (int j = 7; j > 0; j--) {
                if (bd[j] < bd[j - 1]) {
                    float td = bd[j]; bd[j] = bd[j - 1]; bd[j - 1] = td;
                    int ti = bi[j]; bi[j] = bi[j - 1]; bi[j - 1] = ti;
                }
            }
        }
    }
#pragma unroll
    for (int j = 0; j < 8; j++) idx[((b << 10) + n) * 8 + j] = bi[j];
}

// expand stats only (no materialization): o = Q[idx]-Qc+Rc, column sum/sumsq.
// grid: (65536/256, C4/128), block 128.
__global__ void expand_stats_kernel(const float4* __restrict__ Q, const float4* __restrict__ R,
                                    const int* __restrict__ idx, int C4,
                                    float* __restrict__ gsum, float* __restrict__ gss) {
    __shared__ int sidx[256];
    int c4 = blockIdx.y * 128 + threadIdx.x;
    int r0 = blockIdx.x * 256;
    for (int i = threadIdx.x; i < 256; i += 128) sidx[i] = idx[r0 + i];
    __syncthreads();
    int bn0 = r0 >> 3;
    int b = bn0 >> 10;
    float s[4] = {0.f, 0.f, 0.f, 0.f}, q[4] = {0.f, 0.f, 0.f, 0.f};
    for (int gg = 0; gg < 32; gg++) {
        int bn = bn0 + gg;
        float4 qc = Q[(size_t)bn * C4 + c4];
        float4 rr = R[(size_t)bn * C4 + c4];
        float bx = rr.x - qc.x, by = rr.y - qc.y, bz = rr.z - qc.z, bw = rr.w - qc.w;
#pragma unroll
        for (int k = 0; k < 8; k++) {
            int src = (b << 10) + sidx[gg * 8 + k];
            float4 qa = Q[(size_t)src * C4 + c4];
            float ox = qa.x + bx, oy = qa.y + by, oz = qa.z + bz, ow = qa.w + bw;
            s[0] += ox; s[1] += oy; s[2] += oz; s[3] += ow;
            q[0] += ox * ox; q[1] += oy * oy; q[2] += oz * oz; q[3] += ow * ow;
        }
    }
    int c = c4 << 2;
#pragma unroll
    for (int i = 0; i < 4; i++) { atomicAdd(&gsum[c + i], s[i]); atomicAdd(&gss[c + i], q[i]); }
}

// expand recompute + BN + ReLU + fp16 split (WRITE_LO=false -> hi only).
template <bool WRITE_LO>
__global__ void expand_bnrelu_split_kernel(
        const float4* __restrict__ Q, const float4* __restrict__ R,
        const int* __restrict__ idx, int C4,
        const float* __restrict__ sum, const float* __restrict__ ss,
        const float* __restrict__ g, const float* __restrict__ bta,
        __half* __restrict__ hi, __half* __restrict__ lo) {
    __shared__ int sidx[256];
    int c4 = blockIdx.y * 128 + threadIdx.x;
    int r0 = blockIdx.x * 256;
    for (int i = threadIdx.x; i < 256; i += 128) sidx[i] = idx[r0 + i];
    __syncthreads();
    int bn0 = r0 >> 3;
    int b = bn0 >> 10;
    const float invM = 1.0f / 65536.0f;
    int c = c4 << 2;
    float m[4], sc[4], bb[4];
#pragma unroll
    for (int i = 0; i < 4; i++) {
        m[i] = sum[c + i] * invM;
        float var = ss[c + i] * invM - m[i] * m[i];
        sc[i] = g[c + i] * rsqrtf(var + BN_EPS);
        bb[i] = bta[c + i];
    }
    for (int gg = 0; gg < 32; gg++) {
        int bn = bn0 + gg;
        float4 qc = Q[(size_t)bn * C4 + c4];
        float4 rr = R[(size_t)bn * C4 + c4];
        float bx = rr.x - qc.x, by = rr.y - qc.y, bz = rr.z - qc.z, bw = rr.w - qc.w;
#pragma unroll
        for (int k = 0; k < 8; k++) {
            int row = bn * 8 + k;
            int src = (b << 10) + sidx[gg * 8 + k];
            float4 qa = Q[(size_t)src * C4 + c4];
            float o[4] = { qa.x + bx, qa.y + by, qa.z + bz, qa.w + bw };
            float h[4];
#pragma unroll
            for (int i = 0; i < 4; i++) {
                o[i] = fmaxf((o[i] - m[i]) * sc[i] + bb[i], 0.f);
                h[i] = __half2float(__float2half_rn(o[i]));
            }
            uint2 H = { pk_h2(o[0], o[1]), pk_h2(o[2], o[3]) };
            ((uint2*)hi)[(size_t)row * C4 + c4] = H;
            if (WRITE_LO) {
                uint2 L = { pk_h2(o[0] - h[0], o[1] - h[1]),
                            pk_h2(o[2] - h[2], o[3] - h[3]) };
                ((uint2*)lo)[(size_t)row * C4 + c4] = L;
            }
        }
    }
}

// finish: BN+ReLU of raw max (stats over 65536 raw rows) -> fp16 split (l0)
__global__ void finish_split_kernel(const float* __restrict__ mx,
                                    const float* __restrict__ sum, const float* __restrict__ ss,
                                    const float* __restrict__ g, const float* __restrict__ bta,
                                    __half* __restrict__ hi, __half* __restrict__ lo, int C) {
    int t = blockIdx.x * blockDim.x + threadIdx.x;
    int C4 = C >> 2;
    if (t >= 8192 * C4) return;
    int c = (t % C4) << 2;
    const float invM = 1.0f / 65536.0f;
    float4 v = ((const float4*)mx)[t];
    float vv[4] = { v.x, v.y, v.z, v.w };
    float o[4], h[4];
#pragma unroll
    for (int i = 0; i < 4; i++) {
        float m = sum[c + i] * invM;
        float var = ss[c + i] * invM - m * m;
        float sc = g[c + i] * rsqrtf(var + BN_EPS);
        o[i] = fmaxf((vv[i] - m) * sc + bta[c + i], 0.f);
        h[i] = __half2float(__float2half_rn(o[i]));
    }
    uint2 H = { pk_h2(o[0], o[1]), pk_h2(o[2], o[3]) };
    uint2 L = { pk_h2(o[0] - h[0], o[1] - h[1]), pk_h2(o[2] - h[2], o[3] - h[3]) };
    ((uint2*)hi)[t] = H;
    ((uint2*)lo)[t] = L;
}

// finish: BN+ReLU of raw max + transpose to (B, C, N). C=1024.
// grid (32, 32, 8), block (32,8)
__global__ void finish_out_t_kernel(const float* __restrict__ mx,
                                    const float* __restrict__ sum, const float* __restrict__ ss,
                                    const float* __restrict__ g, const float* __restrict__ bta,
                                    float* __restrict__ out) {
    __shared__ float tile[32][33];
    int b = blockIdx.z;
    int n0 = blockIdx.x * 32;
    int c0 = blockIdx.y * 32;
    int c = c0 + threadIdx.x;
    const float invM = 1.0f / 65536.0f;
    float m = sum[c] * invM;
    float var = ss[c] * invM - m * m;
    float sc = g[c] * rsqrtf(var + BN_EPS);
    float bb = bta[c];
#pragma unroll
    for (int j = 0; j < 4; j++) {
        int nl = threadIdx.y + j * 8;
        int bn = (b << 10) + n0 + nl;
        float v = mx[(size_t)bn * 1024 + c];
        tile[threadIdx.x][nl] = fmaxf((v - m) * sc + bb, 0.f);
    }
    __syncthreads();
#pragma unroll
    for (int j = 0; j < 4; j++) {
        int cl = threadIdx.y + j * 8;
        out[((size_t)b * 1024 + c0 + cl) * 1024 + n0 + threadIdx.x] = tile[cl][threadIdx.x];
    }
}

// ================= host orchestration ===========================================
extern "C" void kernel_launch(void* const* d_in, const int* in_sizes, int n_in,
                              void* d_out, int out_size) {
    const float* xyz = (const float*)d_in[0];
    const float* W1  = (const float*)d_in[1];
    const float* g1  = (const float*)d_in[2];
    const float* b1  = (const float*)d_in[3];
    const float* W2  = (const float*)d_in[4];
    const float* g2  = (const float*)d_in[5];
    const float* b2  = (const float*)d_in[6];
    const float* WA1 = (const float*)d_in[7];
    const float* gA1 = (const float*)d_in[8];
    const float* bA1 = (const float*)d_in[9];
    const float* WA2 = (const float*)d_in[10];
    const float* gA2 = (const float*)d_in[11];
    const float* bA2 = (const float*)d_in[12];
    const float* WB1 = (const float*)d_in[13];
    const float* gB1 = (const float*)d_in[14];
    const float* bB1 = (const float*)d_in[15];
    const float* WB2 = (const float*)d_in[16];
    const float* gB2 = (const float*)d_in[17];
    const float* bB2 = (const float*)d_in[18];
    float* out = (float*)d_out;

    float *h1, *h2, *Q, *R, *mx, *sumb, *ssb;
    __half *h1h, *h1l, *h2h, *h2l, *l0h, *l0l, *Ah, *Al;
    __half *W2h, *W2l, *WA1h, *WA1l, *WA2h, *WA2l, *WB1h, *WB1l, *WB2h, *WB2l;
    int* idx;
    cudaGetSymbolAddress((void**)&h1, d_h1);   cudaGetSymbolAddress((void**)&h1h, d_h1h);
    cudaGetSymbolAddress((void**)&h1l, d_h1l); cudaGetSymbolAddress((void**)&h2, d_h2);
    cudaGetSymbolAddress((void**)&h2h, d_h2h); cudaGetSymbolAddress((void**)&h2l, d_h2l);
    cudaGetSymbolAddress((void**)&l0h, d_l0h); cudaGetSymbolAddress((void**)&l0l, d_l0l);
    cudaGetSymbolAddress((void**)&idx, d_idx); cudaGetSymbolAddress((void**)&Q, d_Q);
    cudaGetSymbolAddress((void**)&R, d_R);     cudaGetSymbolAddress((void**)&mx, d_mx);
    cudaGetSymbolAddress((void**)&Ah, d_Ah);   cudaGetSymbolAddress((void**)&Al, d_Al);
    cudaGetSymbolAddress((void**)&W2h, d_W2h);   cudaGetSymbolAddress((void**)&W2l, d_W2l);
    cudaGetSymbolAddress((void**)&WA1h, d_WA1h); cudaGetSymbolAddress((void**)&WA1l, d_WA1l);
    cudaGetSymbolAddress((void**)&WA2h, d_WA2h); cudaGetSymbolAddress((void**)&WA2l, d_WA2l);
    cudaGetSymbolAddress((void**)&WB1h, d_WB1h); cudaGetSymbolAddress((void**)&WB1l, d_WB1l);
    cudaGetSymbolAddress((void**)&WB2h, d_WB2h); cudaGetSymbolAddress((void**)&WB2l, d_WB2l);
    cudaGetSymbolAddress((void**)&sumb, d_sum);  cudaGetSymbolAddress((void**)&ssb, d_ss);

    cudaFuncSetAttribute(gemm_hmma_kernel<true>,
                         cudaFuncAttributeMaxDynamicSharedMemorySize, GSMEM_DYN);
    cudaFuncSetAttribute(gemm_hmma_kernel<false>,
                         cudaFuncAttributeMaxDynamicSharedMemorySize, GSMEM_DYN);
    const int T = 256;

    // weight splits
    split_kernel<<<16, T>>>(W2, W2h, W2l, 256 * 64 / 4);
    split_kernel<<<256, T>>>(WA1, WA1h, WA1l, 512 * 512 / 4);
    split_kernel<<<256, T>>>(WA2, WA2h, WA2l, 512 * 512 / 4);
    split_kernel<<<1024, T>>>(WB1, WB1h, WB1l, 1024 * 1024 / 4);
    split_kernel<<<1024, T>>>(WB2, WB2h, WB2l, 1024 * 1024 / 4);

    // kNN
    knn_kernel<<<dim3(4, 8), T>>>(xyz, idx);

    // layer 1: h1 = bn_relu(xyz @ W1^T), split
    lin1_kernel<<<2048, T>>>(xyz, W1, h1);
    zero_stats_kernel<<<4, T>>>(sumb, ssb);
    colstats_kernel<<<dim3(16, 1), T>>>(h1, 8192, 64, sumb, ssb);
    bnrelu_split_kernel<<<512, T>>>(h1, sumb, ssb, g1, b1, h1h, h1l, 8192, 8192, 64);

    // layer 2: h2 = h1 @ W2^T (+stats), bn_relu split
    zero_stats_kernel<<<4, T>>>(sumb, ssb);
    gemm_hmma_kernel<true><<<dim3(1, 64), T, GSMEM_DYN>>>(h1h, h1l, 64, W2h, W2l, 64,
                                                          h2, nullptr, 256, 64, sumb, ssb);
    bnrelu_split_kernel<<<2048, T>>>(h2, sumb, ssb, g2, b2, h2h, h2l, 8192, 8192, 256);

    // ---- local_op A (3-product everywhere) ----
    gemm_hmma_kernel<true><<<dim3(2, 64), T, GSMEM_DYN>>>(
        h2h, h2l, 256, WA1h, WA1l, 512, Q, nullptr, 512, 256, nullptr, nullptr);
    gemm_hmma_kernel<true><<<dim3(2, 64), T, GSMEM_DYN>>>(
        h2h, h2l, 256, WA1h + 256, WA1l + 256, 512, R, nullptr, 512, 256, nullptr, nullptr);
    zero_stats_kernel<<<4, T>>>(sumb, ssb);
    expand_stats_kernel<<<dim3(256, 1), 128>>>((const float4*)Q, (const float4*)R, idx,
                                               128, sumb, ssb);
    expand_bnrelu_split_kernel<true><<<dim3(256, 1), 128>>>(
        (const float4*)Q, (const float4*)R, idx, 128, sumb, ssb, gA1, bA1, Ah, Al);
    zero_stats_kernel<<<4, T>>>(sumb, ssb);
    gemm_hmma_kernel<true><<<dim3(2, 512), T, GSMEM_DYN>>>(
        Ah, Al, 512, WA2h, WA2l, 512, nullptr, mx, 512, 512, sumb, ssb);
    finish_split_kernel<<<4096, T>>>(mx, sumb, ssb, gA2, bA2, l0h, l0l, 512);

    // ---- local_op B (final GEMM: 2-product, Al never produced/read) ----
    gemm_hmma_kernel<true><<<dim3(4, 64), T, GSMEM_DYN>>>(
        l0h, l0l, 512, WB1h, WB1l, 1024, Q, nullptr, 1024, 512, nullptr, nullptr);
    gemm_hmma_kernel<true><<<dim3(4, 64), T, GSMEM_DYN>>>(
        l0h, l0l, 512, WB1h + 512, WB1l + 512, 1024, R, nullptr, 1024, 512, nullptr, nullptr);
    zero_stats_kernel<<<4, T>>>(sumb, ssb);
    expand_stats_kernel<<<dim3(256, 2), 128>>>((const float4*)Q, (const float4*)R, idx,
                                               256, sumb, ssb);
    expand_bnrelu_split_kernel<false><<<dim3(256, 2), 128>>>(
        (const float4*)Q, (const float4*)R, idx, 256, sumb, ssb, gB1, bB1, Ah, nullptr);
    zero_stats_kernel<<<4, T>>>(sumb, ssb);
    gemm_hmma_kernel<false><<<dim3(4, 512), T, GSMEM_DYN>>>(
        Ah, nullptr, 1024, WB2h, WB2l, 1024, nullptr, mx, 1024, 1024, sumb, ssb);
    finish_out_t_kernel<<<dim3(32, 32, 8), dim3(32, 8)>>>(mx, sumb, ssb, gB2, bB2, out);
}

// round 9
// speedup vs baseline: 1.5192x; 1.5192x over previous
#include <cuda_runtime.h>
#include <cuda_fp16.h>
#include <cstdint>

#define BN_EPS 1e-5f

// ================= persistent scratch (device globals; no allocations) ==========
__device__ float d_h1[8192 * 64];
__device__ __half d_h1h[8192 * 64], d_h1l[8192 * 64];
__device__ float d_h2[8192 * 256];
__device__ __half d_h2h[8192 * 256], d_h2l[8192 * 256];
__device__ __half d_l0h[8192 * 512], d_l0l[8192 * 512];   // l0 fp16 pair
__device__ int   d_idx[8192 * 8];
__device__ float d_Q[8192 * 1024];
__device__ float d_R[8192 * 1024];
__device__ float d_mx[8192 * 1024];                   // raw max-over-k scratch
__device__ __half d_Ah[65536 * 1024];                 // fp16 hi (expanded)
__device__ __half d_Al[65536 * 1024];                 // fp16 lo (expanded; local_op A only)
__device__ __half d_W2h[256 * 64],     d_W2l[256 * 64];
__device__ __half d_WA1h[512 * 512],   d_WA1l[512 * 512];
__device__ __half d_WA2h[512 * 512],   d_WA2l[512 * 512];
__device__ __half d_WB1h[1024 * 1024], d_WB1l[1024 * 1024];
__device__ __half d_WB2h[1024 * 1024], d_WB2l[1024 * 1024];
__device__ float d_sum[1024];
__device__ float d_ss[1024];

// ================= PTX helpers (arch-neutral, sm_80+) ===========================
__device__ __forceinline__ uint32_t smem_u32(const void* p) {
    uint32_t a;
    asm("{ .reg .u64 t; cvta.to.shared.u64 t, %1; cvt.u32.u64 %0, t; }" : "=r"(a) : "l"(p));
    return a;
}
__device__ __forceinline__ void cpa16(uint32_t s, const void* g) {
    asm volatile("cp.async.cg.shared.global [%0], [%1], 16;" :: "r"(s), "l"(g));
}
#define CP_COMMIT() asm volatile("cp.async.commit_group;" ::: "memory")
#define CP_WAIT0()  asm volatile("cp.async.wait_group 0;" ::: "memory")
#define CP_WAIT1()  asm volatile("cp.async.wait_group 1;" ::: "memory")

#define LDSM4(r0, r1, r2, r3, a) \
    asm volatile("ldmatrix.sync.aligned.m8n8.x4.shared.b16 {%0,%1,%2,%3}, [%4];" \
                 : "=r"(r0), "=r"(r1), "=r"(r2), "=r"(r3) : "r"(a))

#define MMA16816(c, a, b) \
    asm volatile("mma.sync.aligned.m16n8k16.row.col.f32.f16.f16.f32 " \
                 "{%0,%1,%2,%3}, {%4,%5,%6,%7}, {%8,%9}, {%0,%1,%2,%3};" \
                 : "+f"((c)[0]), "+f"((c)[1]), "+f"((c)[2]), "+f"((c)[3]) \
                 : "r"((a)[0]), "r"((a)[1]), "r"((a)[2]), "r"((a)[3]), \
                   "r"((b)[0]), "r"((b)[1]))

// ================= HMMA split-fp16 GEMM =========================================
// USE_ALO=true : C = Ah*Bh + Ah*Bl + Al*Bh   (3 products, ~1e-6 rel)
// USE_ALO=false: C = Ah*Bh + Ah*Bl           (2 products, ~2e-4 rel; Al never read)
// CTA tile 128(M) x 256(N), BK=32, 3-stage cp.async pipeline.
// 8 warps, 2(m) x 4(n) grid of 64x64 warp tiles.
// gridDim.z=2 fuses two GEMMs sharing A: z=0 -> (Bh,Bl)->C ; z=1 -> (Bh2,Bl2)->C2.
// Modes: maxout != nullptr -> fused raw max over k=8 groups (no C write) + stats.
#define GBK 32
#define GA_LO  10240u                 // Al offset   (A: 128 * 80 B)
#define GB_HI  20480u                 // Bh offset
#define GB_LO  40960u                 // Bl offset   (B: 256 * 80 B)
#define GSTAGE 61440u
#define GSMEM_DYN 184320

template <bool USE_ALO>
__device__ __forceinline__ void g_load_stage(uint32_t st,
        const __half* Ah, const __half* Al, int lda,
        const __half* Bh, const __half* Bl, int ldb,
        int bm, int bn, int kc, int tid) {
#pragma unroll
    for (int t = 0; t < 2; t++) {                 // A: 512 chunks of 16B
        int i = tid + t * 256;
        int row = i >> 2, cg = i & 3;
        uint32_t off = (uint32_t)(row * 80 + cg * 16);
        size_t ga = (size_t)(bm + row) * lda + kc + cg * 8;
        cpa16(st + off, Ah + ga);
        if (USE_ALO) cpa16(st + GA_LO + off, Al + ga);
    }
#pragma unroll
    for (int t = 0; t < 4; t++) {                 // B: 1024 chunks of 16B (hi & lo)
        int i = tid + t * 256;
        int row = i >> 2, cg = i & 3;
        uint32_t off = (uint32_t)(row * 80 + cg * 16);
        size_t gb = (size_t)(bn + row) * ldb + kc + cg * 8;
        cpa16(st + GB_HI + off, Bh + gb);
        cpa16(st + GB_LO + off, Bl + gb);
    }
}

template <bool USE_ALO>
__global__ void __launch_bounds__(256, 1)
gemm_hmma_kernel(const __half* __restrict__ Ah, const __half* __restrict__ Al, int lda,
                 const __half* __restrict__ Bh_, const __half* __restrict__ Bl_,
                 const __half* __restrict__ Bh2, const __half* __restrict__ Bl2, int ldb,
                 float* __restrict__ C_, float* __restrict__ C2,
                 float* __restrict__ maxout, int ldc, int K,
                 float* __restrict__ gsum, float* __restrict__ gss) {
    extern __shared__ char smem[];
    __shared__ float s_sum[256], s_ss[256];
    const int tid = threadIdx.x;
    const int lane = tid & 31, wid = tid >> 5;
    const int wm = wid & 1, wn = wid >> 1;           // 2 x 4 warp grid, 64x64 tiles
    const int bm = blockIdx.y * 128, bn = blockIdx.x * 256;
    const uint32_t sb = smem_u32(smem);

    const __half* Bh = (blockIdx.z == 0) ? Bh_ : Bh2;
    const __half* Bl = (blockIdx.z == 0) ? Bl_ : Bl2;
    float* C = (blockIdx.z == 0) ? C_ : C2;

    if (gsum) { s_sum[tid] = 0.f; s_ss[tid] = 0.f; }

    float acc[4][8][4];
#pragma unroll
    for (int i = 0; i < 4; i++)
#pragma unroll
        for (int j = 0; j < 8; j++)
#pragma unroll
            for (int v = 0; v < 4; v++) acc[i][j][v] = 0.f;

    // ldmatrix base addresses
    const uint32_t a_off = (uint32_t)((wm * 64 + (lane & 15)) * 80 + (lane >> 4) * 16);
    const int b_n = wn * 64 + (lane & 7) + ((lane >> 4) << 3);
    const uint32_t b_koff = (uint32_t)(((lane >> 3) & 1) * 16);

    const int NC = K / GBK;

    g_load_stage<USE_ALO>(sb, Ah, Al, lda, Bh, Bl, ldb, bm, bn, 0, tid);
    CP_COMMIT();
    if (NC > 1) {
        g_load_stage<USE_ALO>(sb + GSTAGE, Ah, Al, lda, Bh, Bl, ldb, bm, bn, GBK, tid);
        CP_COMMIT();
    }

    for (int c = 0; c < NC; c++) {
        if (c + 1 < NC) CP_WAIT1(); else CP_WAIT0();
        __syncthreads();
        if (c + 2 < NC) {
            g_load_stage<USE_ALO>(sb + (uint32_t)((c + 2) % 3) * GSTAGE, Ah, Al, lda,
                                  Bh, Bl, ldb, bm, bn, (c + 2) * GBK, tid);
            CP_COMMIT();
        }
        uint32_t st = sb + (uint32_t)(c % 3) * GSTAGE;
#pragma unroll
        for (int kk = 0; kk < 2; kk++) {              // two k16 steps in BK=32
            uint32_t kb = (uint32_t)(kk * 32);        // bytes
            uint32_t bh[8][2], bl[8][2];
#pragma unroll
            for (int p = 0; p < 4; p++) {
                uint32_t ba = st + GB_HI + (uint32_t)((b_n + p * 16) * 80) + b_koff + kb;
                LDSM4(bh[2 * p][0], bh[2 * p][1], bh[2 * p + 1][0], bh[2 * p + 1][1], ba);
                LDSM4(bl[2 * p][0], bl[2 * p][1], bl[2 * p + 1][0], bl[2 * p + 1][1],
                      ba + (GB_LO - GB_HI));
            }
#pragma unroll
            for (int mt = 0; mt < 4; mt++) {
                uint32_t ah[4], al[4];
                uint32_t aa = st + a_off + (uint32_t)(mt * 16 * 80) + kb;
                LDSM4(ah[0], ah[1], ah[2], ah[3], aa);
                if (USE_ALO) LDSM4(al[0], al[1], al[2], al[3], aa + GA_LO);
#pragma unroll
                for (int nt = 0; nt < 8; nt++) {
                    MMA16816(acc[mt][nt], ah, bh[nt]);
                    MMA16816(acc[mt][nt], ah, bl[nt]);
                    if (USE_ALO) MMA16816(acc[mt][nt], al, bh[nt]);
                }
            }
        }
    }

    // ---------------- epilogue -------------------------------------------------
    if (maxout) {
#pragma unroll
        for (int mt = 0; mt < 4; mt++) {
            int gA = (bm + wm * 64 + mt * 16) >> 3;   // output group rows gA, gA+1
#pragma unroll
            for (int nt = 0; nt < 8; nt++) {
                float m0 = acc[mt][nt][0], m1 = acc[mt][nt][1];
                float m2 = acc[mt][nt][2], m3 = acc[mt][nt][3];
#pragma unroll
                for (int off = 4; off < 32; off <<= 1) {
                    m0 = fmaxf(m0, __shfl_xor_sync(0xFFFFFFFFu, m0, off));
                    m1 = fmaxf(m1, __shfl_xor_sync(0xFFFFFFFFu, m1, off));
                    m2 = fmaxf(m2, __shfl_xor_sync(0xFFFFFFFFu, m2, off));
                    m3 = fmaxf(m3, __shfl_xor_sync(0xFFFFFFFFu, m3, off));
                }
                if (lane < 4) {
                    int col = bn + wn * 64 + nt * 8 + lane * 2;
                    float2 v0 = { m0, m1 }, v1 = { m2, m3 };
                    *(float2*)(maxout + (size_t)gA * ldc + col) = v0;
                    *(float2*)(maxout + (size_t)(gA + 1) * ldc + col) = v1;
                }
            }
        }
    } else {
#pragma unroll
        for (int mt = 0; mt < 4; mt++) {
            int row = bm + wm * 64 + mt * 16 + (lane >> 2);
#pragma unroll
            for (int nt = 0; nt < 8; nt++) {
                int col = bn + wn * 64 + nt * 8 + (lane & 3) * 2;
                float2 v0 = { acc[mt][nt][0], acc[mt][nt][1] };
                float2 v1 = { acc[mt][nt][2], acc[mt][nt][3] };
                *(float2*)(C + (size_t)row * ldc + col) = v0;
                *(float2*)(C + (size_t)(row + 8) * ldc + col) = v1;
            }
        }
    }
    if (gsum) {
#pragma unroll
        for (int nt = 0; nt < 8; nt++) {
            float se = 0.f, so = 0.f, qe = 0.f, qo = 0.f;
#pragma unroll
            for (int mt = 0; mt < 4; mt++) {
                float e0 = acc[mt][nt][0], e1 = acc[mt][nt][1];
                float e2 = acc[mt][nt][2], e3 = acc[mt][nt][3];
                se += e0 + e2; so += e1 + e3;
                qe += e0 * e0 + e2 * e2; qo += e1 * e1 + e3 * e3;
            }
#pragma unroll
            for (int off = 4; off < 32; off <<= 1) {
                se += __shfl_xor_sync(0xFFFFFFFFu, se, off);
                so += __shfl_xor_sync(0xFFFFFFFFu, so, off);
                qe += __shfl_xor_sync(0xFFFFFFFFu, qe, off);
                qo += __shfl_xor_sync(0xFFFFFFFFu, qo, off);
            }
            if (lane < 4) {
                int cl = wn * 64 + nt * 8 + lane * 2;
                atomicAdd(&s_sum[cl], se);     atomicAdd(&s_sum[cl + 1], so);
                atomicAdd(&s_ss[cl], qe);      atomicAdd(&s_ss[cl + 1], qo);
            }
        }
        __syncthreads();
        atomicAdd(&gsum[bn + tid], s_sum[tid]);
        atomicAdd(&gss[bn + tid], s_ss[tid]);
    }
}

// ================= small elementwise / stats kernels ============================
__global__ void lin1_kernel(const float* __restrict__ xyz, const float* __restrict__ W1,
                            float* __restrict__ out) {
    int t = blockIdx.x * blockDim.x + threadIdx.x;
    int r = t >> 6, o = t & 63;
    float x0 = xyz[r * 3 + 0], x1 = xyz[r * 3 + 1], x2 = xyz[r * 3 + 2];
    out[t] = x0 * W1[o * 3 + 0] + x1 * W1[o * 3 + 1] + x2 * W1[o * 3 + 2];
}

__global__ void zero_stats_kernel(float* __restrict__ s, float* __restrict__ q) {
    int t = blockIdx.x * blockDim.x + threadIdx.x;
    if (t < 1024) { s[t] = 0.f; q[t] = 0.f; }
}

__global__ void colstats_kernel(const float* __restrict__ x, int M, int C,
                                float* __restrict__ sum, float* __restrict__ ss) {
    int c = blockIdx.y * blockDim.x + threadIdx.x;
    if (c >= C) return;
    size_t r0 = (size_t)blockIdx.x * 512;
    const float* p = x + r0 * C + c;
    float s = 0.f, q = 0.f;
    for (int r = 0; r < 512; r++) { float v = p[(size_t)r * C]; s += v; q += v * v; }
    atomicAdd(&sum[c], s);
    atomicAdd(&ss[c], q);
}

__device__ __forceinline__ uint32_t pk_h2(float a, float b) {
    __half2 t = __floats2half2_rn(a, b);
    return *(uint32_t*)&t;
}

// BN + ReLU + hi/lo fp16 split (reads fp32 once, writes fp16 pair).
__global__ void bnrelu_split_kernel(const float* __restrict__ x,
                                    const float* __restrict__ sum, const float* __restrict__ ss,
                                    const float* __restrict__ g, const float* __restrict__ bta,
                                    __half* __restrict__ hi, __half* __restrict__ lo,
                                    int Mstat, int Mrows, int C) {
    int t = blockIdx.x * blockDim.x + threadIdx.x;
    int C4 = C >> 2;
    if (t >= Mrows * C4) return;
    int c = (t % C4) << 2;
    float invM = 1.0f / (float)Mstat;
    float4 v = ((const float4*)x)[t];
    float vv[4] = { v.x, v.y, v.z, v.w };
    float o[4];
#pragma unroll
    for (int i = 0; i < 4; i++) {
        float m = sum[c + i] * invM;
        float var = ss[c + i] * invM - m * m;
        float sc = g[c + i] * rsqrtf(var + BN_EPS);
        o[i] = fmaxf((vv[i] - m) * sc + bta[c + i], 0.f);
    }
    float h[4];
#pragma unroll
    for (int i = 0; i < 4; i++) h[i] = __half2float(__float2half_rn(o[i]));
    uint2 H = { pk_h2(o[0], o[1]), pk_h2(o[2], o[3]) };
    uint2 L = { pk_h2(o[0] - h[0], o[1] - h[1]), pk_h2(o[2] - h[2], o[3] - h[3]) };
    ((uint2*)hi)[t] = H;
    ((uint2*)lo)[t] = L;
}

// plain hi/lo split (weights)
__global__ void split_kernel(const float* __restrict__ x,
                             __half* __restrict__ hi, __half* __restrict__ lo, int n4) {
    int t = blockIdx.x * blockDim.x + threadIdx.x;
    if (t >= n4) return;
    float4 v = ((const float4*)x)[t];
    float o[4] = { v.x, v.y, v.z, v.w };
    float h[4];
#pragma unroll
    for (int i = 0; i < 4; i++) h[i] = __half2float(__float2half_rn(o[i]));
    uint2 H = { pk_h2(o[0], o[1]), pk_h2(o[2], o[3]) };
    uint2 L = { pk_h2(o[0] - h[0], o[1] - h[1]), pk_h2(o[2] - h[2], o[3] - h[3]) };
    ((uint2*)hi)[t] = H;
    ((uint2*)lo)[t] = L;
}

// kNN: k=8 smallest (stable ties, matches top_k(-d2))
__global__ void knn_kernel(const float* __restrict__ xyz, int* __restrict__ idx) {
    __shared__ float sx[1024], sy[1024], sz[1024], sq[1024];
    int b = blockIdx.y, tid = threadIdx.x;
    for (int i = tid; i < 1024; i += 256) {
        float x = xyz[((b << 10) + i) * 3 + 0];
        float y = xyz[((b << 10) + i) * 3 + 1];
        float z = xyz[((b << 10) + i) * 3 + 2];
        sx[i] = x; sy[i] = y; sz[i] = z;
        sq[i] = x * x + y * y + z * z;
    }
    __syncthreads();
    int n = blockIdx.x * 256 + tid;
    float qx = sx[n], qy = sy[n], qz = sz[n], qs = sq[n];
    float bd[8]; int bi[8];
#pragma unroll
    for (int j = 0; j < 8; j++) { bd[j] = 3.4e38f; bi[j] = 0; }
    for (int m = 0; m < 1024; m++) {
        float d2 = qs + sq[m] - 2.f * (qx * sx[m] + qy * sy[m] + qz * sz[m]);
        if (d2 < bd[7]) {
            bd[7] = d2; bi[7] = m;
#pragma unroll
            for (int j = 7; j > 0; j--) {
                if (bd[j] < bd[j - 1]) {
                    float td = bd[j]; bd[j] = bd[j - 1]; bd[j - 1] = td;
                    int ti = bi[j]; bi[j] = bi[j - 1]; bi[j - 1] = ti;
                }
            }
        }
    }
#pragma unroll
    for (int j = 0; j < 8; j++) idx[((b << 10) + n) * 8 + j] = bi[j];
}

// expand stats only (no materialization): o = Q[idx]-Qc+Rc, column sum/sumsq.
// grid: (65536/256, C4/128), block 128.
__global__ void expand_stats_kernel(const float4* __restrict__ Q, const float4* __restrict__ R,
                                    const int* __restrict__ idx, int C4,
                                    float* __restrict__ gsum, float* __restrict__ gss) {
    __shared__ int sidx[256];
    int c4 = blockIdx.y * 128 + threadIdx.x;
    int r0 = blockIdx.x * 256;
    for (int i = threadIdx.x; i < 256; i += 128) sidx[i] = idx[r0 + i];
    __syncthreads();
    int bn0 = r0 >> 3;
    int b = bn0 >> 10;
    float s[4] = {0.f, 0.f, 0.f, 0.f}, q[4] = {0.f, 0.f, 0.f, 0.f};
    for (int gg = 0; gg < 32; gg++) {
        int bn = bn0 + gg;
        float4 qc = Q[(size_t)bn * C4 + c4];
        float4 rr = R[(size_t)bn * C4 + c4];
        float bx = rr.x - qc.x, by = rr.y - qc.y, bz = rr.z - qc.z, bw = rr.w - qc.w;
#pragma unroll
        for (int k = 0; k < 8; k++) {
            int src = (b << 10) + sidx[gg * 8 + k];
            float4 qa = Q[(size_t)src * C4 + c4];
            float ox = qa.x + bx, oy = qa.y + by, oz = qa.z + bz, ow = qa.w + bw;
            s[0] += ox; s[1] += oy; s[2] += oz; s[3] += ow;
            q[0] += ox * ox; q[1] += oy * oy; q[2] += oz * oz; q[3] += ow * ow;
        }
    }
    int c = c4 << 2;
#pragma unroll
    for (int i = 0; i < 4; i++) { atomicAdd(&gsum[c + i], s[i]); atomicAdd(&gss[c + i], q[i]); }
}

// expand recompute + BN + ReLU + fp16 split (WRITE_LO=false -> hi only).
template <bool WRITE_LO>
__global__ void expand_bnrelu_split_kernel(
        const float4* __restrict__ Q, const float4* __restrict__ R,
        const int* __restrict__ idx, int C4,
        const float* __restrict__ sum, const float* __restrict__ ss,
        const float* __restrict__ g, const float* __restrict__ bta,
        __half* __restrict__ hi, __half* __restrict__ lo) {
    __shared__ int sidx[256];
    int c4 = blockIdx.y * 128 + threadIdx.x;
    int r0 = blockIdx.x * 256;
    for (int i = threadIdx.x; i < 256; i += 128) sidx[i] = idx[r0 + i];
    __syncthreads();
    int bn0 = r0 >> 3;
    int b = bn0 >> 10;
    const float invM = 1.0f / 65536.0f;
    int c = c4 << 2;
    float m[4], sc[4], bb[4];
#pragma unroll
    for (int i = 0; i < 4; i++) {
        m[i] = sum[c + i] * invM;
        float var = ss[c + i] * invM - m[i] * m[i];
        sc[i] = g[c + i] * rsqrtf(var + BN_EPS);
        bb[i] = bta[c + i];
    }
    for (int gg = 0; gg < 32; gg++) {
        int bn = bn0 + gg;
        float4 qc = Q[(size_t)bn * C4 + c4];
        float4 rr = R[(size_t)bn * C4 + c4];
        float bx = rr.x - qc.x, by = rr.y - qc.y, bz = rr.z - qc.z, bw = rr.w - qc.w;
#pragma unroll
        for (int k = 0; k < 8; k++) {
            int row = bn * 8 + k;
            int src = (b << 10) + sidx[gg * 8 + k];
            float4 qa = Q[(size_t)src * C4 + c4];
            float o[4] = { qa.x + bx, qa.y + by, qa.z + bz, qa.w + bw };
            float h[4];
#pragma unroll
            for (int i = 0; i < 4; i++) {
                o[i] = fmaxf((o[i] - m[i]) * sc[i] + bb[i], 0.f);
                h[i] = __half2float(__float2half_rn(o[i]));
            }
            uint2 H = { pk_h2(o[0], o[1]), pk_h2(o[2], o[3]) };
            ((uint2*)hi)[(size_t)row * C4 + c4] = H;
            if (WRITE_LO) {
                uint2 L = { pk_h2(o[0] - h[0], o[1] - h[1]),
                            pk_h2(o[2] - h[2], o[3] - h[3]) };
                ((uint2*)lo)[(size_t)row * C4 + c4] = L;
            }
        }
    }
}

// finish: BN+ReLU of raw max (stats over 65536 raw rows) -> fp16 split (l0)
__global__ void finish_split_kernel(const float* __restrict__ mx,
                                    const float* __restrict__ sum, const float* __restrict__ ss,
                                    const float* __restrict__ g, const float* __restrict__ bta,
                                    __half* __restrict__ hi, __half* __restrict__ lo, int C) {
    int t = blockIdx.x * blockDim.x + threadIdx.x;
    int C4 = C >> 2;
    if (t >= 8192 * C4) return;
    int c = (t % C4) << 2;
    const float invM = 1.0f / 65536.0f;
    float4 v = ((const float4*)mx)[t];
    float vv[4] = { v.x, v.y, v.z, v.w };
    float o[4], h[4];
#pragma unroll
    for (int i = 0; i < 4; i++) {
        float m = sum[c + i] * invM;
        float var = ss[c + i] * invM - m * m;
        float sc = g[c + i] * rsqrtf(var + BN_EPS);
        o[i] = fmaxf((vv[i] - m) * sc + bta[c + i], 0.f);
        h[i] = __half2float(__float2half_rn(o[i]));
    }
    uint2 H = { pk_h2(o[0], o[1]), pk_h2(o[2], o[3]) };
    uint2 L = { pk_h2(o[0] - h[0], o[1] - h[1]), pk_h2(o[2] - h[2], o[3] - h[3]) };
    ((uint2*)hi)[t] = H;
    ((uint2*)lo)[t] = L;
}

// finish: BN+ReLU of raw max + transpose to (B, C, N). C=1024.
// grid (32, 32, 8), block (32,8)
__global__ void finish_out_t_kernel(const float* __restrict__ mx,
                                    const float* __restrict__ sum, const float* __restrict__ ss,
                                    const float* __restrict__ g, const float* __restrict__ bta,
                                    float* __restrict__ out) {
    __shared__ float tile[32][33];
    int b = blockIdx.z;
    int n0 = blockIdx.x * 32;
    int c0 = blockIdx.y * 32;
    int c = c0 + threadIdx.x;
    const float invM = 1.0f / 65536.0f;
    float m = sum[c] * invM;
    float var = ss[c] * invM - m * m;
    float sc = g[c] * rsqrtf(var + BN_EPS);
    float bb = bta[c];
#pragma unroll
    for (int j = 0; j < 4; j++) {
        int nl = threadIdx.y + j * 8;
        int bn = (b << 10) + n0 + nl;
        float v = mx[(size_t)bn * 1024 + c];
        tile[threadIdx.x][nl] = fmaxf((v - m) * sc + bb, 0.f);
    }
    __syncthreads();
#pragma unroll
    for (int j = 0; j < 4; j++) {
        int cl = threadIdx.y + j * 8;
        out[((size_t)b * 1024 + c0 + cl) * 1024 + n0 + threadIdx.x] = tile[cl][threadIdx.x];
    }
}

// ================= host orchestration ===========================================
extern "C" void kernel_launch(void* const* d_in, const int* in_sizes, int n_in,
                              void* d_out, int out_size) {
    const float* xyz = (const float*)d_in[0];
    const float* W1  = (const float*)d_in[1];
    const float* g1  = (const float*)d_in[2];
    const float* b1  = (const float*)d_in[3];
    const float* W2  = (const float*)d_in[4];
    const float* g2  = (const float*)d_in[5];
    const float* b2  = (const float*)d_in[6];
    const float* WA1 = (const float*)d_in[7];
    const float* gA1 = (const float*)d_in[8];
    const float* bA1 = (const float*)d_in[9];
    const float* WA2 = (const float*)d_in[10];
    const float* gA2 = (const float*)d_in[11];
    const float* bA2 = (const float*)d_in[12];
    const float* WB1 = (const float*)d_in[13];
    const float* gB1 = (const float*)d_in[14];
    const float* bB1 = (const float*)d_in[15];
    const float* WB2 = (const float*)d_in[16];
    const float* gB2 = (const float*)d_in[17];
    const float* bB2 = (const float*)d_in[18];
    float* out = (float*)d_out;

    float *h1, *h2, *Q, *R, *mx, *sumb, *ssb;
    __half *h1h, *h1l, *h2h, *h2l, *l0h, *l0l, *Ah, *Al;
    __half *W2h, *W2l, *WA1h, *WA1l, *WA2h, *WA2l, *WB1h, *WB1l, *WB2h, *WB2l;
    int* idx;
    cudaGetSymbolAddress((void**)&h1, d_h1);   cudaGetSymbolAddress((void**)&h1h, d_h1h);
    cudaGetSymbolAddress((void**)&h1l, d_h1l); cudaGetSymbolAddress((void**)&h2, d_h2);
    cudaGetSymbolAddress((void**)&h2h, d_h2h); cudaGetSymbolAddress((void**)&h2l, d_h2l);
    cudaGetSymbolAddress((void**)&l0h, d_l0h); cudaGetSymbolAddress((void**)&l0l, d_l0l);
    cudaGetSymbolAddress((void**)&idx, d_idx); cudaGetSymbolAddress((void**)&Q, d_Q);
    cudaGetSymbolAddress((void**)&R, d_R);     cudaGetSymbolAddress((void**)&mx, d_mx);
    cudaGetSymbolAddress((void**)&Ah, d_Ah);   cudaGetSymbolAddress((void**)&Al, d_Al);
    cudaGetSymbolAddress((void**)&W2h, d_W2h);   cudaGetSymbolAddress((void**)&W2l, d_W2l);
    cudaGetSymbolAddress((void**)&WA1h, d_WA1h); cudaGetSymbolAddress((void**)&WA1l, d_WA1l);
    cudaGetSymbolAddress((void**)&WA2h, d_WA2h); cudaGetSymbolAddress((void**)&WA2l, d_WA2l);
    cudaGetSymbolAddress((void**)&WB1h, d_WB1h); cudaGetSymbolAddress((void**)&WB1l, d_WB1l);
    cudaGetSymbolAddress((void**)&WB2h, d_WB2h); cudaGetSymbolAddress((void**)&WB2l, d_WB2l);
    cudaGetSymbolAddress((void**)&sumb, d_sum);  cudaGetSymbolAddress((void**)&ssb, d_ss);

    cudaFuncSetAttribute(gemm_hmma_kernel<true>,
                         cudaFuncAttributeMaxDynamicSharedMemorySize, GSMEM_DYN);
    cudaFuncSetAttribute(gemm_hmma_kernel<false>,
                         cudaFuncAttributeMaxDynamicSharedMemorySize, GSMEM_DYN);
    const int T = 256;

    // weight splits
    split_kernel<<<16, T>>>(W2, W2h, W2l, 256 * 64 / 4);
    split_kernel<<<256, T>>>(WA1, WA1h, WA1l, 512 * 512 / 4);
    split_kernel<<<256, T>>>(WA2, WA2h, WA2l, 512 * 512 / 4);
    split_kernel<<<1024, T>>>(WB1, WB1h, WB1l, 1024 * 1024 / 4);
    split_kernel<<<1024, T>>>(WB2, WB2h, WB2l, 1024 * 1024 / 4);

    // kNN
    knn_kernel<<<dim3(4, 8), T>>>(xyz, idx);

    // layer 1: h1 = bn_relu(xyz @ W1^T), split
    lin1_kernel<<<2048, T>>>(xyz, W1, h1);
    zero_stats_kernel<<<4, T>>>(sumb, ssb);
    colstats_kernel<<<dim3(16, 1), T>>>(h1, 8192, 64, sumb, ssb);
    bnrelu_split_kernel<<<512, T>>>(h1, sumb, ssb, g1, b1, h1h, h1l, 8192, 8192, 64);

    // layer 2: h2 = h1 @ W2^T (+stats), bn_relu split
    zero_stats_kernel<<<4, T>>>(sumb, ssb);
    gemm_hmma_kernel<true><<<dim3(1, 64, 1), T, GSMEM_DYN>>>(
        h1h, h1l, 64, W2h, W2l, nullptr, nullptr, 64,
        h2, nullptr, nullptr, 256, 64, sumb, ssb);
    bnrelu_split_kernel<<<2048, T>>>(h2, sumb, ssb, g2, b2, h2h, h2l, 8192, 8192, 256);

    // ---- local_op A (3-product; fused Q+R GEMM via grid.z) ----
    gemm_hmma_kernel<true><<<dim3(2, 64, 2), T, GSMEM_DYN>>>(
        h2h, h2l, 256, WA1h, WA1l, WA1h + 256, WA1l + 256, 512,
        Q, R, nullptr, 512, 256, nullptr, nullptr);
    zero_stats_kernel<<<4, T>>>(sumb, ssb);
    expand_stats_kernel<<<dim3(256, 1), 128>>>((const float4*)Q, (const float4*)R, idx,
                                               128, sumb, ssb);
    expand_bnrelu_split_kernel<true><<<dim3(256, 1), 128>>>(
        (const float4*)Q, (const float4*)R, idx, 128, sumb, ssb, gA1, bA1, Ah, Al);
    zero_stats_kernel<<<4, T>>>(sumb, ssb);
    gemm_hmma_kernel<true><<<dim3(2, 512, 1), T, GSMEM_DYN>>>(
        Ah, Al, 512, WA2h, WA2l, nullptr, nullptr, 512,
        nullptr, nullptr, mx, 512, 512, sumb, ssb);
    finish_split_kernel<<<4096, T>>>(mx, sumb, ssb, gA2, bA2, l0h, l0l, 512);

    // ---- local_op B (fused Q+R GEMM; final GEMM 2-product, Al never produced) ----
    gemm_hmma_kernel<true><<<dim3(4, 64, 2), T, GSMEM_DYN>>>(
        l0h, l0l, 512, WB1h, WB1l, WB1h + 512, WB1l + 512, 1024,
        Q, R, nullptr, 1024, 512, nullptr, nullptr);
    zero_stats_kernel<<<4, T>>>(sumb, ssb);
    expand_stats_kernel<<<dim3(256, 2), 128>>>((const float4*)Q, (const float4*)R, idx,
                                               256, sumb, ssb);
    expand_bnrelu_split_kernel<false><<<dim3(256, 2), 128>>>(
        (const float4*)Q, (const float4*)R, idx, 256, sumb, ssb, gB1, bB1, Ah, nullptr);
    zero_stats_kernel<<<4, T>>>(sumb, ssb);
    gemm_hmma_kernel<false><<<dim3(4, 512, 1), T, GSMEM_DYN>>>(
        Ah, nullptr, 1024, WB2h, WB2l, nullptr, nullptr, 1024,
        nullptr, nullptr, mx, 1024, 1024, sumb, ssb);
    finish_out_t_kernel<<<dim3(32, 32, 8), dim3(32, 8)>>>(mx, sumb, ssb, gB2, bB2, out);
}

// round 11
// speedup vs baseline: 1.5938x; 1.0491x over previous
#include <cuda_runtime.h>
#include <cuda_fp16.h>
#include <cstdint>

#define BN_EPS 1e-5f

// ================= persistent scratch (device globals; no allocations) ==========
__device__ float d_h1[8192 * 64];
__device__ __half d_h1h[8192 * 64], d_h1l[8192 * 64];
__device__ float d_h2[8192 * 256];
__device__ __half d_h2h[8192 * 256], d_h2l[8192 * 256];
__device__ __half d_l0h[8192 * 512], d_l0l[8192 * 512];   // l0 fp16 pair (QR-B 3-prod)
__device__ int   d_idx[8192 * 8];
__device__ float d_Q[8192 * 1024];
__device__ float d_R[8192 * 1024];
__device__ float d_mx[8192 * 1024];                   // raw max-over-k scratch
__device__ __half d_Ah[65536 * 1024];                 // fp16 hi (expanded; 2-prod GEMMs)
__device__ __half d_W2h[256 * 64],     d_W2l[256 * 64];
__device__ __half d_WA1h[512 * 512],   d_WA1l[512 * 512];
__device__ __half d_WA2h[512 * 512],   d_WA2l[512 * 512];
__device__ __half d_WB1h[1024 * 1024], d_WB1l[1024 * 1024];
__device__ __half d_WB2h[1024 * 1024], d_WB2l[1024 * 1024];
__device__ float d_sum[1024];
__device__ float d_ss[1024];

// ================= PTX helpers (arch-neutral, sm_80+) ===========================
__device__ __forceinline__ uint32_t smem_u32(const void* p) {
    uint32_t a;
    asm("{ .reg .u64 t; cvta.to.shared.u64 t, %1; cvt.u32.u64 %0, t; }" : "=r"(a) : "l"(p));
    return a;
}
__device__ __forceinline__ void cpa16(uint32_t s, const void* g) {
    asm volatile("cp.async.cg.shared.global [%0], [%1], 16;" :: "r"(s), "l"(g));
}
#define CP_COMMIT() asm volatile("cp.async.commit_group;" ::: "memory")
#define CP_WAIT0()  asm volatile("cp.async.wait_group 0;" ::: "memory")
#define CP_WAIT1()  asm volatile("cp.async.wait_group 1;" ::: "memory")

#define LDSM4(r0, r1, r2, r3, a) \
    asm volatile("ldmatrix.sync.aligned.m8n8.x4.shared.b16 {%0,%1,%2,%3}, [%4];" \
                 : "=r"(r0), "=r"(r1), "=r"(r2), "=r"(r3) : "r"(a))

#define MMA16816(c, a, b) \
    asm volatile("mma.sync.aligned.m16n8k16.row.col.f32.f16.f16.f32 " \
                 "{%0,%1,%2,%3}, {%4,%5,%6,%7}, {%8,%9}, {%0,%1,%2,%3};" \
                 : "+f"((c)[0]), "+f"((c)[1]), "+f"((c)[2]), "+f"((c)[3]) \
                 : "r"((a)[0]), "r"((a)[1]), "r"((a)[2]), "r"((a)[3]), \
                   "r"((b)[0]), "r"((b)[1]))

// ================= HMMA split-fp16 GEMM =========================================
// USE_ALO=true : C = Ah*Bh + Ah*Bl + Al*Bh   (3 products, ~1e-6 rel)
// USE_ALO=false: C = Ah*Bh + Ah*Bl           (2 products, ~2.5e-4 rel; Al never read)
// CTA tile 128(M) x 256(N), BK=32, 3-stage cp.async pipeline.
// 8 warps, 2(m) x 4(n) grid of 64x64 warp tiles.
// gridDim.z=2 fuses two GEMMs sharing A: z=0 -> (Bh,Bl)->C ; z=1 -> (Bh2,Bl2)->C2.
// Modes: maxout != nullptr -> fused raw max over k=8 groups (no C write) + stats.
#define GBK 32
#define GA_LO  10240u                 // Al offset   (A: 128 * 80 B)
#define GB_HI  20480u                 // Bh offset
#define GB_LO  40960u                 // Bl offset   (B: 256 * 80 B)
#define GSTAGE 61440u
#define GSMEM_DYN 184320

template <bool USE_ALO>
__device__ __forceinline__ void g_load_stage(uint32_t st,
        const __half* Ah, const __half* Al, int lda,
        const __half* Bh, const __half* Bl, int ldb,
        int bm, int bn, int kc, int tid) {
#pragma unroll
    for (int t = 0; t < 2; t++) {                 // A: 512 chunks of 16B
        int i = tid + t * 256;
        int row = i >> 2, cg = i & 3;
        uint32_t off = (uint32_t)(row * 80 + cg * 16);
        size_t ga = (size_t)(bm + row) * lda + kc + cg * 8;
        cpa16(st + off, Ah + ga);
        if (USE_ALO) cpa16(st + GA_LO + off, Al + ga);
    }
#pragma unroll
    for (int t = 0; t < 4; t++) {                 // B: 1024 chunks of 16B (hi & lo)
        int i = tid + t * 256;
        int row = i >> 2, cg = i & 3;
        uint32_t off = (uint32_t)(row * 80 + cg * 16);
        size_t gb = (size_t)(bn + row) * ldb + kc + cg * 8;
        cpa16(st + GB_HI + off, Bh + gb);
        cpa16(st + GB_LO + off, Bl + gb);
    }
}

template <bool USE_ALO>
__global__ void __launch_bounds__(256, 1)
gemm_hmma_kernel(const __half* __restrict__ Ah, const __half* __restrict__ Al, int lda,
                 const __half* __restrict__ Bh_, const __half* __restrict__ Bl_,
                 const __half* __restrict__ Bh2, const __half* __restrict__ Bl2, int ldb,
                 float* __restrict__ C_, float* __restrict__ C2,
                 float* __restrict__ maxout, int ldc, int K,
                 float* __restrict__ gsum, float* __restrict__ gss) {
    extern __shared__ char smem[];
    __shared__ float s_sum[256], s_ss[256];
    const int tid = threadIdx.x;
    const int lane = tid & 31, wid = tid >> 5;
    const int wm = wid & 1, wn = wid >> 1;           // 2 x 4 warp grid, 64x64 tiles
    const int bm = blockIdx.y * 128, bn = blockIdx.x * 256;
    const uint32_t sb = smem_u32(smem);

    const __half* Bh = (blockIdx.z == 0) ? Bh_ : Bh2;
    const __half* Bl = (blockIdx.z == 0) ? Bl_ : Bl2;
    float* C = (blockIdx.z == 0) ? C_ : C2;

    if (gsum) { s_sum[tid] = 0.f; s_ss[tid] = 0.f; }

    float acc[4][8][4];
#pragma unroll
    for (int i = 0; i < 4; i++)
#pragma unroll
        for (int j = 0; j < 8; j++)
#pragma unroll
            for (int v = 0; v < 4; v++) acc[i][j][v] = 0.f;

    // ldmatrix base addresses
    const uint32_t a_off = (uint32_t)((wm * 64 + (lane & 15)) * 80 + (lane >> 4) * 16);
    const int b_n = wn * 64 + (lane & 7) + ((lane >> 4) << 3);
    const uint32_t b_koff = (uint32_t)(((lane >> 3) & 1) * 16);

    const int NC = K / GBK;

    g_load_stage<USE_ALO>(sb, Ah, Al, lda, Bh, Bl, ldb, bm, bn, 0, tid);
    CP_COMMIT();
    if (NC > 1) {
        g_load_stage<USE_ALO>(sb + GSTAGE, Ah, Al, lda, Bh, Bl, ldb, bm, bn, GBK, tid);
        CP_COMMIT();
    }

    for (int c = 0; c < NC; c++) {
        if (c + 1 < NC) CP_WAIT1(); else CP_WAIT0();
        __syncthreads();
        if (c + 2 < NC) {
            g_load_stage<USE_ALO>(sb + (uint32_t)((c + 2) % 3) * GSTAGE, Ah, Al, lda,
                                  Bh, Bl, ldb, bm, bn, (c + 2) * GBK, tid);
            CP_COMMIT();
        }
        uint32_t st = sb + (uint32_t)(c % 3) * GSTAGE;
#pragma unroll
        for (int kk = 0; kk < 2; kk++) {              // two k16 steps in BK=32
            uint32_t kb = (uint32_t)(kk * 32);        // bytes
            uint32_t bh[8][2], bl[8][2];
#pragma unroll
            for (int p = 0; p < 4; p++) {
                uint32_t ba = st + GB_HI + (uint32_t)((b_n + p * 16) * 80) + b_koff + kb;
                LDSM4(bh[2 * p][0], bh[2 * p][1], bh[2 * p + 1][0], bh[2 * p + 1][1], ba);
                LDSM4(bl[2 * p][0], bl[2 * p][1], bl[2 * p + 1][0], bl[2 * p + 1][1],
                      ba + (GB_LO - GB_HI));
            }
#pragma unroll
            for (int mt = 0; mt < 4; mt++) {
                uint32_t ah[4], al[4];
                uint32_t aa = st + a_off + (uint32_t)(mt * 16 * 80) + kb;
                LDSM4(ah[0], ah[1], ah[2], ah[3], aa);
                if (USE_ALO) LDSM4(al[0], al[1], al[2], al[3], aa + GA_LO);
#pragma unroll
                for (int nt = 0; nt < 8; nt++) {
                    MMA16816(acc[mt][nt], ah, bh[nt]);
                    MMA16816(acc[mt][nt], ah, bl[nt]);
                    if (USE_ALO) MMA16816(acc[mt][nt], al, bh[nt]);
                }
            }
        }
    }

    // ---------------- epilogue -------------------------------------------------
    if (maxout) {
#pragma unroll
        for (int mt = 0; mt < 4; mt++) {
            int gA = (bm + wm * 64 + mt * 16) >> 3;   // output group rows gA, gA+1
#pragma unroll
            for (int nt = 0; nt < 8; nt++) {
                float m0 = acc[mt][nt][0], m1 = acc[mt][nt][1];
                float m2 = acc[mt][nt][2], m3 = acc[mt][nt][3];
#pragma unroll
                for (int off = 4; off < 32; off <<= 1) {
                    m0 = fmaxf(m0, __shfl_xor_sync(0xFFFFFFFFu, m0, off));
                    m1 = fmaxf(m1, __shfl_xor_sync(0xFFFFFFFFu, m1, off));
                    m2 = fmaxf(m2, __shfl_xor_sync(0xFFFFFFFFu, m2, off));
                    m3 = fmaxf(m3, __shfl_xor_sync(0xFFFFFFFFu, m3, off));
                }
                if (lane < 4) {
                    int col = bn + wn * 64 + nt * 8 + lane * 2;
                    float2 v0 = { m0, m1 }, v1 = { m2, m3 };
                    *(float2*)(maxout + (size_t)gA * ldc + col) = v0;
                    *(float2*)(maxout + (size_t)(gA + 1) * ldc + col) = v1;
                }
            }
        }
    } else {
#pragma unroll
        for (int mt = 0; mt < 4; mt++) {
            int row = bm + wm * 64 + mt * 16 + (lane >> 2);
#pragma unroll
            for (int nt = 0; nt < 8; nt++) {
                int col = bn + wn * 64 + nt * 8 + (lane & 3) * 2;
                float2 v0 = { acc[mt][nt][0], acc[mt][nt][1] };
                float2 v1 = { acc[mt][nt][2], acc[mt][nt][3] };
                *(float2*)(C + (size_t)row * ldc + col) = v0;
                *(float2*)(C + (size_t)(row + 8) * ldc + col) = v1;
            }
        }
    }
    if (gsum) {
#pragma unroll
        for (int nt = 0; nt < 8; nt++) {
            float se = 0.f, so = 0.f, qe = 0.f, qo = 0.f;
#pragma unroll
            for (int mt = 0; mt < 4; mt++) {
                float e0 = acc[mt][nt][0], e1 = acc[mt][nt][1];
                float e2 = acc[mt][nt][2], e3 = acc[mt][nt][3];
                se += e0 + e2; so += e1 + e3;
                qe += e0 * e0 + e2 * e2; qo += e1 * e1 + e3 * e3;
            }
#pragma unroll
            for (int off = 4; off < 32; off <<= 1) {
                se += __shfl_xor_sync(0xFFFFFFFFu, se, off);
                so += __shfl_xor_sync(0xFFFFFFFFu, so, off);
                qe += __shfl_xor_sync(0xFFFFFFFFu, qe, off);
                qo += __shfl_xor_sync(0xFFFFFFFFu, qo, off);
            }
            if (lane < 4) {
                int cl = wn * 64 + nt * 8 + lane * 2;
                atomicAdd(&s_sum[cl], se);     atomicAdd(&s_sum[cl + 1], so);
                atomicAdd(&s_ss[cl], qe);      atomicAdd(&s_ss[cl + 1], qo);
            }
        }
        __syncthreads();
        atomicAdd(&gsum[bn + tid], s_sum[tid]);
        atomicAdd(&gss[bn + tid], s_ss[tid]);
    }
}

// ================= small elementwise / stats kernels ============================
__global__ void lin1_kernel(const float* __restrict__ xyz, const float* __restrict__ W1,
                            float* __restrict__ out) {
    int t = blockIdx.x * blockDim.x + threadIdx.x;
    int r = t >> 6, o = t & 63;
    float x0 = xyz[r * 3 + 0], x1 = xyz[r * 3 + 1], x2 = xyz[r * 3 + 2];
    out[t] = x0 * W1[o * 3 + 0] + x1 * W1[o * 3 + 1] + x2 * W1[o * 3 + 2];
}

__global__ void zero_stats_kernel(float* __restrict__ s, float* __restrict__ q) {
    int t = blockIdx.x * blockDim.x + threadIdx.x;
    if (t < 1024) { s[t] = 0.f; q[t] = 0.f; }
}

__global__ void colstats_kernel(const float* __restrict__ x, int M, int C,
                                float* __restrict__ sum, float* __restrict__ ss) {
    int c = blockIdx.y * blockDim.x + threadIdx.x;
    if (c >= C) return;
    size_t r0 = (size_t)blockIdx.x * 512;
    const float* p = x + r0 * C + c;
    float s = 0.f, q = 0.f;
    for (int r = 0; r < 512; r++) { float v = p[(size_t)r * C]; s += v; q += v * v; }
    atomicAdd(&sum[c], s);
    atomicAdd(&ss[c], q);
}

__device__ __forceinline__ uint32_t pk_h2(float a, float b) {
    __half2 t = __floats2half2_rn(a, b);
    return *(uint32_t*)&t;
}

// BN + ReLU + hi/lo fp16 split (reads fp32 once, writes fp16 pair).
__global__ void bnrelu_split_kernel(const float* __restrict__ x,
                                    const float* __restrict__ sum, const float* __restrict__ ss,
                                    const float* __restrict__ g, const float* __restrict__ bta,
                                    __half* __restrict__ hi, __half* __restrict__ lo,
                                    int Mstat, int Mrows, int C) {
    int t = blockIdx.x * blockDim.x + threadIdx.x;
    int C4 = C >> 2;
    if (t >= Mrows * C4) return;
    int c = (t % C4) << 2;
    float invM = 1.0f / (float)Mstat;
    float4 v = ((const float4*)x)[t];
    float vv[4] = { v.x, v.y, v.z, v.w };
    float o[4];
#pragma unroll
    for (int i = 0; i < 4; i++) {
        float m = sum[c + i] * invM;
        float var = ss[c + i] * invM - m * m;
        float sc = g[c + i] * rsqrtf(var + BN_EPS);
        o[i] = fmaxf((vv[i] - m) * sc + bta[c + i], 0.f);
    }
    float h[4];
#pragma unroll
    for (int i = 0; i < 4; i++) h[i] = __half2float(__float2half_rn(o[i]));
    uint2 H = { pk_h2(o[0], o[1]), pk_h2(o[2], o[3]) };
    uint2 L = { pk_h2(o[0] - h[0], o[1] - h[1]), pk_h2(o[2] - h[2], o[3] - h[3]) };
    ((uint2*)hi)[t] = H;
    ((uint2*)lo)[t] = L;
}

// plain hi/lo split (weights)
__global__ void split_kernel(const float* __restrict__ x,
                             __half* __restrict__ hi, __half* __restrict__ lo, int n4) {
    int t = blockIdx.x * blockDim.x + threadIdx.x;
    if (t >= n4) return;
    float4 v = ((const float4*)x)[t];
    float o[4] = { v.x, v.y, v.z, v.w };
    float h[4];
#pragma unroll
    for (int i = 0; i < 4; i++) h[i] = __half2float(__float2half_rn(o[i]));
    uint2 H = { pk_h2(o[0], o[1]), pk_h2(o[2], o[3]) };
    uint2 L = { pk_h2(o[0] - h[0], o[1] - h[1]), pk_h2(o[2] - h[2], o[3] - h[3]) };
    ((uint2*)hi)[t] = H;
    ((uint2*)lo)[t] = L;
}

// kNN: k=8 smallest (stable ties, matches top_k(-d2))
__global__ void knn_kernel(const float* __restrict__ xyz, int* __restrict__ idx) {
    __shared__ float sx[1024], sy[1024], sz[1024], sq[1024];
    int b = blockIdx.y, tid = threadIdx.x;
    for (int i = tid; i < 1024; i += 256) {
        float x = xyz[((b << 10) + i) * 3 + 0];
        float y = xyz[((b << 10) + i) * 3 + 1];
        float z = xyz[((b << 10) + i) * 3 + 2];
        sx[i] = x; sy[i] = y; sz[i] = z;
        sq[i] = x * x + y * y + z * z;
    }
    __syncthreads();
    int n = blockIdx.x * 256 + tid;
    float qx = sx[n], qy = sy[n], qz = sz[n], qs = sq[n];
    float bd[8]; int bi[8];
#pragma unroll
    for (int j = 0; j < 8; j++) { bd[j] = 3.4e38f; bi[j] = 0; }
    for (int m = 0; m < 1024; m++) {
        float d2 = qs + sq[m] - 2.f * (qx * sx[m] + qy * sy[m] + qz * sz[m]);
        if (d2 < bd[7]) {
            bd[7] = d2; bi[7] = m;
#pragma unroll
            for (int j = 7; j > 0; j--) {
                if (bd[j] < bd[j - 1]) {
                    float td = bd[j]; bd[j] = bd[j - 1]; bd[j - 1] = td;
                    int ti = bi[j]; bi[j] = bi[j - 1]; bi[j - 1] = ti;
                }
            }
        }
    }
#pragma unroll
    for (int j = 0; j < 8; j++) idx[((b << 10) + n) * 8 + j] = bi[j];
}

// expand stats only (no materialization): o = Q[idx]-Qc+Rc, column sum/sumsq.
// grid: (65536/256, C4/128), block 128.
__global__ void expand_stats_kernel(const float4* __restrict__ Q, const float4* __restrict__ R,
                                    const int* __restrict__ idx, int C4,
                                    float* __restrict__ gsum, float* __restrict__ gss) {
    __shared__ int sidx[256];
    int c4 = blockIdx.y * 128 + threadIdx.x;
    int r0 = blockIdx.x * 256;
    for (int i = threadIdx.x; i < 256; i += 128) sidx[i] = idx[r0 + i];
    __syncthreads();
    int bn0 = r0 >> 3;
    int b = bn0 >> 10;
    float s[4] = {0.f, 0.f, 0.f, 0.f}, q[4] = {0.f, 0.f, 0.f, 0.f};
    for (int gg = 0; gg < 32; gg++) {
        int bn = bn0 + gg;
        float4 qc = Q[(size_t)bn * C4 + c4];
        float4 rr = R[(size_t)bn * C4 + c4];
        float bx = rr.x - qc.x, by = rr.y - qc.y, bz = rr.z - qc.z, bw = rr.w - qc.w;
#pragma unroll
        for (int k = 0; k < 8; k++) {
            int src = (b << 10) + sidx[gg * 8 + k];
            float4 qa = Q[(size_t)src * C4 + c4];
            float ox = qa.x + bx, oy = qa.y + by, oz = qa.z + bz, ow = qa.w + bw;
            s[0] += ox; s[1] += oy; s[2] += oz; s[3] += ow;
            q[0] += ox * ox; q[1] += oy * oy; q[2] += oz * oz; q[3] += ow * ow;
        }
    }
    int c = c4 << 2;
#pragma unroll
    for (int i = 0; i < 4; i++) { atomicAdd(&gsum[c + i], s[i]); atomicAdd(&gss[c + i], q[i]); }
}

// expand recompute + BN + ReLU + fp16 hi (lo never consumed: 2-product GEMM2 next).
__global__ void expand_bnrelu_split_kernel(
        const float4* __restrict__ Q, const float4* __restrict__ R,
        const int* __restrict__ idx, int C4,
        const float* __restrict__ sum, const float* __restrict__ ss,
        const float* __restrict__ g, const float* __restrict__ bta,
        __half* __restrict__ hi) {
    __shared__ int sidx[256];
    int c4 = blockIdx.y * 128 + threadIdx.x;
    int r0 = blockIdx.x * 256;
    for (int i = threadIdx.x; i < 256; i += 128) sidx[i] = idx[r0 + i];
    __syncthreads();
    int bn0 = r0 >> 3;
    int b = bn0 >> 10;
    const float invM = 1.0f / 65536.0f;
    int c = c4 << 2;
    float m[4], sc[4], bb[4];
#pragma unroll
    for (int i = 0; i < 4; i++) {
        m[i] = sum[c + i] * invM;
        float var = ss[c + i] * invM - m[i] * m[i];
        sc[i] = g[c + i] * rsqrtf(var + BN_EPS);
        bb[i] = bta[c + i];
    }
    for (int gg = 0; gg < 32; gg++) {
        int bn = bn0 + gg;
        float4 qc = Q[(size_t)bn * C4 + c4];
        float4 rr = R[(size_t)bn * C4 + c4];
        float bx = rr.x - qc.x, by = rr.y - qc.y, bz = rr.z - qc.z, bw = rr.w - qc.w;
#pragma unroll
        for (int k = 0; k < 8; k++) {
            int row = bn * 8 + k;
            int src = (b << 10) + sidx[gg * 8 + k];
            float4 qa = Q[(size_t)src * C4 + c4];
            float o[4] = { qa.x + bx, qa.y + by, qa.z + bz, qa.w + bw };
#pragma unroll
            for (int i = 0; i < 4; i++)
                o[i] = fmaxf((o[i] - m[i]) * sc[i] + bb[i], 0.f);
            uint2 H = { pk_h2(o[0], o[1]), pk_h2(o[2], o[3]) };
            ((uint2*)hi)[(size_t)row * C4 + c4] = H;
        }
    }
}

// finish: BN+ReLU of raw max (stats over 65536 raw rows) -> fp16 PAIR (l0, QR-B 3-prod)
__global__ void finish_split_kernel(const float* __restrict__ mx,
                                    const float* __restrict__ sum, const float* __restrict__ ss,
                                    const float* __restrict__ g, const float* __restrict__ bta,
                                    __half* __restrict__ hi, __half* __restrict__ lo, int C) {
    int t = blockIdx.x * blockDim.x + threadIdx.x;
    int C4 = C >> 2;
    if (t >= 8192 * C4) return;
    int c = (t % C4) << 2;
    const float invM = 1.0f / 65536.0f;
    float4 v = ((const float4*)mx)[t];
    float vv[4] = { v.x, v.y, v.z, v.w };
    float o[4], h[4];
#pragma unroll
    for (int i = 0; i < 4; i++) {
        float m = sum[c + i] * invM;
        float var = ss[c + i] * invM - m * m;
        float sc = g[c + i] * rsqrtf(var + BN_EPS);
        o[i] = fmaxf((vv[i] - m) * sc + bta[c + i], 0.f);
        h[i] = __half2float(__float2half_rn(o[i]));
    }
    uint2 H = { pk_h2(o[0], o[1]), pk_h2(o[2], o[3]) };
    uint2 L = { pk_h2(o[0] - h[0], o[1] - h[1]), pk_h2(o[2] - h[2], o[3] - h[3]) };
    ((uint2*)hi)[t] = H;
    ((uint2*)lo)[t] = L;
}

// finish: BN+ReLU of raw max + transpose to (B, C, N). C=1024.
// grid (32, 32, 8), block (32,8)
__global__ void finish_out_t_kernel(const float* __restrict__ mx,
                                    const float* __restrict__ sum, const float* __restrict__ ss,
                                    const float* __restrict__ g, const float* __restrict__ bta,
                                    float* __restrict__ out) {
    __shared__ float tile[32][33];
    int b = blockIdx.z;
    int n0 = blockIdx.x * 32;
    int c0 = blockIdx.y * 32;
    int c = c0 + threadIdx.x;
    const float invM = 1.0f / 65536.0f;
    float m = sum[c] * invM;
    float var = ss[c] * invM - m * m;
    float sc = g[c] * rsqrtf(var + BN_EPS);
    float bb = bta[c];
#pragma unroll
    for (int j = 0; j < 4; j++) {
        int nl = threadIdx.y + j * 8;
        int bn = (b << 10) + n0 + nl;
        float v = mx[(size_t)bn * 1024 + c];
        tile[threadIdx.x][nl] = fmaxf((v - m) * sc + bb, 0.f);
    }
    __syncthreads();
#pragma unroll
    for (int j = 0; j < 4; j++) {
        int cl = threadIdx.y + j * 8;
        out[((size_t)b * 1024 + c0 + cl) * 1024 + n0 + threadIdx.x] = tile[cl][threadIdx.x];
    }
}

// ================= host orchestration ===========================================
extern "C" void kernel_launch(void* const* d_in, const int* in_sizes, int n_in,
                              void* d_out, int out_size) {
    const float* xyz = (const float*)d_in[0];
    const float* W1  = (const float*)d_in[1];
    const float* g1  = (const float*)d_in[2];
    const float* b1  = (const float*)d_in[3];
    const float* W2  = (const float*)d_in[4];
    const float* g2  = (const float*)d_in[5];
    const float* b2  = (const float*)d_in[6];
    const float* WA1 = (const float*)d_in[7];
    const float* gA1 = (const float*)d_in[8];
    const float* bA1 = (const float*)d_in[9];
    const float* WA2 = (const float*)d_in[10];
    const float* gA2 = (const float*)d_in[11];
    const float* bA2 = (const float*)d_in[12];
    const float* WB1 = (const float*)d_in[13];
    const float* gB1 = (const float*)d_in[14];
    const float* bB1 = (const float*)d_in[15];
    const float* WB2 = (const float*)d_in[16];
    const float* gB2 = (const float*)d_in[17];
    const float* bB2 = (const float*)d_in[18];
    float* out = (float*)d_out;

    float *h1, *h2, *Q, *R, *mx, *sumb, *ssb;
    __half *h1h, *h1l, *h2h, *h2l, *l0h, *l0l, *Ah;
    __half *W2h, *W2l, *WA1h, *WA1l, *WA2h, *WA2l, *WB1h, *WB1l, *WB2h, *WB2l;
    int* idx;
    cudaGetSymbolAddress((void**)&h1, d_h1);   cudaGetSymbolAddress((void**)&h1h, d_h1h);
    cudaGetSymbolAddress((void**)&h1l, d_h1l); cudaGetSymbolAddress((void**)&h2, d_h2);
    cudaGetSymbolAddress((void**)&h2h, d_h2h); cudaGetSymbolAddress((void**)&h2l, d_h2l);
    cudaGetSymbolAddress((void**)&l0h, d_l0h); cudaGetSymbolAddress((void**)&l0l, d_l0l);
    cudaGetSymbolAddress((void**)&idx, d_idx); cudaGetSymbolAddress((void**)&Q, d_Q);
    cudaGetSymbolAddress((void**)&R, d_R);     cudaGetSymbolAddress((void**)&mx, d_mx);
    cudaGetSymbolAddress((void**)&Ah, d_Ah);
    cudaGetSymbolAddress((void**)&W2h, d_W2h);   cudaGetSymbolAddress((void**)&W2l, d_W2l);
    cudaGetSymbolAddress((void**)&WA1h, d_WA1h); cudaGetSymbolAddress((void**)&WA1l, d_WA1l);
    cudaGetSymbolAddress((void**)&WA2h, d_WA2h); cudaGetSymbolAddress((void**)&WA2l, d_WA2l);
    cudaGetSymbolAddress((void**)&WB1h, d_WB1h); cudaGetSymbolAddress((void**)&WB1l, d_WB1l);
    cudaGetSymbolAddress((void**)&WB2h, d_WB2h); cudaGetSymbolAddress((void**)&WB2l, d_WB2l);
    cudaGetSymbolAddress((void**)&sumb, d_sum);  cudaGetSymbolAddress((void**)&ssb, d_ss);

    cudaFuncSetAttribute(gemm_hmma_kernel<true>,
                         cudaFuncAttributeMaxDynamicSharedMemorySize, GSMEM_DYN);
    cudaFuncSetAttribute(gemm_hmma_kernel<false>,
                         cudaFuncAttributeMaxDynamicSharedMemorySize, GSMEM_DYN);
    const int T = 256;

    // weight splits
    split_kernel<<<16, T>>>(W2, W2h, W2l, 256 * 64 / 4);
    split_kernel<<<256, T>>>(WA1, WA1h, WA1l, 512 * 512 / 4);
    split_kernel<<<256, T>>>(WA2, WA2h, WA2l, 512 * 512 / 4);
    split_kernel<<<1024, T>>>(WB1, WB1h, WB1l, 1024 * 1024 / 4);
    split_kernel<<<1024, T>>>(WB2, WB2h, WB2l, 1024 * 1024 / 4);

    // kNN
    knn_kernel<<<dim3(4, 8), T>>>(xyz, idx);

    // layer 1: h1 = bn_relu(xyz @ W1^T), split
    lin1_kernel<<<2048, T>>>(xyz, W1, h1);
    zero_stats_kernel<<<4, T>>>(sumb, ssb);
    colstats_kernel<<<dim3(16, 1), T>>>(h1, 8192, 64, sumb, ssb);
    bnrelu_split_kernel<<<512, T>>>(h1, sumb, ssb, g1, b1, h1h, h1l, 8192, 8192, 64);

    // layer 2: h2 = h1 @ W2^T (+stats), 3-product, bn_relu split
    zero_stats_kernel<<<4, T>>>(sumb, ssb);
    gemm_hmma_kernel<true><<<dim3(1, 64, 1), T, GSMEM_DYN>>>(
        h1h, h1l, 64, W2h, W2l, nullptr, nullptr, 64,
        h2, nullptr, nullptr, 256, 64, sumb, ssb);
    bnrelu_split_kernel<<<2048, T>>>(h2, sumb, ssb, g2, b2, h2h, h2l, 8192, 8192, 256);

    // ---- local_op A: QR 3-product (fused z), GEMM2-A 2-product ----
    gemm_hmma_kernel<true><<<dim3(2, 64, 2), T, GSMEM_DYN>>>(
        h2h, h2l, 256, WA1h, WA1l, WA1h + 256, WA1l + 256, 512,
        Q, R, nullptr, 512, 256, nullptr, nullptr);
    zero_stats_kernel<<<4, T>>>(sumb, ssb);
    expand_stats_kernel<<<dim3(256, 1), 128>>>((const float4*)Q, (const float4*)R, idx,
                                               128, sumb, ssb);
    expand_bnrelu_split_kernel<<<dim3(256, 1), 128>>>(
        (const float4*)Q, (const float4*)R, idx, 128, sumb, ssb, gA1, bA1, Ah);
    zero_stats_kernel<<<4, T>>>(sumb, ssb);
    gemm_hmma_kernel<false><<<dim3(2, 512, 1), T, GSMEM_DYN>>>(
        Ah, nullptr, 512, WA2h, WA2l, nullptr, nullptr, 512,
        nullptr, nullptr, mx, 512, 512, sumb, ssb);
    finish_split_kernel<<<4096, T>>>(mx, sumb, ssb, gA2, bA2, l0h, l0l, 512);

    // ---- local_op B: QR 3-product (fused z), GEMM2-B 2-product ----
    gemm_hmma_kernel<true><<<dim3(4, 64, 2), T, GSMEM_DYN>>>(
        l0h, l0l, 512, WB1h, WB1l, WB1h + 512, WB1l + 512, 1024,
        Q, R, nullptr, 1024, 512, nullptr, nullptr);
    zero_stats_kernel<<<4, T>>>(sumb, ssb);
    expand_stats_kernel<<<dim3(256, 2), 128>>>((const float4*)Q, (const float4*)R, idx,
                                               256, sumb, ssb);
    expand_bnrelu_split_kernel<<<dim3(256, 2), 128>>>(
        (const float4*)Q, (const float4*)R, idx, 256, sumb, ssb, gB1, bB1, Ah);
    zero_stats_kernel<<<4, T>>>(sumb, ssb);
    gemm_hmma_kernel<false><<<dim3(4, 512, 1), T, GSMEM_DYN>>>(
        Ah, nullptr, 1024, WB2h, WB2l, nullptr, nullptr, 1024,
        nullptr, nullptr, mx, 1024, 1024, sumb, ssb);
    finish_out_t_kernel<<<dim3(32, 32, 8), dim3(32, 8)>>>(mx, sumb, ssb, gB2, bB2, out);
}

// round 12
// speedup vs baseline: 1.6869x; 1.0584x over previous
#include <cuda_runtime.h>
#include <cuda_fp16.h>
#include <cstdint>

#define BN_EPS 1e-5f

// ================= persistent scratch (device globals; no allocations) ==========
__device__ float d_h1[8192 * 64];
__device__ __half d_h1h[8192 * 64], d_h1l[8192 * 64];
__device__ float d_h2[8192 * 256];
__device__ __half d_h2h[8192 * 256], d_h2l[8192 * 256];
__device__ __half d_l0h[8192 * 512], d_l0l[8192 * 512];   // l0 fp16 pair (QR-B 3-prod)
__device__ int   d_idx[8192 * 8];
__device__ float d_Q[8192 * 1024];
__device__ float d_R[8192 * 1024];
__device__ float d_mx[8192 * 1024];                   // raw max-over-k scratch
__device__ __half d_Ah[65536 * 1024];                 // fp16 hi (expanded; 2-prod GEMMs)
__device__ __half d_W2h[256 * 64],     d_W2l[256 * 64];
__device__ __half d_WA1h[512 * 512],   d_WA1l[512 * 512];
__device__ __half d_WA2h[512 * 512],   d_WA2l[512 * 512];
__device__ __half d_WB1h[1024 * 1024], d_WB1l[1024 * 1024];
__device__ __half d_WB2h[1024 * 1024], d_WB2l[1024 * 1024];
__device__ float d_sum[6 * 1024];                     // 6 independent stat buffers
__device__ float d_ss[6 * 1024];

// ================= PTX helpers (arch-neutral, sm_80+) ===========================
__device__ __forceinline__ uint32_t smem_u32(const void* p) {
    uint32_t a;
    asm("{ .reg .u64 t; cvta.to.shared.u64 t, %1; cvt.u32.u64 %0, t; }" : "=r"(a) : "l"(p));
    return a;
}
__device__ __forceinline__ void cpa16(uint32_t s, const void* g) {
    asm volatile("cp.async.cg.shared.global [%0], [%1], 16;" :: "r"(s), "l"(g));
}
#define CP_COMMIT() asm volatile("cp.async.commit_group;" ::: "memory")
#define CP_WAIT0()  asm volatile("cp.async.wait_group 0;" ::: "memory")
#define CP_WAIT1()  asm volatile("cp.async.wait_group 1;" ::: "memory")
#define CP_WAIT2()  asm volatile("cp.async.wait_group 2;" ::: "memory")

#define LDSM4(r0, r1, r2, r3, a) \
    asm volatile("ldmatrix.sync.aligned.m8n8.x4.shared.b16 {%0,%1,%2,%3}, [%4];" \
                 : "=r"(r0), "=r"(r1), "=r"(r2), "=r"(r3) : "r"(a))

#define MMA16816(c, a, b) \
    asm volatile("mma.sync.aligned.m16n8k16.row.col.f32.f16.f16.f32 " \
                 "{%0,%1,%2,%3}, {%4,%5,%6,%7}, {%8,%9}, {%0,%1,%2,%3};" \
                 : "+f"((c)[0]), "+f"((c)[1]), "+f"((c)[2]), "+f"((c)[3]) \
                 : "r"((a)[0]), "r"((a)[1]), "r"((a)[2]), "r"((a)[3]), \
                   "r"((b)[0]), "r"((b)[1]))

// ================= 3-product HMMA GEMM (128M x 256N), unchanged =================
// C = Ah*Bh + Ah*Bl + Al*Bh. 3-stage pipeline. gridDim.z=2 fuses 2 GEMMs sharing A.
#define GBK 32
#define GA_LO  10240u
#define GB_HI  20480u
#define GB_LO  40960u
#define GSTAGE 61440u
#define GSMEM_DYN 184320

__device__ __forceinline__ void g_load_stage(uint32_t st,
        const __half* Ah, const __half* Al, int lda,
        const __half* Bh, const __half* Bl, int ldb,
        int bm, int bn, int kc, int tid) {
#pragma unroll
    for (int t = 0; t < 2; t++) {
        int i = tid + t * 256;
        int row = i >> 2, cg = i & 3;
        uint32_t off = (uint32_t)(row * 80 + cg * 16);
        size_t ga = (size_t)(bm + row) * lda + kc + cg * 8;
        cpa16(st + off, Ah + ga);
        cpa16(st + GA_LO + off, Al + ga);
    }
#pragma unroll
    for (int t = 0; t < 4; t++) {
        int i = tid + t * 256;
        int row = i >> 2, cg = i & 3;
        uint32_t off = (uint32_t)(row * 80 + cg * 16);
        size_t gb = (size_t)(bn + row) * ldb + kc + cg * 8;
        cpa16(st + GB_HI + off, Bh + gb);
        cpa16(st + GB_LO + off, Bl + gb);
    }
}

__global__ void __launch_bounds__(256, 1)
gemm_hmma_kernel(const __half* __restrict__ Ah, const __half* __restrict__ Al, int lda,
                 const __half* __restrict__ Bh_, const __half* __restrict__ Bl_,
                 const __half* __restrict__ Bh2, const __half* __restrict__ Bl2, int ldb,
                 float* __restrict__ C_, float* __restrict__ C2, int ldc, int K,
                 float* __restrict__ gsum, float* __restrict__ gss) {
    extern __shared__ char smem[];
    __shared__ float s_sum[256], s_ss[256];
    const int tid = threadIdx.x;
    const int lane = tid & 31, wid = tid >> 5;
    const int wm = wid & 1, wn = wid >> 1;           // 2 x 4 warp grid, 64x64 tiles
    const int bm = blockIdx.y * 128, bn = blockIdx.x * 256;
    const uint32_t sb = smem_u32(smem);

    const __half* Bh = (blockIdx.z == 0) ? Bh_ : Bh2;
    const __half* Bl = (blockIdx.z == 0) ? Bl_ : Bl2;
    float* C = (blockIdx.z == 0) ? C_ : C2;

    if (gsum) { s_sum[tid] = 0.f; s_ss[tid] = 0.f; }

    float acc[4][8][4];
#pragma unroll
    for (int i = 0; i < 4; i++)
#pragma unroll
        for (int j = 0; j < 8; j++)
#pragma unroll
            for (int v = 0; v < 4; v++) acc[i][j][v] = 0.f;

    const uint32_t a_off = (uint32_t)((wm * 64 + (lane & 15)) * 80 + (lane >> 4) * 16);
    const int b_n = wn * 64 + (lane & 7) + ((lane >> 4) << 3);
    const uint32_t b_koff = (uint32_t)(((lane >> 3) & 1) * 16);

    const int NC = K / GBK;

    g_load_stage(sb, Ah, Al, lda, Bh, Bl, ldb, bm, bn, 0, tid);
    CP_COMMIT();
    if (NC > 1) {
        g_load_stage(sb + GSTAGE, Ah, Al, lda, Bh, Bl, ldb, bm, bn, GBK, tid);
        CP_COMMIT();
    }

    for (int c = 0; c < NC; c++) {
        if (c + 1 < NC) CP_WAIT1(); else CP_WAIT0();
        __syncthreads();
        if (c + 2 < NC) {
            g_load_stage(sb + (uint32_t)((c + 2) % 3) * GSTAGE, Ah, Al, lda,
                         Bh, Bl, ldb, bm, bn, (c + 2) * GBK, tid);
            CP_COMMIT();
        }
        uint32_t st = sb + (uint32_t)(c % 3) * GSTAGE;
#pragma unroll
        for (int kk = 0; kk < 2; kk++) {
            uint32_t kb = (uint32_t)(kk * 32);
            uint32_t bh[8][2], bl[8][2];
#pragma unroll
            for (int p = 0; p < 4; p++) {
                uint32_t ba = st + GB_HI + (uint32_t)((b_n + p * 16) * 80) + b_koff + kb;
                LDSM4(bh[2 * p][0], bh[2 * p][1], bh[2 * p + 1][0], bh[2 * p + 1][1], ba);
                LDSM4(bl[2 * p][0], bl[2 * p][1], bl[2 * p + 1][0], bl[2 * p + 1][1],
                      ba + (GB_LO - GB_HI));
            }
#pragma unroll
            for (int mt = 0; mt < 4; mt++) {
                uint32_t ah[4], al[4];
                uint32_t aa = st + a_off + (uint32_t)(mt * 16 * 80) + kb;
                LDSM4(ah[0], ah[1], ah[2], ah[3], aa);
                LDSM4(al[0], al[1], al[2], al[3], aa + GA_LO);
#pragma unroll
                for (int nt = 0; nt < 8; nt++) {
                    MMA16816(acc[mt][nt], ah, bh[nt]);
                    MMA16816(acc[mt][nt], ah, bl[nt]);
                    MMA16816(acc[mt][nt], al, bh[nt]);
                }
            }
        }
    }

    // epilogue: C write (+ optional fused stats)
#pragma unroll
    for (int mt = 0; mt < 4; mt++) {
        int row = bm + wm * 64 + mt * 16 + (lane >> 2);
#pragma unroll
        for (int nt = 0; nt < 8; nt++) {
            int col = bn + wn * 64 + nt * 8 + (lane & 3) * 2;
            float2 v0 = { acc[mt][nt][0], acc[mt][nt][1] };
            float2 v1 = { acc[mt][nt][2], acc[mt][nt][3] };
            *(float2*)(C + (size_t)row * ldc + col) = v0;
            *(float2*)(C + (size_t)(row + 8) * ldc + col) = v1;
        }
    }
    if (gsum) {
#pragma unroll
        for (int nt = 0; nt < 8; nt++) {
            float se = 0.f, so = 0.f, qe = 0.f, qo = 0.f;
#pragma unroll
            for (int mt = 0; mt < 4; mt++) {
                float e0 = acc[mt][nt][0], e1 = acc[mt][nt][1];
                float e2 = acc[mt][nt][2], e3 = acc[mt][nt][3];
                se += e0 + e2; so += e1 + e3;
                qe += e0 * e0 + e2 * e2; qo += e1 * e1 + e3 * e3;
            }
#pragma unroll
            for (int off = 4; off < 32; off <<= 1) {
                se += __shfl_xor_sync(0xFFFFFFFFu, se, off);
                so += __shfl_xor_sync(0xFFFFFFFFu, so, off);
                qe += __shfl_xor_sync(0xFFFFFFFFu, qe, off);
                qo += __shfl_xor_sync(0xFFFFFFFFu, qo, off);
            }
            if (lane < 4) {
                int cl = wn * 64 + nt * 8 + lane * 2;
                atomicAdd(&s_sum[cl], se);     atomicAdd(&s_sum[cl + 1], so);
                atomicAdd(&s_ss[cl], qe);      atomicAdd(&s_ss[cl + 1], qo);
            }
        }
        __syncthreads();
        atomicAdd(&gsum[bn + tid], s_sum[tid]);
        atomicAdd(&gss[bn + tid], s_ss[tid]);
    }
}

// ================= 2-product HMMA GEMM (256M x 128N), traffic-optimized =========
// C = Ah*Bh + Ah*Bl (A hi only). 4-stage pipeline, fused max-over-k + stats only.
#define H2_BH  20480u                 // A hi: 256*80 = 20480
#define H2_BL  30720u
#define H2_STG 40960u
#define H2_SMEM_DYN 163840            // 4 stages

__device__ __forceinline__ void h2_load_stage(uint32_t st,
        const __half* Ah, int lda, const __half* Bh, const __half* Bl, int ldb,
        int bm, int bn, int kc, int tid) {
#pragma unroll
    for (int t = 0; t < 4; t++) {                 // A: 1024 chunks of 16B
        int i = tid + t * 256;
        int row = i >> 2, cg = i & 3;
        uint32_t off = (uint32_t)(row * 80 + cg * 16);
        cpa16(st + off, Ah + (size_t)(bm + row) * lda + kc + cg * 8);
    }
#pragma unroll
    for (int t = 0; t < 2; t++) {                 // B: 512 chunks each half
        int i = tid + t * 256;
        int row = i >> 2, cg = i & 3;
        uint32_t off = (uint32_t)(row * 80 + cg * 16);
        size_t gb = (size_t)(bn + row) * ldb + kc + cg * 8;
        cpa16(st + H2_BH + off, Bh + gb);
        cpa16(st + H2_BL + off, Bl + gb);
    }
}

__global__ void __launch_bounds__(256, 1)
gemm_hmma2_kernel(const __half* __restrict__ Ah, int lda,
                  const __half* __restrict__ Bh, const __half* __restrict__ Bl, int ldb,
                  float* __restrict__ maxout, int ldc, int K,
                  float* __restrict__ gsum, float* __restrict__ gss) {
    extern __shared__ char smem[];
    __shared__ float s_sum[128], s_ss[128];
    const int tid = threadIdx.x;
    const int lane = tid & 31, wid = tid >> 5;
    const int wm = wid & 3, wn = wid >> 2;           // 4 x 2 warp grid, 64x64 tiles
    const int bm = blockIdx.y * 256, bn = blockIdx.x * 128;
    const uint32_t sb = smem_u32(smem);

    if (tid < 128) { s_sum[tid] = 0.f; s_ss[tid] = 0.f; }

    float acc[4][8][4];
#pragma unroll
    for (int i = 0; i < 4; i++)
#pragma unroll
        for (int j = 0; j < 8; j++)
#pragma unroll
            for (int v = 0; v < 4; v++) acc[i][j][v] = 0.f;

    const uint32_t a_off = (uint32_t)((wm * 64 + (lane & 15)) * 80 + (lane >> 4) * 16);
    const int b_n = wn * 64 + (lane & 7) + ((lane >> 4) << 3);
    const uint32_t b_koff = (uint32_t)(((lane >> 3) & 1) * 16);

    const int NC = K / GBK;          // NC >= 3 for all uses (16 or 32)

    h2_load_stage(sb, Ah, lda, Bh, Bl, ldb, bm, bn, 0, tid);
    CP_COMMIT();
    h2_load_stage(sb + H2_STG, Ah, lda, Bh, Bl, ldb, bm, bn, GBK, tid);
    CP_COMMIT();
    h2_load_stage(sb + 2 * H2_STG, Ah, lda, Bh, Bl, ldb, bm, bn, 2 * GBK, tid);
    CP_COMMIT();

    for (int c = 0; c < NC; c++) {
        if (c + 2 < NC) CP_WAIT2();
        else if (c + 1 < NC) CP_WAIT1();
        else CP_WAIT0();
        __syncthreads();
        if (c + 3 < NC) {
            h2_load_stage(sb + (uint32_t)((c + 3) & 3) * H2_STG, Ah, lda, Bh, Bl, ldb,
                          bm, bn, (c + 3) * GBK, tid);
            CP_COMMIT();
        }
        uint32_t st = sb + (uint32_t)(c & 3) * H2_STG;
#pragma unroll
        for (int kk = 0; kk < 2; kk++) {
            uint32_t kb = (uint32_t)(kk * 32);
            uint32_t bh[8][2], bl[8][2];
#pragma unroll
            for (int p = 0; p < 4; p++) {
                uint32_t ba = st + H2_BH + (uint32_t)((b_n + p * 16) * 80) + b_koff + kb;
                LDSM4(bh[2 * p][0], bh[2 * p][1], bh[2 * p + 1][0], bh[2 * p + 1][1], ba);
                LDSM4(bl[2 * p][0], bl[2 * p][1], bl[2 * p + 1][0], bl[2 * p + 1][1],
                      ba + (H2_BL - H2_BH));
            }
#pragma unroll
            for (int mt = 0; mt < 4; mt++) {
                uint32_t ah[4];
                uint32_t aa = st + a_off + (uint32_t)(mt * 16 * 80) + kb;
                LDSM4(ah[0], ah[1], ah[2], ah[3], aa);
#pragma unroll
                for (int nt = 0; nt < 8; nt++) {
                    MMA16816(acc[mt][nt], ah, bh[nt]);
                    MMA16816(acc[mt][nt], ah, bl[nt]);
                }
            }
        }
    }

    // epilogue: fused raw max over k=8 groups + column stats
#pragma unroll
    for (int mt = 0; mt < 4; mt++) {
        int gA = (bm + wm * 64 + mt * 16) >> 3;
#pragma unroll
        for (int nt = 0; nt < 8; nt++) {
            float m0 = acc[mt][nt][0], m1 = acc[mt][nt][1];
            float m2 = acc[mt][nt][2], m3 = acc[mt][nt][3];
#pragma unroll
            for (int off = 4; off < 32; off <<= 1) {
                m0 = fmaxf(m0, __shfl_xor_sync(0xFFFFFFFFu, m0, off));
                m1 = fmaxf(m1, __shfl_xor_sync(0xFFFFFFFFu, m1, off));
                m2 = fmaxf(m2, __shfl_xor_sync(0xFFFFFFFFu, m2, off));
                m3 = fmaxf(m3, __shfl_xor_sync(0xFFFFFFFFu, m3, off));
            }
            if (lane < 4) {
                int col = bn + wn * 64 + nt * 8 + lane * 2;
                float2 v0 = { m0, m1 }, v1 = { m2, m3 };
                *(float2*)(maxout + (size_t)gA * ldc + col) = v0;
                *(float2*)(maxout + (size_t)(gA + 1) * ldc + col) = v1;
            }
        }
    }
#pragma unroll
    for (int nt = 0; nt < 8; nt++) {
        float se = 0.f, so = 0.f, qe = 0.f, qo = 0.f;
#pragma unroll
        for (int mt = 0; mt < 4; mt++) {
            float e0 = acc[mt][nt][0], e1 = acc[mt][nt][1];
            float e2 = acc[mt][nt][2], e3 = acc[mt][nt][3];
            se += e0 + e2; so += e1 + e3;
            qe += e0 * e0 + e2 * e2; qo += e1 * e1 + e3 * e3;
        }
#pragma unroll
        for (int off = 4; off < 32; off <<= 1) {
            se += __shfl_xor_sync(0xFFFFFFFFu, se, off);
            so += __shfl_xor_sync(0xFFFFFFFFu, so, off);
            qe += __shfl_xor_sync(0xFFFFFFFFu, qe, off);
            qo += __shfl_xor_sync(0xFFFFFFFFu, qo, off);
        }
        if (lane < 4) {
            int cl = wn * 64 + nt * 8 + lane * 2;
            atomicAdd(&s_sum[cl], se);     atomicAdd(&s_sum[cl + 1], so);
            atomicAdd(&s_ss[cl], qe);      atomicAdd(&s_ss[cl + 1], qo);
        }
    }
    __syncthreads();
    if (tid < 128) {
        atomicAdd(&gsum[bn + tid], s_sum[tid]);
        atomicAdd(&gss[bn + tid], s_ss[tid]);
    }
}

// ================= small elementwise / stats kernels ============================
__device__ __forceinline__ uint32_t pk_h2(float a, float b) {
    __half2 t = __floats2half2_rn(a, b);
    return *(uint32_t*)&t;
}

__device__ __forceinline__ void split4(const float* __restrict__ x,
                                       __half* __restrict__ hi, __half* __restrict__ lo,
                                       int t) {
    float4 v = ((const float4*)x)[t];
    float o[4] = { v.x, v.y, v.z, v.w };
    float h[4];
#pragma unroll
    for (int i = 0; i < 4; i++) h[i] = __half2float(__float2half_rn(o[i]));
    uint2 H = { pk_h2(o[0], o[1]), pk_h2(o[2], o[3]) };
    uint2 L = { pk_h2(o[0] - h[0], o[1] - h[1]), pk_h2(o[2] - h[2], o[3] - h[3]) };
    ((uint2*)hi)[t] = H;
    ((uint2*)lo)[t] = L;
}

// combined: all 5 weight splits + zero all 6 stat buffer pairs. grid 2588 x 256.
__global__ void splitzero_kernel(
        const float* W2, __half* W2h, __half* W2l,
        const float* WA1, __half* WA1h, __half* WA1l,
        const float* WA2, __half* WA2h, __half* WA2l,
        const float* WB1, __half* WB1h, __half* WB1l,
        const float* WB2, __half* WB2h, __half* WB2l,
        float* sum, float* ss) {
    int t = blockIdx.x * 256 + threadIdx.x;
    if (t < 4096)          split4(W2,  W2h,  W2l,  t);
    else if (t < 69632)    split4(WA1, WA1h, WA1l, t - 4096);
    else if (t < 135168)   split4(WA2, WA2h, WA2l, t - 69632);
    else if (t < 397312)   split4(WB1, WB1h, WB1l, t - 135168);
    else if (t < 659456)   split4(WB2, WB2h, WB2l, t - 397312);
    else if (t < 660992)   ((float4*)sum)[t - 659456] = make_float4(0.f, 0.f, 0.f, 0.f);
    else if (t < 662528)   ((float4*)ss)[t - 660992]  = make_float4(0.f, 0.f, 0.f, 0.f);
}

__global__ void lin1_kernel(const float* __restrict__ xyz, const float* __restrict__ W1,
                            float* __restrict__ out) {
    int t = blockIdx.x * blockDim.x + threadIdx.x;
    int r = t >> 6, o = t & 63;
    float x0 = xyz[r * 3 + 0], x1 = xyz[r * 3 + 1], x2 = xyz[r * 3 + 2];
    out[t] = x0 * W1[o * 3 + 0] + x1 * W1[o * 3 + 1] + x2 * W1[o * 3 + 2];
}

__global__ void colstats_kernel(const float* __restrict__ x, int M, int C,
                                float* __restrict__ sum, float* __restrict__ ss) {
    int c = blockIdx.y * blockDim.x + threadIdx.x;
    if (c >= C) return;
    size_t r0 = (size_t)blockIdx.x * 512;
    const float* p = x + r0 * C + c;
    float s = 0.f, q = 0.f;
    for (int r = 0; r < 512; r++) { float v = p[(size_t)r * C]; s += v; q += v * v; }
    atomicAdd(&sum[c], s);
    atomicAdd(&ss[c], q);
}

// BN + ReLU + hi/lo fp16 split (reads fp32 once, writes fp16 pair).
__global__ void bnrelu_split_kernel(const float* __restrict__ x,
                                    const float* __restrict__ sum, const float* __restrict__ ss,
                                    const float* __restrict__ g, const float* __restrict__ bta,
                                    __half* __restrict__ hi, __half* __restrict__ lo,
                                    int Mstat, int Mrows, int C) {
    int t = blockIdx.x * blockDim.x + threadIdx.x;
    int C4 = C >> 2;
    if (t >= Mrows * C4) return;
    int c = (t % C4) << 2;
    float invM = 1.0f / (float)Mstat;
    float4 v = ((const float4*)x)[t];
    float vv[4] = { v.x, v.y, v.z, v.w };
    float o[4];
#pragma unroll
    for (int i = 0; i < 4; i++) {
        float m = sum[c + i] * invM;
        float var = ss[c + i] * invM - m * m;
        float sc = g[c + i] * rsqrtf(var + BN_EPS);
        o[i] = fmaxf((vv[i] - m) * sc + bta[c + i], 0.f);
    }
    float h[4];
#pragma unroll
    for (int i = 0; i < 4; i++) h[i] = __half2float(__float2half_rn(o[i]));
    uint2 H = { pk_h2(o[0], o[1]), pk_h2(o[2], o[3]) };
    uint2 L = { pk_h2(o[0] - h[0], o[1] - h[1]), pk_h2(o[2] - h[2], o[3] - h[3]) };
    ((uint2*)hi)[t] = H;
    ((uint2*)lo)[t] = L;
}

// kNN: k=8 smallest (stable ties, matches top_k(-d2))
__global__ void knn_kernel(const float* __restrict__ xyz, int* __restrict__ idx) {
    __shared__ float sx[1024], sy[1024], sz[1024], sq[1024];
    int b = blockIdx.y, tid = threadIdx.x;
    for (int i = tid; i < 1024; i += 256) {
        float x = xyz[((b << 10) + i) * 3 + 0];
        float y = xyz[((b << 10) + i) * 3 + 1];
        float z = xyz[((b << 10) + i) * 3 + 2];
        sx[i] = x; sy[i] = y; sz[i] = z;
        sq[i] = x * x + y * y + z * z;
    }
    __syncthreads();
    int n = blockIdx.x * 256 + tid;
    float qx = sx[n], qy = sy[n], qz = sz[n], qs = sq[n];
    float bd[8]; int bi[8];
#pragma unroll
    for (int j = 0; j < 8; j++) { bd[j] = 3.4e38f; bi[j] = 0; }
    for (int m = 0; m < 1024; m++) {
        float d2 = qs + sq[m] - 2.f * (qx * sx[m] + qy * sy[m] + qz * sz[m]);
        if (d2 < bd[7]) {
            bd[7] = d2; bi[7] = m;
#pragma unroll
            for (int j = 7; j > 0; j--) {
                if (bd[j] < bd[j - 1]) {
                    float td = bd[j]; bd[j] = bd[j - 1]; bd[j - 1] = td;
                    int ti = bi[j]; bi[j] = bi[j - 1]; bi[j - 1] = ti;
                }
            }
        }
    }
#pragma unroll
    for (int j = 0; j < 8; j++) idx[((b << 10) + n) * 8 + j] = bi[j];
}

// expand stats only: o = Q[idx]-Qc+Rc, column sum/sumsq.
__global__ void expand_stats_kernel(const float4* __restrict__ Q, const float4* __restrict__ R,
                                    const int* __restrict__ idx, int C4,
                                    float* __restrict__ gsum, float* __restrict__ gss) {
    __shared__ int sidx[256];
    int c4 = blockIdx.y * 128 + threadIdx.x;
    int r0 = blockIdx.x * 256;
    for (int i = threadIdx.x; i < 256; i += 128) sidx[i] = idx[r0 + i];
    __syncthreads();
    int bn0 = r0 >> 3;
    int b = bn0 >> 10;
    float s[4] = {0.f, 0.f, 0.f, 0.f}, q[4] = {0.f, 0.f, 0.f, 0.f};
    for (int gg = 0; gg < 32; gg++) {
        int bn = bn0 + gg;
        float4 qc = Q[(size_t)bn * C4 + c4];
        float4 rr = R[(size_t)bn * C4 + c4];
        float bx = rr.x - qc.x, by = rr.y - qc.y, bz = rr.z - qc.z, bw = rr.w - qc.w;
#pragma unroll
        for (int k = 0; k < 8; k++) {
            int src = (b << 10) + sidx[gg * 8 + k];
            float4 qa = Q[(size_t)src * C4 + c4];
            float ox = qa.x + bx, oy = qa.y + by, oz = qa.z + bz, ow = qa.w + bw;
            s[0] += ox; s[1] += oy; s[2] += oz; s[3] += ow;
            q[0] += ox * ox; q[1] += oy * oy; q[2] += oz * oz; q[3] += ow * ow;
        }
    }
    int c = c4 << 2;
#pragma unroll
    for (int i = 0; i < 4; i++) { atomicAdd(&gsum[c + i], s[i]); atomicAdd(&gss[c + i], q[i]); }
}

// expand recompute + BN + ReLU + fp16 hi (lo never consumed: 2-product GEMM2 next).
__global__ void expand_bnrelu_split_kernel(
        const float4* __restrict__ Q, const float4* __restrict__ R,
        const int* __restrict__ idx, int C4,
        const float* __restrict__ sum, const float* __restrict__ ss,
        const float* __restrict__ g, const float* __restrict__ bta,
        __half* __restrict__ hi) {
    __shared__ int sidx[256];
    int c4 = blockIdx.y * 128 + threadIdx.x;
    int r0 = blockIdx.x * 256;
    for (int i = threadIdx.x; i < 256; i += 128) sidx[i] = idx[r0 + i];
    __syncthreads();
    int bn0 = r0 >> 3;
    int b = bn0 >> 10;
    const float invM = 1.0f / 65536.0f;
    int c = c4 << 2;
    float m[4], sc[4], bb[4];
#pragma unroll
    for (int i = 0; i < 4; i++) {
        m[i] = sum[c + i] * invM;
        float var = ss[c + i] * invM - m[i] * m[i];
        sc[i] = g[c + i] * rsqrtf(var + BN_EPS);
        bb[i] = bta[c + i];
    }
    for (int gg = 0; gg < 32; gg++) {
        int bn = bn0 + gg;
        float4 qc = Q[(size_t)bn * C4 + c4];
        float4 rr = R[(size_t)bn * C4 + c4];
        float bx = rr.x - qc.x, by = rr.y - qc.y, bz = rr.z - qc.z, bw = rr.w - qc.w;
#pragma unroll
        for (int k = 0; k < 8; k++) {
            int row = bn * 8 + k;
            int src = (b << 10) + sidx[gg * 8 + k];
            float4 qa = Q[(size_t)src * C4 + c4];
            float o[4] = { qa.x + bx, qa.y + by, qa.z + bz, qa.w + bw };
#pragma unroll
            for (int i = 0; i < 4; i++)
                o[i] = fmaxf((o[i] - m[i]) * sc[i] + bb[i], 0.f);
            uint2 H = { pk_h2(o[0], o[1]), pk_h2(o[2], o[3]) };
            ((uint2*)hi)[(size_t)row * C4 + c4] = H;
        }
    }
}

// finish: BN+ReLU of raw max (stats over 65536 raw rows) -> fp16 PAIR (l0, QR-B 3-prod)
__global__ void finish_split_kernel(const float* __restrict__ mx,
                                    const float* __restrict__ sum, const float* __restrict__ ss,
                                    const float* __restrict__ g, const float* __restrict__ bta,
                                    __half* __restrict__ hi, __half* __restrict__ lo, int C) {
    int t = blockIdx.x * blockDim.x + threadIdx.x;
    int C4 = C >> 2;
    if (t >= 8192 * C4) return;
    int c = (t % C4) << 2;
    const float invM = 1.0f / 65536.0f;
    float4 v = ((const float4*)mx)[t];
    float vv[4] = { v.x, v.y, v.z, v.w };
    float o[4], h[4];
#pragma unroll
    for (int i = 0; i < 4; i++) {
        float m = sum[c + i] * invM;
        float var = ss[c + i] * invM - m * m;
        float sc = g[c + i] * rsqrtf(var + BN_EPS);
        o[i] = fmaxf((vv[i] - m) * sc + bta[c + i], 0.f);
        h[i] = __half2float(__float2half_rn(o[i]));
    }
    uint2 H = { pk_h2(o[0], o[1]), pk_h2(o[2], o[3]) };
    uint2 L = { pk_h2(o[0] - h[0], o[1] - h[1]), pk_h2(o[2] - h[2], o[3] - h[3]) };
    ((uint2*)hi)[t] = H;
    ((uint2*)lo)[t] = L;
}

// finish: BN+ReLU of raw max + transpose to (B, C, N). C=1024.
__global__ void finish_out_t_kernel(const float* __restrict__ mx,
                                    const float* __restrict__ sum, const float* __restrict__ ss,
                                    const float* __restrict__ g, const float* __restrict__ bta,
                                    float* __restrict__ out) {
    __shared__ float tile[32][33];
    int b = blockIdx.z;
    int n0 = blockIdx.x * 32;
    int c0 = blockIdx.y * 32;
    int c = c0 + threadIdx.x;
    const float invM = 1.0f / 65536.0f;
    float m = sum[c] * invM;
    float var = ss[c] * invM - m * m;
    float sc = g[c] * rsqrtf(var + BN_EPS);
    float bb = bta[c];
#pragma unroll
    for (int j = 0; j < 4; j++) {
        int nl = threadIdx.y + j * 8;
        int bn = (b << 10) + n0 + nl;
        float v = mx[(size_t)bn * 1024 + c];
        tile[threadIdx.x][nl] = fmaxf((v - m) * sc + bb, 0.f);
    }
    __syncthreads();
#pragma unroll
    for (int j = 0; j < 4; j++) {
        int cl = threadIdx.y + j * 8;
        out[((size_t)b * 1024 + c0 + cl) * 1024 + n0 + threadIdx.x] = tile[cl][threadIdx.x];
    }
}

// ================= host orchestration ===========================================
extern "C" void kernel_launch(void* const* d_in, const int* in_sizes, int n_in,
                              void* d_out, int out_size) {
    const float* xyz = (const float*)d_in[0];
    const float* W1  = (const float*)d_in[1];
    const float* g1  = (const float*)d_in[2];
    const float* b1  = (const float*)d_in[3];
    const float* W2  = (const float*)d_in[4];
    const float* g2  = (const float*)d_in[5];
    const float* b2  = (const float*)d_in[6];
    const float* WA1 = (const float*)d_in[7];
    const float* gA1 = (const float*)d_in[8];
    const float* bA1 = (const float*)d_in[9];
    const float* WA2 = (const float*)d_in[10];
    const float* gA2 = (const float*)d_in[11];
    const float* bA2 = (const float*)d_in[12];
    const float* WB1 = (const float*)d_in[13];
    const float* gB1 = (const float*)d_in[14];
    const float* bB1 = (const float*)d_in[15];
    const float* WB2 = (const float*)d_in[16];
    const float* gB2 = (const float*)d_in[17];
    const float* bB2 = (const float*)d_in[18];
    float* out = (float*)d_out;

    float *h1, *h2, *Q, *R, *mx, *sumb, *ssb;
    __half *h1h, *h1l, *h2h, *h2l, *l0h, *l0l, *Ah;
    __half *W2h, *W2l, *WA1h, *WA1l, *WA2h, *WA2l, *WB1h, *WB1l, *WB2h, *WB2l;
    int* idx;
    cudaGetSymbolAddress((void**)&h1, d_h1);   cudaGetSymbolAddress((void**)&h1h, d_h1h);
    cudaGetSymbolAddress((void**)&h1l, d_h1l); cudaGetSymbolAddress((void**)&h2, d_h2);
    cudaGetSymbolAddress((void**)&h2h, d_h2h); cudaGetSymbolAddress((void**)&h2l, d_h2l);
    cudaGetSymbolAddress((void**)&l0h, d_l0h); cudaGetSymbolAddress((void**)&l0l, d_l0l);
    cudaGetSymbolAddress((void**)&idx, d_idx); cudaGetSymbolAddress((void**)&Q, d_Q);
    cudaGetSymbolAddress((void**)&R, d_R);     cudaGetSymbolAddress((void**)&mx, d_mx);
    cudaGetSymbolAddress((void**)&Ah, d_Ah);
    cudaGetSymbolAddress((void**)&W2h, d_W2h);   cudaGetSymbolAddress((void**)&W2l, d_W2l);
    cudaGetSymbolAddress((void**)&WA1h, d_WA1h); cudaGetSymbolAddress((void**)&WA1l, d_WA1l);
    cudaGetSymbolAddress((void**)&WA2h, d_WA2h); cudaGetSymbolAddress((void**)&WA2l, d_WA2l);
    cudaGetSymbolAddress((void**)&WB1h, d_WB1h); cudaGetSymbolAddress((void**)&WB1l, d_WB1l);
    cudaGetSymbolAddress((void**)&WB2h, d_WB2h); cudaGetSymbolAddress((void**)&WB2l, d_WB2l);
    cudaGetSymbolAddress((void**)&sumb, d_sum);  cudaGetSymbolAddress((void**)&ssb, d_ss);

    // stat buffer slices: 0=layer1, 1=layer2, 2=expandA, 3=gemm2A, 4=expandB, 5=gemm2B
    float* S[6];  float* Q_[6];
    for (int i = 0; i < 6; i++) { S[i] = sumb + 1024 * i; Q_[i] = ssb + 1024 * i; }

    cudaFuncSetAttribute(gemm_hmma_kernel,
                         cudaFuncAttributeMaxDynamicSharedMemorySize, GSMEM_DYN);
    cudaFuncSetAttribute(gemm_hmma2_kernel,
                         cudaFuncAttributeMaxDynamicSharedMemorySize, H2_SMEM_DYN);
    const int T = 256;

    // (1) all weight splits + zero all stats
    splitzero_kernel<<<2588, T>>>(W2, W2h, W2l, WA1, WA1h, WA1l, WA2, WA2h, WA2l,
                                  WB1, WB1h, WB1l, WB2, WB2h, WB2l, sumb, ssb);
    // (2-4) layer 1
    lin1_kernel<<<2048, T>>>(xyz, W1, h1);
    colstats_kernel<<<dim3(16, 1), T>>>(h1, 8192, 64, S[0], Q_[0]);
    bnrelu_split_kernel<<<512, T>>>(h1, S[0], Q_[0], g1, b1, h1h, h1l, 8192, 8192, 64);
    // (5) layer 2 GEMM (3-product, fused stats) — profiled launch
    gemm_hmma_kernel<<<dim3(1, 64, 1), T, GSMEM_DYN>>>(
        h1h, h1l, 64, W2h, W2l, nullptr, nullptr, 64,
        h2, nullptr, 256, 64, S[1], Q_[1]);
    // (6) kNN
    knn_kernel<<<dim3(4, 8), T>>>(xyz, idx);
    // (7) layer-2 BN+ReLU+split
    bnrelu_split_kernel<<<2048, T>>>(h2, S[1], Q_[1], g2, b2, h2h, h2l, 8192, 8192, 256);

    // ---- local_op A: QR 3-product (fused z), GEMM2-A 2-product (256x128 tile) ----
    gemm_hmma_kernel<<<dim3(2, 64, 2), T, GSMEM_DYN>>>(
        h2h, h2l, 256, WA1h, WA1l, WA1h + 256, WA1l + 256, 512,
        Q, R, 512, 256, nullptr, nullptr);
    expand_stats_kernel<<<dim3(256, 1), 128>>>((const float4*)Q, (const float4*)R, idx,
                                               128, S[2], Q_[2]);
    expand_bnrelu_split_kernel<<<dim3(256, 1), 128>>>(
        (const float4*)Q, (const float4*)R, idx, 128, S[2], Q_[2], gA1, bA1, Ah);
    gemm_hmma2_kernel<<<dim3(4, 256), T, H2_SMEM_DYN>>>(
        Ah, 512, WA2h, WA2l, 512, mx, 512, 512, S[3], Q_[3]);
    finish_split_kernel<<<4096, T>>>(mx, S[3], Q_[3], gA2, bA2, l0h, l0l, 512);

    // ---- local_op B: QR 3-product (fused z), GEMM2-B 2-product (256x128 tile) ----
    gemm_hmma_kernel<<<dim3(4, 64, 2), T, GSMEM_DYN>>>(
        l0h, l0l, 512, WB1h, WB1l, WB1h + 512, WB1l + 512, 1024,
        Q, R, 1024, 512, nullptr, nullptr);
    expand_stats_kernel<<<dim3(256, 2), 128>>>((const float4*)Q, (const float4*)R, idx,
                                               256, S[4], Q_[4]);
    expand_bnrelu_split_kernel<<<dim3(256, 2), 128>>>(
        (const float4*)Q, (const float4*)R, idx, 256, S[4], Q_[4], gB1, bB1, Ah);
    gemm_hmma2_kernel<<<dim3(8, 256), T, H2_SMEM_DYN>>>(
        Ah, 1024, WB2h, WB2l, 1024, mx, 1024, 1024, S[5], Q_[5]);
    finish_out_t_kernel<<<dim3(32, 32, 8), dim3(32, 8)>>>(mx, S[5], Q_[5], gB2, bB2, out);
}

// round 14
// speedup vs baseline: 1.9124x; 1.1337x over previous
#include <cuda_runtime.h>
#include <cuda_fp16.h>
#include <cstdint>

#define BN_EPS 1e-5f

// ================= persistent scratch (device globals; no allocations) ==========
__device__ float d_h1[8192 * 64];
__device__ __half d_h1h[8192 * 64], d_h1l[8192 * 64];
__device__ float d_h2[8192 * 256];
__device__ __half d_h2h[8192 * 256], d_h2l[8192 * 256];
__device__ __half d_l0h[8192 * 512], d_l0l[8192 * 512];   // l0 fp16 pair (QR-B 3-prod)
__device__ int   d_idx[8192 * 8];
__device__ float d_Q[8192 * 1024];
__device__ float d_R[8192 * 1024];
__device__ float d_mx[8192 * 1024];                   // raw max-over-k scratch
__device__ __half d_Ah[65536 * 1024];                 // fp16 hi (expanded)
__device__ __half d_Al[65536 * 512];                  // fp16 lo (expanded; A path only)
__device__ __half d_W2h[256 * 64],     d_W2l[256 * 64];
__device__ __half d_WA1h[512 * 512],   d_WA1l[512 * 512];
__device__ __half d_WA2h[512 * 512],   d_WA2l[512 * 512];
__device__ __half d_WB1h[1024 * 1024], d_WB1l[1024 * 1024];
__device__ __half d_WB2h[1024 * 1024], d_WB2l[1024 * 1024];
__device__ float d_sum[6 * 1024];
__device__ float d_ss[6 * 1024];

// ================= PTX helpers (arch-neutral, sm_80+) ===========================
__device__ __forceinline__ uint32_t smem_u32(const void* p) {
    uint32_t a;
    asm("{ .reg .u64 t; cvta.to.shared.u64 t, %1; cvt.u32.u64 %0, t; }" : "=r"(a) : "l"(p));
    return a;
}
__device__ __forceinline__ void cpa16(uint32_t s, const void* g) {
    asm volatile("cp.async.cg.shared.global [%0], [%1], 16;" :: "r"(s), "l"(g));
}
#define CP_COMMIT() asm volatile("cp.async.commit_group;" ::: "memory")
#define CP_WAIT0()  asm volatile("cp.async.wait_group 0;" ::: "memory")
#define CP_WAIT1()  asm volatile("cp.async.wait_group 1;" ::: "memory")
#define CP_WAIT2()  asm volatile("cp.async.wait_group 2;" ::: "memory")

#define LDSM4(r0, r1, r2, r3, a) \
    asm volatile("ldmatrix.sync.aligned.m8n8.x4.shared.b16 {%0,%1,%2,%3}, [%4];" \
                 : "=r"(r0), "=r"(r1), "=r"(r2), "=r"(r3) : "r"(a))

#define MMA16816(c, a, b) \
    asm volatile("mma.sync.aligned.m16n8k16.row.col.f32.f16.f16.f32 " \
                 "{%0,%1,%2,%3}, {%4,%5,%6,%7}, {%8,%9}, {%0,%1,%2,%3};" \
                 : "+f"((c)[0]), "+f"((c)[1]), "+f"((c)[2]), "+f"((c)[3]) \
                 : "r"((a)[0]), "r"((a)[1]), "r"((a)[2]), "r"((a)[3]), \
                   "r"((b)[0]), "r"((b)[1]))

// ================= 3-product HMMA GEMM (128M x 256N), C-writer ==================
// C = Ah*Bh + Ah*Bl + Al*Bh. 3-stage pipeline. gridDim.z=2 fuses 2 GEMMs sharing A.
#define GBK 32
#define GA_LO  10240u
#define GB_HI  20480u
#define GB_LO  40960u
#define GSTAGE 61440u
#define GSMEM_DYN 184320

__device__ __forceinline__ void g_load_stage(uint32_t st,
        const __half* Ah, const __half* Al, int lda,
        const __half* Bh, const __half* Bl, int ldb,
        int bm, int bn, int kc, int tid) {
#pragma unroll
    for (int t = 0; t < 2; t++) {
        int i = tid + t * 256;
        int row = i >> 2, cg = i & 3;
        uint32_t off = (uint32_t)(row * 80 + cg * 16);
        size_t ga = (size_t)(bm + row) * lda + kc + cg * 8;
        cpa16(st + off, Ah + ga);
        cpa16(st + GA_LO + off, Al + ga);
    }
#pragma unroll
    for (int t = 0; t < 4; t++) {
        int i = tid + t * 256;
        int row = i >> 2, cg = i & 3;
        uint32_t off = (uint32_t)(row * 80 + cg * 16);
        size_t gb = (size_t)(bn + row) * ldb + kc + cg * 8;
        cpa16(st + GB_HI + off, Bh + gb);
        cpa16(st + GB_LO + off, Bl + gb);
    }
}

__global__ void __launch_bounds__(256, 1)
gemm_hmma_kernel(const __half* __restrict__ Ah, const __half* __restrict__ Al, int lda,
                 const __half* __restrict__ Bh_, const __half* __restrict__ Bl_,
                 const __half* __restrict__ Bh2, const __half* __restrict__ Bl2, int ldb,
                 float* __restrict__ C_, float* __restrict__ C2, int ldc, int K,
                 float* __restrict__ gsum, float* __restrict__ gss) {
    extern __shared__ char smem[];
    __shared__ float s_sum[256], s_ss[256];
    const int tid = threadIdx.x;
    const int lane = tid & 31, wid = tid >> 5;
    const int wm = wid & 1, wn = wid >> 1;
    const int bm = blockIdx.y * 128, bn = blockIdx.x * 256;
    const uint32_t sb = smem_u32(smem);

    const __half* Bh = (blockIdx.z == 0) ? Bh_ : Bh2;
    const __half* Bl = (blockIdx.z == 0) ? Bl_ : Bl2;
    float* C = (blockIdx.z == 0) ? C_ : C2;

    if (gsum) { s_sum[tid] = 0.f; s_ss[tid] = 0.f; }

    float acc[4][8][4];
#pragma unroll
    for (int i = 0; i < 4; i++)
#pragma unroll
        for (int j = 0; j < 8; j++)
#pragma unroll
            for (int v = 0; v < 4; v++) acc[i][j][v] = 0.f;

    const uint32_t a_off = (uint32_t)((wm * 64 + (lane & 15)) * 80 + (lane >> 4) * 16);
    const int b_n = wn * 64 + (lane & 7) + ((lane >> 4) << 3);
    const uint32_t b_koff = (uint32_t)(((lane >> 3) & 1) * 16);

    const int NC = K / GBK;

    g_load_stage(sb, Ah, Al, lda, Bh, Bl, ldb, bm, bn, 0, tid);
    CP_COMMIT();
    if (NC > 1) {
        g_load_stage(sb + GSTAGE, Ah, Al, lda, Bh, Bl, ldb, bm, bn, GBK, tid);
        CP_COMMIT();
    }

    for (int c = 0; c < NC; c++) {
        if (c + 1 < NC) CP_WAIT1(); else CP_WAIT0();
        __syncthreads();
        if (c + 2 < NC) {
            g_load_stage(sb + (uint32_t)((c + 2) % 3) * GSTAGE, Ah, Al, lda,
                         Bh, Bl, ldb, bm, bn, (c + 2) * GBK, tid);
            CP_COMMIT();
        }
        uint32_t st = sb + (uint32_t)(c % 3) * GSTAGE;
#pragma unroll
        for (int kk = 0; kk < 2; kk++) {
            uint32_t kb = (uint32_t)(kk * 32);
            uint32_t bh[8][2], bl[8][2];
#pragma unroll
            for (int p = 0; p < 4; p++) {
                uint32_t ba = st + GB_HI + (uint32_t)((b_n + p * 16) * 80) + b_koff + kb;
                LDSM4(bh[2 * p][0], bh[2 * p][1], bh[2 * p + 1][0], bh[2 * p + 1][1], ba);
                LDSM4(bl[2 * p][0], bl[2 * p][1], bl[2 * p + 1][0], bl[2 * p + 1][1],
                      ba + (GB_LO - GB_HI));
            }
#pragma unroll
            for (int mt = 0; mt < 4; mt++) {
                uint32_t ah[4], al[4];
                uint32_t aa = st + a_off + (uint32_t)(mt * 16 * 80) + kb;
                LDSM4(ah[0], ah[1], ah[2], ah[3], aa);
                LDSM4(al[0], al[1], al[2], al[3], aa + GA_LO);
#pragma unroll
                for (int nt = 0; nt < 8; nt++) {
                    MMA16816(acc[mt][nt], ah, bh[nt]);
                    MMA16816(acc[mt][nt], ah, bl[nt]);
                    MMA16816(acc[mt][nt], al, bh[nt]);
                }
            }
        }
    }

#pragma unroll
    for (int mt = 0; mt < 4; mt++) {
        int row = bm + wm * 64 + mt * 16 + (lane >> 2);
#pragma unroll
        for (int nt = 0; nt < 8; nt++) {
            int col = bn + wn * 64 + nt * 8 + (lane & 3) * 2;
            float2 v0 = { acc[mt][nt][0], acc[mt][nt][1] };
            float2 v1 = { acc[mt][nt][2], acc[mt][nt][3] };
            *(float2*)(C + (size_t)row * ldc + col) = v0;
            *(float2*)(C + (size_t)(row + 8) * ldc + col) = v1;
        }
    }
    if (gsum) {
#pragma unroll
        for (int nt = 0; nt < 8; nt++) {
            float se = 0.f, so = 0.f, qe = 0.f, qo = 0.f;
#pragma unroll
            for (int mt = 0; mt < 4; mt++) {
                float e0 = acc[mt][nt][0], e1 = acc[mt][nt][1];
                float e2 = acc[mt][nt][2], e3 = acc[mt][nt][3];
                se += e0 + e2; so += e1 + e3;
                qe += e0 * e0 + e2 * e2; qo += e1 * e1 + e3 * e3;
            }
#pragma unroll
            for (int off = 4; off < 32; off <<= 1) {
                se += __shfl_xor_sync(0xFFFFFFFFu, se, off);
                so += __shfl_xor_sync(0xFFFFFFFFu, so, off);
                qe += __shfl_xor_sync(0xFFFFFFFFu, qe, off);
                qo += __shfl_xor_sync(0xFFFFFFFFu, qo, off);
            }
            if (lane < 4) {
                int cl = wn * 64 + nt * 8 + lane * 2;
                atomicAdd(&s_sum[cl], se);     atomicAdd(&s_sum[cl + 1], so);
                atomicAdd(&s_ss[cl], qe);      atomicAdd(&s_ss[cl + 1], qo);
            }
        }
        __syncthreads();
        atomicAdd(&gsum[bn + tid], s_sum[tid]);
        atomicAdd(&gss[bn + tid], s_ss[tid]);
    }
}

// ================= NPROD-product HMMA GEMM (256M x 128N), max epilogue ==========
// NPROD=3: Ah*Bh+Ah*Bl+Al*Bh ; NPROD=2: Ah*Bh+Ah*Bl ; NPROD=1: Ah*Bh.
// Stage layout: A_hi @0 (20480B) | A_lo @20480 (3p) | Bh @B_OFF | Bl @B_OFF+10240.
template <int NPROD> struct H2C {
    static constexpr uint32_t B_OFF = (NPROD == 3) ? 40960u : 20480u;
    static constexpr uint32_t STG   = (NPROD == 3) ? 61440u : (NPROD == 2 ? 40960u : 30720u);
    static constexpr int      NST   = (NPROD == 3) ? 3 : 4;
    static constexpr int      SMEM  = (int)(STG * NST);
};

template <int NPROD>
__device__ __forceinline__ void h2_load_stage(uint32_t st,
        const __half* Ah, const __half* Al, int lda,
        const __half* Bh, const __half* Bl, int ldb,
        int bm, int bn, int kc, int tid) {
#pragma unroll
    for (int t = 0; t < 4; t++) {                 // A: 1024 chunks of 16B
        int i = tid + t * 256;
        int row = i >> 2, cg = i & 3;
        uint32_t off = (uint32_t)(row * 80 + cg * 16);
        size_t ga = (size_t)(bm + row) * lda + kc + cg * 8;
        cpa16(st + off, Ah + ga);
        if (NPROD == 3) cpa16(st + 20480u + off, Al + ga);
    }
#pragma unroll
    for (int t = 0; t < 2; t++) {                 // B: 512 chunks per half
        int i = tid + t * 256;
        int row = i >> 2, cg = i & 3;
        uint32_t off = (uint32_t)(row * 80 + cg * 16);
        size_t gb = (size_t)(bn + row) * ldb + kc + cg * 8;
        cpa16(st + H2C<NPROD>::B_OFF + off, Bh + gb);
        if (NPROD >= 2) cpa16(st + H2C<NPROD>::B_OFF + 10240u + off, Bl + gb);
    }
}

template <int NPROD>
__global__ void __launch_bounds__(256, 1)
gemm_hmma2_kernel(const __half* __restrict__ Ah, const __half* __restrict__ Al, int lda,
                  const __half* __restrict__ Bh, const __half* __restrict__ Bl, int ldb,
                  float* __restrict__ maxout, int ldc, int K,
                  float* __restrict__ gsum, float* __restrict__ gss) {
    constexpr uint32_t STG = H2C<NPROD>::STG;
    constexpr int NST = H2C<NPROD>::NST;
    extern __shared__ char smem[];
    __shared__ float s_sum[128], s_ss[128];
    const int tid = threadIdx.x;
    const int lane = tid & 31, wid = tid >> 5;
    const int wm = wid & 3, wn = wid >> 2;           // 4 x 2 warp grid, 64x64 tiles
    const int bm = blockIdx.y * 256, bn = blockIdx.x * 128;
    const uint32_t sb = smem_u32(smem);

    if (tid < 128) { s_sum[tid] = 0.f; s_ss[tid] = 0.f; }

    float acc[4][8][4];
#pragma unroll
    for (int i = 0; i < 4; i++)
#pragma unroll
        for (int j = 0; j < 8; j++)
#pragma unroll
            for (int v = 0; v < 4; v++) acc[i][j][v] = 0.f;

    const uint32_t a_off = (uint32_t)((wm * 64 + (lane & 15)) * 80 + (lane >> 4) * 16);
    const int b_n = wn * 64 + (lane & 7) + ((lane >> 4) << 3);
    const uint32_t b_koff = (uint32_t)(((lane >> 3) & 1) * 16);

    const int NC = K / GBK;          // NC >= 16 for all uses

#pragma unroll
    for (int s = 0; s < NST - 1; s++) {
        h2_load_stage<NPROD>(sb + (uint32_t)s * STG, Ah, Al, lda, Bh, Bl, ldb,
                             bm, bn, s * GBK, tid);
        CP_COMMIT();
    }

    for (int c = 0; c < NC; c++) {
        if (NST == 4) {
            if (c + 2 < NC) CP_WAIT2();
            else if (c + 1 < NC) CP_WAIT1();
            else CP_WAIT0();
        } else {
            if (c + 1 < NC) CP_WAIT1(); else CP_WAIT0();
        }
        __syncthreads();
        if (c + NST - 1 < NC) {
            h2_load_stage<NPROD>(sb + (uint32_t)((c + NST - 1) % NST) * STG,
                                 Ah, Al, lda, Bh, Bl, ldb, bm, bn,
                                 (c + NST - 1) * GBK, tid);
            CP_COMMIT();
        }
        uint32_t st = sb + (uint32_t)(c % NST) * STG;
#pragma unroll
        for (int kk = 0; kk < 2; kk++) {
            uint32_t kb = (uint32_t)(kk * 32);
            uint32_t bh[8][2], bl[8][2];
#pragma unroll
            for (int p = 0; p < 4; p++) {
                uint32_t ba = st + H2C<NPROD>::B_OFF +
                              (uint32_t)((b_n + p * 16) * 80) + b_koff + kb;
                LDSM4(bh[2 * p][0], bh[2 * p][1], bh[2 * p + 1][0], bh[2 * p + 1][1], ba);
                if (NPROD >= 2)
                    LDSM4(bl[2 * p][0], bl[2 * p][1], bl[2 * p + 1][0], bl[2 * p + 1][1],
                          ba + 10240u);
            }
#pragma unroll
            for (int mt = 0; mt < 4; mt++) {
                uint32_t ah[4], al[4];
                uint32_t aa = st + a_off + (uint32_t)(mt * 16 * 80) + kb;
                LDSM4(ah[0], ah[1], ah[2], ah[3], aa);
                if (NPROD == 3) LDSM4(al[0], al[1], al[2], al[3], aa + 20480u);
#pragma unroll
                for (int nt = 0; nt < 8; nt++) {
                    MMA16816(acc[mt][nt], ah, bh[nt]);
                    if (NPROD >= 2) MMA16816(acc[mt][nt], ah, bl[nt]);
                    if (NPROD == 3) MMA16816(acc[mt][nt], al, bh[nt]);
                }
            }
        }
    }

    // epilogue: fused raw max over k=8 groups + column stats
#pragma unroll
    for (int mt = 0; mt < 4; mt++) {
        int gA = (bm + wm * 64 + mt * 16) >> 3;
#pragma unroll
        for (int nt = 0; nt < 8; nt++) {
            float m0 = acc[mt][nt][0], m1 = acc[mt][nt][1];
            float m2 = acc[mt][nt][2], m3 = acc[mt][nt][3];
#pragma unroll
            for (int off = 4; off < 32; off <<= 1) {
                m0 = fmaxf(m0, __shfl_xor_sync(0xFFFFFFFFu, m0, off));
                m1 = fmaxf(m1, __shfl_xor_sync(0xFFFFFFFFu, m1, off));
                m2 = fmaxf(m2, __shfl_xor_sync(0xFFFFFFFFu, m2, off));
                m3 = fmaxf(m3, __shfl_xor_sync(0xFFFFFFFFu, m3, off));
            }
            if (lane < 4) {
                int col = bn + wn * 64 + nt * 8 + lane * 2;
                float2 v0 = { m0, m1 }, v1 = { m2, m3 };
                *(float2*)(maxout + (size_t)gA * ldc + col) = v0;
                *(float2*)(maxout + (size_t)(gA + 1) * ldc + col) = v1;
            }
        }
    }
#pragma unroll
    for (int nt = 0; nt < 8; nt++) {
        float se = 0.f, so = 0.f, qe = 0.f, qo = 0.f;
#pragma unroll
        for (int mt = 0; mt < 4; mt++) {
            float e0 = acc[mt][nt][0], e1 = acc[mt][nt][1];
            float e2 = acc[mt][nt][2], e3 = acc[mt][nt][3];
            se += e0 + e2; so += e1 + e3;
            qe += e0 * e0 + e2 * e2; qo += e1 * e1 + e3 * e3;
        }
#pragma unroll
        for (int off = 4; off < 32; off <<= 1) {
            se += __shfl_xor_sync(0xFFFFFFFFu, se, off);
            so += __shfl_xor_sync(0xFFFFFFFFu, so, off);
            qe += __shfl_xor_sync(0xFFFFFFFFu, qe, off);
            qo += __shfl_xor_sync(0xFFFFFFFFu, qo, off);
        }
        if (lane < 4) {
            int cl = wn * 64 + nt * 8 + lane * 2;
            atomicAdd(&s_sum[cl], se);     atomicAdd(&s_sum[cl + 1], so);
            atomicAdd(&s_ss[cl], qe);      atomicAdd(&s_ss[cl + 1], qo);
        }
    }
    __syncthreads();
    if (tid < 128) {
        atomicAdd(&gsum[bn + tid], s_sum[tid]);
        atomicAdd(&gss[bn + tid], s_ss[tid]);
    }
}

// ================= small elementwise / stats kernels ============================
__device__ __forceinline__ uint32_t pk_h2(float a, float b) {
    __half2 t = __floats2half2_rn(a, b);
    return *(uint32_t*)&t;
}

__device__ __forceinline__ void split4(const float* __restrict__ x,
                                       __half* __restrict__ hi, __half* __restrict__ lo,
                                       int t) {
    float4 v = ((const float4*)x)[t];
    float o[4] = { v.x, v.y, v.z, v.w };
    float h[4];
#pragma unroll
    for (int i = 0; i < 4; i++) h[i] = __half2float(__float2half_rn(o[i]));
    uint2 H = { pk_h2(o[0], o[1]), pk_h2(o[2], o[3]) };
    uint2 L = { pk_h2(o[0] - h[0], o[1] - h[1]), pk_h2(o[2] - h[2], o[3] - h[3]) };
    ((uint2*)hi)[t] = H;
    ((uint2*)lo)[t] = L;
}

// combined: all 5 weight splits + zero all 6 stat buffer pairs.
__global__ void splitzero_kernel(
        const float* W2, __half* W2h, __half* W2l,
        const float* WA1, __half* WA1h, __half* WA1l,
        const float* WA2, __half* WA2h, __half* WA2l,
        const float* WB1, __half* WB1h, __half* WB1l,
        const float* WB2, __half* WB2h, __half* WB2l,
        float* sum, float* ss) {
    int t = blockIdx.x * 256 + threadIdx.x;
    if (t < 4096)          split4(W2,  W2h,  W2l,  t);
    else if (t < 69632)    split4(WA1, WA1h, WA1l, t - 4096);
    else if (t < 135168)   split4(WA2, WA2h, WA2l, t - 69632);
    else if (t < 397312)   split4(WB1, WB1h, WB1l, t - 135168);
    else if (t < 659456)   split4(WB2, WB2h, WB2l, t - 397312);
    else if (t < 660992)   ((float4*)sum)[t - 659456] = make_float4(0.f, 0.f, 0.f, 0.f);
    else if (t < 662528)   ((float4*)ss)[t - 660992]  = make_float4(0.f, 0.f, 0.f, 0.f);
}

__global__ void lin1_kernel(const float* __restrict__ xyz, const float* __restrict__ W1,
                            float* __restrict__ out) {
    int t = blockIdx.x * blockDim.x + threadIdx.x;
    int r = t >> 6, o = t & 63;
    float x0 = xyz[r * 3 + 0], x1 = xyz[r * 3 + 1], x2 = xyz[r * 3 + 2];
    out[t] = x0 * W1[o * 3 + 0] + x1 * W1[o * 3 + 1] + x2 * W1[o * 3 + 2];
}

__global__ void colstats_kernel(const float* __restrict__ x, int M, int C,
                                float* __restrict__ sum, float* __restrict__ ss) {
    int c = blockIdx.y * blockDim.x + threadIdx.x;
    if (c >= C) return;
    size_t r0 = (size_t)blockIdx.x * 512;
    const float* p = x + r0 * C + c;
    float s = 0.f, q = 0.f;
    for (int r = 0; r < 512; r++) { float v = p[(size_t)r * C]; s += v; q += v * v; }
    atomicAdd(&sum[c], s);
    atomicAdd(&ss[c], q);
}

// BN + ReLU + hi/lo fp16 split (reads fp32 once, writes fp16 pair).
__global__ void bnrelu_split_kernel(const float* __restrict__ x,
                                    const float* __restrict__ sum, const float* __restrict__ ss,
                                    const float* __restrict__ g, const float* __restrict__ bta,
                                    __half* __restrict__ hi, __half* __restrict__ lo,
                                    int Mstat, int Mrows, int C) {
    int t = blockIdx.x * blockDim.x + threadIdx.x;
    int C4 = C >> 2;
    if (t >= Mrows * C4) return;
    int c = (t % C4) << 2;
    float invM = 1.0f / (float)Mstat;
    float4 v = ((const float4*)x)[t];
    float vv[4] = { v.x, v.y, v.z, v.w };
    float o[4];
#pragma unroll
    for (int i = 0; i < 4; i++) {
        float m = sum[c + i] * invM;
        float var = ss[c + i] * invM - m * m;
        float sc = g[c + i] * rsqrtf(var + BN_EPS);
        o[i] = fmaxf((vv[i] - m) * sc + bta[c + i], 0.f);
    }
    float h[4];
#pragma unroll
    for (int i = 0; i < 4; i++) h[i] = __half2float(__float2half_rn(o[i]));
    uint2 H = { pk_h2(o[0], o[1]), pk_h2(o[2], o[3]) };
    uint2 L = { pk_h2(o[0] - h[0], o[1] - h[1]), pk_h2(o[2] - h[2], o[3] - h[3]) };
    ((uint2*)hi)[t] = H;
    ((uint2*)lo)[t] = L;
}

// kNN: k=8 smallest (stable ties, matches top_k(-d2))
__global__ void knn_kernel(const float* __restrict__ xyz, int* __restrict__ idx) {
    __shared__ float sx[1024], sy[1024], sz[1024], sq[1024];
    int b = blockIdx.y, tid = threadIdx.x;
    for (int i = tid; i < 1024; i += 256) {
        float x = xyz[((b << 10) + i) * 3 + 0];
        float y = xyz[((b << 10) + i) * 3 + 1];
        float z = xyz[((b << 10) + i) * 3 + 2];
        sx[i] = x; sy[i] = y; sz[i] = z;
        sq[i] = x * x + y * y + z * z;
    }
    __syncthreads();
    int n = blockIdx.x * 256 + tid;
    float qx = sx[n], qy = sy[n], qz = sz[n], qs = sq[n];
    float bd[8]; int bi[8];
#pragma unroll
    for (int j = 0; j < 8; j++) { bd[j] = 3.4e38f; bi[j] = 0; }
    for (int m = 0; m < 1024; m++) {
        float d2 = qs + sq[m] - 2.f * (qx * sx[m] + qy * sy[m] + qz * sz[m]);
        if (d2 < bd[7]) {
            bd[7] = d2; bi[7] = m;
#pragma unroll
            for (int j = 7; j > 0; j--) {
                if (bd[j] < bd[j - 1]) {
                    float td = bd[j]; bd[j] = bd[j - 1]; bd[j - 1] = td;
                    int ti = bi[j]; bi[j] = bi[j - 1]; bi[j - 1] = ti;
                }
            }
        }
    }
#pragma unroll
    for (int j = 0; j < 8; j++) idx[((b << 10) + n) * 8 + j] = bi[j];
}

// expand stats only: o = Q[idx]-Qc+Rc, column sum/sumsq.
__global__ void expand_stats_kernel(const float4* __restrict__ Q, const float4* __restrict__ R,
                                    const int* __restrict__ idx, int C4,
                                    float* __restrict__ gsum, float* __restrict__ gss) {
    __shared__ int sidx[256];
    int c4 = blockIdx.y * 128 + threadIdx.x;
    int r0 = blockIdx.x * 256;
    for (int i = threadIdx.x; i < 256; i += 128) sidx[i] = idx[r0 + i];
    __syncthreads();
    int bn0 = r0 >> 3;
    int b = bn0 >> 10;
    float s[4] = {0.f, 0.f, 0.f, 0.f}, q[4] = {0.f, 0.f, 0.f, 0.f};
    for (int gg = 0; gg < 32; gg++) {
        int bn = bn0 + gg;
        float4 qc = Q[(size_t)bn * C4 + c4];
        float4 rr = R[(size_t)bn * C4 + c4];
        float bx = rr.x - qc.x, by = rr.y - qc.y, bz = rr.z - qc.z, bw = rr.w - qc.w;
#pragma unroll
        for (int k = 0; k < 8; k++) {
            int src = (b << 10) + sidx[gg * 8 + k];
            float4 qa = Q[(size_t)src * C4 + c4];
            float ox = qa.x + bx, oy = qa.y + by, oz = qa.z + bz, ow = qa.w + bw;
            s[0] += ox; s[1] += oy; s[2] += oz; s[3] += ow;
            q[0] += ox * ox; q[1] += oy * oy; q[2] += oz * oz; q[3] += ow * ow;
        }
    }
    int c = c4 << 2;
#pragma unroll
    for (int i = 0; i < 4; i++) { atomicAdd(&gsum[c + i], s[i]); atomicAdd(&gss[c + i], q[i]); }
}

// expand recompute + BN + ReLU + fp16 split (WRITE_LO=false -> hi only).
template <bool WRITE_LO>
__global__ void expand_bnrelu_split_kernel(
        const float4* __restrict__ Q, const float4* __restrict__ R,
        const int* __restrict__ idx, int C4,
        const float* __restrict__ sum, const float* __restrict__ ss,
        const float* __restrict__ g, const float* __restrict__ bta,
        __half* __restrict__ hi, __half* __restrict__ lo) {
    __shared__ int sidx[256];
    int c4 = blockIdx.y * 128 + threadIdx.x;
    int r0 = blockIdx.x * 256;
    for (int i = threadIdx.x; i < 256; i += 128) sidx[i] = idx[r0 + i];
    __syncthreads();
    int bn0 = r0 >> 3;
    int b = bn0 >> 10;
    const float invM = 1.0f / 65536.0f;
    int c = c4 << 2;
    float m[4], sc[4], bb[4];
#pragma unroll
    for (int i = 0; i < 4; i++) {
        m[i] = sum[c + i] * invM;
        float var = ss[c + i] * invM - m[i] * m[i];
        sc[i] = g[c + i] * rsqrtf(var + BN_EPS);
        bb[i] = bta[c + i];
    }
    for (int gg = 0; gg < 32; gg++) {
        int bn = bn0 + gg;
        float4 qc = Q[(size_t)bn * C4 + c4];
        float4 rr = R[(size_t)bn * C4 + c4];
        float bx = rr.x - qc.x, by = rr.y - qc.y, bz = rr.z - qc.z, bw = rr.w - qc.w;
#pragma unroll
        for (int k = 0; k < 8; k++) {
            int row = bn * 8 + k;
            int src = (b << 10) + sidx[gg * 8 + k];
            float4 qa = Q[(size_t)src * C4 + c4];
            float o[4] = { qa.x + bx, qa.y + by, qa.z + bz, qa.w + bw };
            float h[4];
#pragma unroll
            for (int i = 0; i < 4; i++) {
                o[i] = fmaxf((o[i] - m[i]) * sc[i] + bb[i], 0.f);
                h[i] = __half2float(__float2half_rn(o[i]));
            }
            uint2 H = { pk_h2(o[0], o[1]), pk_h2(o[2], o[3]) };
            ((uint2*)hi)[(size_t)row * C4 + c4] = H;
            if (WRITE_LO) {
                uint2 L = { pk_h2(o[0] - h[0], o[1] - h[1]),
                            pk_h2(o[2] - h[2], o[3] - h[3]) };
                ((uint2*)lo)[(size_t)row * C4 + c4] = L;
            }
        }
    }
}

// finish: BN+ReLU of raw max (stats over 65536 raw rows) -> fp16 PAIR (l0)
__global__ void finish_split_kernel(const float* __restrict__ mx,
                                    const float* __restrict__ sum, const float* __restrict__ ss,
                                    const float* __restrict__ g, const float* __restrict__ bta,
                                    __half* __restrict__ hi, __half* __restrict__ lo, int C) {
    int t = blockIdx.x * blockDim.x + threadIdx.x;
    int C4 = C >> 2;
    if (t >= 8192 * C4) return;
    int c = (t % C4) << 2;
    const float invM = 1.0f / 65536.0f;
    float4 v = ((const float4*)mx)[t];
    float vv[4] = { v.x, v.y, v.z, v.w };
    float o[4], h[4];
#pragma unroll
    for (int i = 0; i < 4; i++) {
        float m = sum[c + i] * invM;
        float var = ss[c + i] * invM - m * m;
        float sc = g[c + i] * rsqrtf(var + BN_EPS);
        o[i] = fmaxf((vv[i] - m) * sc + bta[c + i], 0.f);
        h[i] = __half2float(__float2half_rn(o[i]));
    }
    uint2 H = { pk_h2(o[0], o[1]), pk_h2(o[2], o[3]) };
    uint2 L = { pk_h2(o[0] - h[0], o[1] - h[1]), pk_h2(o[2] - h[2], o[3] - h[3]) };
    ((uint2*)hi)[t] = H;
    ((uint2*)lo)[t] = L;
}

// finish: BN+ReLU of raw max + transpose to (B, C, N). C=1024.
__global__ void finish_out_t_kernel(const float* __restrict__ mx,
                                    const float* __restrict__ sum, const float* __restrict__ ss,
                                    const float* __restrict__ g, const float* __restrict__ bta,
                                    float* __restrict__ out) {
    __shared__ float tile[32][33];
    int b = blockIdx.z;
    int n0 = blockIdx.x * 32;
    int c0 = blockIdx.y * 32;
    int c = c0 + threadIdx.x;
    const float invM = 1.0f / 65536.0f;
    float m = sum[c] * invM;
    float var = ss[c] * invM - m * m;
    float sc = g[c] * rsqrtf(var + BN_EPS);
    float bb = bta[c];
#pragma unroll
    for (int j = 0; j < 4; j++) {
        int nl = threadIdx.y + j * 8;
        int bn = (b << 10) + n0 + nl;
        float v = mx[(size_t)bn * 1024 + c];
        tile[threadIdx.x][nl] = fmaxf((v - m) * sc + bb, 0.f);
    }
    __syncthreads();
#pragma unroll
    for (int j = 0; j < 4; j++) {
        int cl = threadIdx.y + j * 8;
        out[((size_t)b * 1024 + c0 + cl) * 1024 + n0 + threadIdx.x] = tile[cl][threadIdx.x];
    }
}

// ================= host orchestration ===========================================
extern "C" void kernel_launch(void* const* d_in, const int* in_sizes, int n_in,
                              void* d_out, int out_size) {
    const float* xyz = (const float*)d_in[0];
    const float* W1  = (const float*)d_in[1];
    const float* g1  = (const float*)d_in[2];
    const float* b1  = (const float*)d_in[3];
    const float* W2  = (const float*)d_in[4];
    const float* g2  = (const float*)d_in[5];
    const float* b2  = (const float*)d_in[6];
    const float* WA1 = (const float*)d_in[7];
    const float* gA1 = (const float*)d_in[8];
    const float* bA1 = (const float*)d_in[9];
    const float* WA2 = (const float*)d_in[10];
    const float* gA2 = (const float*)d_in[11];
    const float* bA2 = (const float*)d_in[12];
    const float* WB1 = (const float*)d_in[13];
    const float* gB1 = (const float*)d_in[14];
    const float* bB1 = (const float*)d_in[15];
    const float* WB2 = (const float*)d_in[16];
    const float* gB2 = (const float*)d_in[17];
    const float* bB2 = (const float*)d_in[18];
    float* out = (float*)d_out;

    float *h1, *h2, *Q, *R, *mx, *sumb, *ssb;
    __half *h1h, *h1l, *h2h, *h2l, *l0h, *l0l, *Ah, *Al;
    __half *W2h, *W2l, *WA1h, *WA1l, *WA2h, *WA2l, *WB1h, *WB1l, *WB2h, *WB2l;
    int* idx;
    cudaGetSymbolAddress((void**)&h1, d_h1);   cudaGetSymbolAddress((void**)&h1h, d_h1h);
    cudaGetSymbolAddress((void**)&h1l, d_h1l); cudaGetSymbolAddress((void**)&h2, d_h2);
    cudaGetSymbolAddress((void**)&h2h, d_h2h); cudaGetSymbolAddress((void**)&h2l, d_h2l);
    cudaGetSymbolAddress((void**)&l0h, d_l0h); cudaGetSymbolAddress((void**)&l0l, d_l0l);
    cudaGetSymbolAddress((void**)&idx, d_idx); cudaGetSymbolAddress((void**)&Q, d_Q);
    cudaGetSymbolAddress((void**)&R, d_R);     cudaGetSymbolAddress((void**)&mx, d_mx);
    cudaGetSymbolAddress((void**)&Ah, d_Ah);   cudaGetSymbolAddress((void**)&Al, d_Al);
    cudaGetSymbolAddress((void**)&W2h, d_W2h);   cudaGetSymbolAddress((void**)&W2l, d_W2l);
    cudaGetSymbolAddress((void**)&WA1h, d_WA1h); cudaGetSymbolAddress((void**)&WA1l, d_WA1l);
    cudaGetSymbolAddress((void**)&WA2h, d_WA2h); cudaGetSymbolAddress((void**)&WA2l, d_WA2l);
    cudaGetSymbolAddress((void**)&WB1h, d_WB1h); cudaGetSymbolAddress((void**)&WB1l, d_WB1l);
    cudaGetSymbolAddress((void**)&WB2h, d_WB2h); cudaGetSymbolAddress((void**)&WB2l, d_WB2l);
    cudaGetSymbolAddress((void**)&sumb, d_sum);  cudaGetSymbolAddress((void**)&ssb, d_ss);

    // stat slices: 0=layer1, 1=layer2, 2=expandA, 3=gemm2A, 4=expandB, 5=gemm2B
    float* S[6];  float* Q_[6];
    for (int i = 0; i < 6; i++) { S[i] = sumb + 1024 * i; Q_[i] = ssb + 1024 * i; }

    cudaFuncSetAttribute(gemm_hmma_kernel,
                         cudaFuncAttributeMaxDynamicSharedMemorySize, GSMEM_DYN);
    cudaFuncSetAttribute(gemm_hmma2_kernel<3>,
                         cudaFuncAttributeMaxDynamicSharedMemorySize, H2C<3>::SMEM);
    cudaFuncSetAttribute(gemm_hmma2_kernel<1>,
                         cudaFuncAttributeMaxDynamicSharedMemorySize, H2C<1>::SMEM);
    const int T = 256;

    // (1) all weight splits + zero all stats
    splitzero_kernel<<<2588, T>>>(W2, W2h, W2l, WA1, WA1h, WA1l, WA2, WA2h, WA2l,
                                  WB1, WB1h, WB1l, WB2, WB2h, WB2l, sumb, ssb);
    // layer 1
    lin1_kernel<<<2048, T>>>(xyz, W1, h1);
    colstats_kernel<<<dim3(16, 1), T>>>(h1, 8192, 64, S[0], Q_[0]);
    bnrelu_split_kernel<<<512, T>>>(h1, S[0], Q_[0], g1, b1, h1h, h1l, 8192, 8192, 64);
    // layer 2 GEMM (3-product, fused stats)
    gemm_hmma_kernel<<<dim3(1, 64, 1), T, GSMEM_DYN>>>(
        h1h, h1l, 64, W2h, W2l, nullptr, nullptr, 64,
        h2, nullptr, 256, 64, S[1], Q_[1]);
    // kNN
    knn_kernel<<<dim3(4, 8), T>>>(xyz, idx);
    bnrelu_split_kernel<<<2048, T>>>(h2, S[1], Q_[1], g2, b2, h2h, h2l, 8192, 8192, 256);

    // ---- local_op A: QR 3-product (fused z), GEMM2-A 3-product (256x128) ----
    gemm_hmma_kernel<<<dim3(2, 64, 2), T, GSMEM_DYN>>>(
        h2h, h2l, 256, WA1h, WA1l, WA1h + 256, WA1l + 256, 512,
        Q, R, 512, 256, nullptr, nullptr);
    expand_stats_kernel<<<dim3(256, 1), 128>>>((const float4*)Q, (const float4*)R, idx,
                                               128, S[2], Q_[2]);
    expand_bnrelu_split_kernel<true><<<dim3(256, 1), 128>>>(
        (const float4*)Q, (const float4*)R, idx, 128, S[2], Q_[2], gA1, bA1, Ah, Al);
    gemm_hmma2_kernel<3><<<dim3(4, 256), T, H2C<3>::SMEM>>>(
        Ah, Al, 512, WA2h, WA2l, 512, mx, 512, 512, S[3], Q_[3]);
    finish_split_kernel<<<4096, T>>>(mx, S[3], Q_[3], gA2, bA2, l0h, l0l, 512);

    // ---- local_op B: QR 3-product (fused z), GEMM2-B 1-product (256x128) ----
    gemm_hmma_kernel<<<dim3(4, 64, 2), T, GSMEM_DYN>>>(
        l0h, l0l, 512, WB1h, WB1l, WB1h + 512, WB1l + 512, 1024,
        Q, R, 1024, 512, nullptr, nullptr);
    expand_stats_kernel<<<dim3(256, 2), 128>>>((const float4*)Q, (const float4*)R, idx,
                                               256, S[4], Q_[4]);
    expand_bnrelu_split_kernel<false><<<dim3(256, 2), 128>>>(
        (const float4*)Q, (const float4*)R, idx, 256, S[4], Q_[4], gB1, bB1, Ah, nullptr);
    gemm_hmma2_kernel<1><<<dim3(8, 256), T, H2C<1>::SMEM>>>(
        Ah, nullptr, 1024, WB2h, nullptr, 1024, mx, 1024, 1024, S[5], Q_[5]);
    finish_out_t_kernel<<<dim3(32, 32, 8), dim3(32, 8)>>>(mx, S[5], Q_[5], gB2, bB2, out);
}

// round 17
// speedup vs baseline: 2.1134x; 1.1051x over previous
#include <cuda_runtime.h>
#include <cuda_fp16.h>
#include <cstdint>

#define BN_EPS 1e-5f

// ================= persistent scratch (device globals; no allocations) ==========
__device__ float d_h1[8192 * 64];
__device__ __half d_h1h[8192 * 64], d_h1l[8192 * 64];
__device__ float d_h2[8192 * 256];
__device__ __half d_h2h[8192 * 256], d_h2l[8192 * 256];
__device__ __half d_l0h[8192 * 512], d_l0l[8192 * 512];   // l0 fp16 pair
__device__ int   d_idx[8192 * 8];
__device__ float d_Q[8192 * 1024];
__device__ float d_R[8192 * 1024];
__device__ float d_mx[8192 * 1024];                   // raw max-over-k scratch
__device__ __half d_Ah[65536 * 1024];                 // fp16 hi (expanded)
__device__ __half d_Al[65536 * 512];                  // fp16 lo (expanded; A path only)
__device__ __half d_W2h[256 * 64],     d_W2l[256 * 64];
__device__ __half d_WA1h[512 * 512],   d_WA1l[512 * 512];
__device__ __half d_WA2h[512 * 512],   d_WA2l[512 * 512];
__device__ __half d_WB1h[1024 * 1024], d_WB1l[1024 * 1024];
__device__ __half d_WB2h[1024 * 1024], d_WB2l[1024 * 1024];
__device__ float d_sum[6 * 1024];
__device__ float d_ss[6 * 1024];

// ================= PTX helpers (arch-neutral, sm_80+) ===========================
__device__ __forceinline__ uint32_t smem_u32(const void* p) {
    uint32_t a;
    asm("{ .reg .u64 t; cvta.to.shared.u64 t, %1; cvt.u32.u64 %0, t; }" : "=r"(a) : "l"(p));
    return a;
}
__device__ __forceinline__ void cpa16(uint32_t s, const void* g) {
    asm volatile("cp.async.cg.shared.global [%0], [%1], 16;" :: "r"(s), "l"(g));
}
#define CP_COMMIT() asm volatile("cp.async.commit_group;" ::: "memory")
#define CP_WAIT0()  asm volatile("cp.async.wait_group 0;" ::: "memory")
#define CP_WAIT1()  asm volatile("cp.async.wait_group 1;" ::: "memory")
#define CP_WAIT2()  asm volatile("cp.async.wait_group 2;" ::: "memory")

#define LDSM4(r0, r1, r2, r3, a) \
    asm volatile("ldmatrix.sync.aligned.m8n8.x4.shared.b16 {%0,%1,%2,%3}, [%4];" \
                 : "=r"(r0), "=r"(r1), "=r"(r2), "=r"(r3) : "r"(a))

#define MMA16816(c, a, b) \
    asm volatile("mma.sync.aligned.m16n8k16.row.col.f32.f16.f16.f32 " \
                 "{%0,%1,%2,%3}, {%4,%5,%6,%7}, {%8,%9}, {%0,%1,%2,%3};" \
                 : "+f"((c)[0]), "+f"((c)[1]), "+f"((c)[2]), "+f"((c)[3]) \
                 : "r"((a)[0]), "r"((a)[1]), "r"((a)[2]), "r"((a)[3]), \
                   "r"((b)[0]), "r"((b)[1]))

// ================= HMMA GEMM (128M x 256N), C-writer ============================
// Products: Ah*Bh + (BLO? Ah*Bl) + Al*Bh. gridDim.z=2 fuses 2 GEMMs sharing A.
// Layout: Ah @0 (10240) | Al @10240 | Bh @20480 (20480) | Bl @40960 (BLO).
#define GBK 32
template <bool BLO> struct GC {
    static constexpr uint32_t STG  = BLO ? 61440u : 40960u;
    static constexpr int      NST  = BLO ? 3 : 4;
    static constexpr int      SMEM = (int)(STG * NST);
};

template <bool BLO>
__device__ __forceinline__ void g_load_stage(uint32_t st,
        const __half* Ah, const __half* Al, int lda,
        const __half* Bh, const __half* Bl, int ldb,
        int bm, int bn, int kc, int tid) {
#pragma unroll
    for (int t = 0; t < 2; t++) {                 // A: 512 16B chunks per half
        int i = tid + t * 256;
        int row = i >> 2, cg = i & 3;
        uint32_t off = (uint32_t)(row * 80 + cg * 16);
        size_t ga = (size_t)(bm + row) * lda + kc + cg * 8;
        cpa16(st + off, Ah + ga);
        cpa16(st + 10240u + off, Al + ga);
    }
#pragma unroll
    for (int t = 0; t < 4; t++) {                 // B: 1024 16B chunks per half
        int i = tid + t * 256;
        int row = i >> 2, cg = i & 3;
        uint32_t off = (uint32_t)(row * 80 + cg * 16);
        size_t gb = (size_t)(bn + row) * ldb + kc + cg * 8;
        cpa16(st + 20480u + off, Bh + gb);
        if (BLO) cpa16(st + 40960u + off, Bl + gb);
    }
}

template <bool BLO>
__global__ void __launch_bounds__(256, 1)
gemm_hmma_kernel(const __half* __restrict__ Ah, const __half* __restrict__ Al, int lda,
                 const __half* __restrict__ Bh_, const __half* __restrict__ Bl_,
                 const __half* __restrict__ Bh2, const __half* __restrict__ Bl2, int ldb,
                 float* __restrict__ C_, float* __restrict__ C2, int ldc, int K,
                 float* __restrict__ gsum, float* __restrict__ gss) {
    constexpr uint32_t STG = GC<BLO>::STG;
    constexpr int NST = GC<BLO>::NST;
    extern __shared__ char smem[];
    __shared__ float s_sum[256], s_ss[256];
    const int tid = threadIdx.x;
    const int lane = tid & 31, wid = tid >> 5;
    const int wm = wid & 1, wn = wid >> 1;           // 2 x 4 warp grid, 64x64 tiles
    const int bm = blockIdx.y * 128, bn = blockIdx.x * 256;
    const uint32_t sb = smem_u32(smem);

    const __half* Bh = (blockIdx.z == 0) ? Bh_ : Bh2;
    const __half* Bl = (blockIdx.z == 0) ? Bl_ : Bl2;
    float* C = (blockIdx.z == 0) ? C_ : C2;

    if (gsum) { s_sum[tid] = 0.f; s_ss[tid] = 0.f; }

    float acc[4][8][4];
#pragma unroll
    for (int i = 0; i < 4; i++)
#pragma unroll
        for (int j = 0; j < 8; j++)
#pragma unroll
            for (int v = 0; v < 4; v++) acc[i][j][v] = 0.f;

    const uint32_t a_off = (uint32_t)((wm * 64 + (lane & 15)) * 80 + (lane >> 4) * 16);
    const int b_n = wn * 64 + (lane & 7) + ((lane >> 4) << 3);
    const uint32_t b_koff = (uint32_t)(((lane >> 3) & 1) * 16);

    const int NC = K / GBK;

#pragma unroll
    for (int s = 0; s < NST - 1; s++) {
        if (s < NC) {
            g_load_stage<BLO>(sb + (uint32_t)s * STG, Ah, Al, lda, Bh, Bl, ldb,
                              bm, bn, s * GBK, tid);
            CP_COMMIT();
        }
    }

    for (int c = 0; c < NC; c++) {
        int inflight = min(NC, c + NST - 1) - c - 1;   // groups ahead still wanted
        if (inflight >= 2) CP_WAIT2();
        else if (inflight == 1) CP_WAIT1();
        else CP_WAIT0();
        __syncthreads();
        if (c + NST - 1 < NC) {
            g_load_stage<BLO>(sb + (uint32_t)((c + NST - 1) % NST) * STG, Ah, Al, lda,
                              Bh, Bl, ldb, bm, bn, (c + NST - 1) * GBK, tid);
            CP_COMMIT();
        }
        uint32_t st = sb + (uint32_t)(c % NST) * STG;
#pragma unroll
        for (int kk = 0; kk < 2; kk++) {
            uint32_t kb = (uint32_t)(kk * 32);
            uint32_t bh[8][2], bl[8][2];
#pragma unroll
            for (int p = 0; p < 4; p++) {
                uint32_t ba = st + 20480u + (uint32_t)((b_n + p * 16) * 80) + b_koff + kb;
                LDSM4(bh[2 * p][0], bh[2 * p][1], bh[2 * p + 1][0], bh[2 * p + 1][1], ba);
                if (BLO)
                    LDSM4(bl[2 * p][0], bl[2 * p][1], bl[2 * p + 1][0], bl[2 * p + 1][1],
                          ba + 20480u);
            }
#pragma unroll
            for (int mt = 0; mt < 4; mt++) {
                uint32_t ah[4], al[4];
                uint32_t aa = st + a_off + (uint32_t)(mt * 16 * 80) + kb;
                LDSM4(ah[0], ah[1], ah[2], ah[3], aa);
                LDSM4(al[0], al[1], al[2], al[3], aa + 10240u);
#pragma unroll
                for (int nt = 0; nt < 8; nt++) {
                    MMA16816(acc[mt][nt], ah, bh[nt]);
                    if (BLO) MMA16816(acc[mt][nt], ah, bl[nt]);
                    MMA16816(acc[mt][nt], al, bh[nt]);
                }
            }
        }
    }

#pragma unroll
    for (int mt = 0; mt < 4; mt++) {
        int row = bm + wm * 64 + mt * 16 + (lane >> 2);
#pragma unroll
        for (int nt = 0; nt < 8; nt++) {
            int col = bn + wn * 64 + nt * 8 + (lane & 3) * 2;
            float2 v0 = { acc[mt][nt][0], acc[mt][nt][1] };
            float2 v1 = { acc[mt][nt][2], acc[mt][nt][3] };
            *(float2*)(C + (size_t)row * ldc + col) = v0;
            *(float2*)(C + (size_t)(row + 8) * ldc + col) = v1;
        }
    }
    if (gsum) {
#pragma unroll
        for (int nt = 0; nt < 8; nt++) {
            float se = 0.f, so = 0.f, qe = 0.f, qo = 0.f;
#pragma unroll
            for (int mt = 0; mt < 4; mt++) {
                float e0 = acc[mt][nt][0], e1 = acc[mt][nt][1];
                float e2 = acc[mt][nt][2], e3 = acc[mt][nt][3];
                se += e0 + e2; so += e1 + e3;
                qe += e0 * e0 + e2 * e2; qo += e1 * e1 + e3 * e3;
            }
#pragma unroll
            for (int off = 4; off < 32; off <<= 1) {
                se += __shfl_xor_sync(0xFFFFFFFFu, se, off);
                so += __shfl_xor_sync(0xFFFFFFFFu, so, off);
                qe += __shfl_xor_sync(0xFFFFFFFFu, qe, off);
                qo += __shfl_xor_sync(0xFFFFFFFFu, qo, off);
            }
            if (lane < 4) {
                int cl = wn * 64 + nt * 8 + lane * 2;
                atomicAdd(&s_sum[cl], se);     atomicAdd(&s_sum[cl + 1], so);
                atomicAdd(&s_ss[cl], qe);      atomicAdd(&s_ss[cl + 1], qo);
            }
        }
        __syncthreads();
        atomicAdd(&gsum[bn + tid], s_sum[tid]);
        atomicAdd(&gss[bn + tid], s_ss[tid]);
    }
}

// ================= HMMA GEMM (256M x 128N), max epilogue ========================
// Products: Ah*Bh + (BLO? Ah*Bl) + (ALO? Al*Bh).
// Layout: Ah @0 (20480) | Al @20480 (ALO) | Bh @B_OFF (10240) | Bl @B_OFF+10240.
template <bool ALO, bool BLO> struct H2C {
    static constexpr uint32_t B_OFF = 20480u + (ALO ? 20480u : 0u);
    static constexpr uint32_t STG   = B_OFF + 10240u + (BLO ? 10240u : 0u);
    static constexpr int      NST   = (ALO || BLO) ? 3 : 4;
    static constexpr int      SMEM  = (int)(STG * NST);
};

template <bool ALO, bool BLO>
__device__ __forceinline__ void h2_load_stage(uint32_t st,
        const __half* Ah, const __half* Al, int lda,
        const __half* Bh, const __half* Bl, int ldb,
        int bm, int bn, int kc, int tid) {
#pragma unroll
    for (int t = 0; t < 4; t++) {                 // A: 1024 16B chunks per half
        int i = tid + t * 256;
        int row = i >> 2, cg = i & 3;
        uint32_t off = (uint32_t)(row * 80 + cg * 16);
        size_t ga = (size_t)(bm + row) * lda + kc + cg * 8;
        cpa16(st + off, Ah + ga);
        if (ALO) cpa16(st + 20480u + off, Al + ga);
    }
#pragma unroll
    for (int t = 0; t < 2; t++) {                 // B: 512 16B chunks per half
        int i = tid + t * 256;
        int row = i >> 2, cg = i & 3;
        uint32_t off = (uint32_t)(row * 80 + cg * 16);
        size_t gb = (size_t)(bn + row) * ldb + kc + cg * 8;
        cpa16(st + H2C<ALO, BLO>::B_OFF + off, Bh + gb);
        if (BLO) cpa16(st + H2C<ALO, BLO>::B_OFF + 10240u + off, Bl + gb);
    }
}

template <bool ALO, bool BLO>
__global__ void __launch_bounds__(256, 1)
gemm_hmma2_kernel(const __half* __restrict__ Ah, const __half* __restrict__ Al, int lda,
                  const __half* __restrict__ Bh, const __half* __restrict__ Bl, int ldb,
                  float* __restrict__ maxout, int ldc, int K,
                  float* __restrict__ gsum, float* __restrict__ gss) {
    constexpr uint32_t STG = H2C<ALO, BLO>::STG;
    constexpr int NST = H2C<ALO, BLO>::NST;
    extern __shared__ char smem[];
    __shared__ float s_sum[128], s_ss[128];
    const int tid = threadIdx.x;
    const int lane = tid & 31, wid = tid >> 5;
    const int wm = wid & 3, wn = wid >> 2;           // 4 x 2 warp grid, 64x64 tiles
    const int bm = blockIdx.y * 256, bn = blockIdx.x * 128;
    const uint32_t sb = smem_u32(smem);

    if (tid < 128) { s_sum[tid] = 0.f; s_ss[tid] = 0.f; }

    float acc[4][8][4];
#pragma unroll
    for (int i = 0; i < 4; i++)
#pragma unroll
        for (int j = 0; j < 8; j++)
#pragma unroll
            for (int v = 0; v < 4; v++) acc[i][j][v] = 0.f;

    const uint32_t a_off = (uint32_t)((wm * 64 + (lane & 15)) * 80 + (lane >> 4) * 16);
    const int b_n = wn * 64 + (lane & 7) + ((lane >> 4) << 3);
    const uint32_t b_koff = (uint32_t)(((lane >> 3) & 1) * 16);

    const int NC = K / GBK;          // >= 16 for all uses

#pragma unroll
    for (int s = 0; s < NST - 1; s++) {
        h2_load_stage<ALO, BLO>(sb + (uint32_t)s * STG, Ah, Al, lda, Bh, Bl, ldb,
                                bm, bn, s * GBK, tid);
        CP_COMMIT();
    }

    for (int c = 0; c < NC; c++) {
        int inflight = min(NC, c + NST - 1) - c - 1;
        if (inflight >= 2) CP_WAIT2();
        else if (inflight == 1) CP_WAIT1();
        else CP_WAIT0();
        __syncthreads();
        if (c + NST - 1 < NC) {
            h2_load_stage<ALO, BLO>(sb + (uint32_t)((c + NST - 1) % NST) * STG,
                                    Ah, Al, lda, Bh, Bl, ldb, bm, bn,
                                    (c + NST - 1) * GBK, tid);
            CP_COMMIT();
        }
        uint32_t st = sb + (uint32_t)(c % NST) * STG;
#pragma unroll
        for (int kk = 0; kk < 2; kk++) {
            uint32_t kb = (uint32_t)(kk * 32);
            uint32_t bh[8][2], bl[8][2];
#pragma unroll
            for (int p = 0; p < 4; p++) {
                uint32_t ba = st + H2C<ALO, BLO>::B_OFF +
                              (uint32_t)((b_n + p * 16) * 80) + b_koff + kb;
                LDSM4(bh[2 * p][0], bh[2 * p][1], bh[2 * p + 1][0], bh[2 * p + 1][1], ba);
                if (BLO)
                    LDSM4(bl[2 * p][0], bl[2 * p][1], bl[2 * p + 1][0], bl[2 * p + 1][1],
                          ba + 10240u);
            }
#pragma unroll
            for (int mt = 0; mt < 4; mt++) {
                uint32_t ah[4], al[4];
                uint32_t aa = st + a_off + (uint32_t)(mt * 16 * 80) + kb;
                LDSM4(ah[0], ah[1], ah[2], ah[3], aa);
                if (ALO) LDSM4(al[0], al[1], al[2], al[3], aa + 20480u);
#pragma unroll
                for (int nt = 0; nt < 8; nt++) {
                    MMA16816(acc[mt][nt], ah, bh[nt]);
                    if (BLO) MMA16816(acc[mt][nt], ah, bl[nt]);
                    if (ALO) MMA16816(acc[mt][nt], al, bh[nt]);
                }
            }
        }
    }

    // epilogue: fused raw max over k=8 groups + column stats
#pragma unroll
    for (int mt = 0; mt < 4; mt++) {
        int gA = (bm + wm * 64 + mt * 16) >> 3;
#pragma unroll
        for (int nt = 0; nt < 8; nt++) {
            float m0 = acc[mt][nt][0], m1 = acc[mt][nt][1];
            float m2 = acc[mt][nt][2], m3 = acc[mt][nt][3];
#pragma unroll
            for (int off = 4; off < 32; off <<= 1) {
                m0 = fmaxf(m0, __shfl_xor_sync(0xFFFFFFFFu, m0, off));
                m1 = fmaxf(m1, __shfl_xor_sync(0xFFFFFFFFu, m1, off));
                m2 = fmaxf(m2, __shfl_xor_sync(0xFFFFFFFFu, m2, off));
                m3 = fmaxf(m3, __shfl_xor_sync(0xFFFFFFFFu, m3, off));
            }
            if (lane < 4) {
                int col = bn + wn * 64 + nt * 8 + lane * 2;
                float2 v0 = { m0, m1 }, v1 = { m2, m3 };
                *(float2*)(maxout + (size_t)gA * ldc + col) = v0;
                *(float2*)(maxout + (size_t)(gA + 1) * ldc + col) = v1;
            }
        }
    }
#pragma unroll
    for (int nt = 0; nt < 8; nt++) {
        float se = 0.f, so = 0.f, qe = 0.f, qo = 0.f;
#pragma unroll
        for (int mt = 0; mt < 4; mt++) {
            float e0 = acc[mt][nt][0], e1 = acc[mt][nt][1];
            float e2 = acc[mt][nt][2], e3 = acc[mt][nt][3];
            se += e0 + e2; so += e1 + e3;
            qe += e0 * e0 + e2 * e2; qo += e1 * e1 + e3 * e3;
        }
#pragma unroll
        for (int off = 4; off < 32; off <<= 1) {
            se += __shfl_xor_sync(0xFFFFFFFFu, se, off);
            so += __shfl_xor_sync(0xFFFFFFFFu, so, off);
            qe += __shfl_xor_sync(0xFFFFFFFFu, qe, off);
            qo += __shfl_xor_sync(0xFFFFFFFFu, qo, off);
        }
        if (lane < 4) {
            int cl = wn * 64 + nt * 8 + lane * 2;
            atomicAdd(&s_sum[cl], se);     atomicAdd(&s_sum[cl + 1], so);
            atomicAdd(&s_ss[cl], qe);      atomicAdd(&s_ss[cl + 1], qo);
        }
    }
    __syncthreads();
    if (tid < 128) {
        atomicAdd(&gsum[bn + tid], s_sum[tid]);
        atomicAdd(&gss[bn + tid], s_ss[tid]);
    }
}

// ================= small elementwise / stats kernels ============================
__device__ __forceinline__ uint32_t pk_h2(float a, float b) {
    __half2 t = __floats2half2_rn(a, b);
    return *(uint32_t*)&t;
}

__device__ __forceinline__ void split4(const float* __restrict__ x,
                                       __half* __restrict__ hi, __half* __restrict__ lo,
                                       int t) {
    float4 v = ((const float4*)x)[t];
    float o[4] = { v.x, v.y, v.z, v.w };
    float h[4];
#pragma unroll
    for (int i = 0; i < 4; i++) h[i] = __half2float(__float2half_rn(o[i]));
    uint2 H = { pk_h2(o[0], o[1]), pk_h2(o[2], o[3]) };
    uint2 L = { pk_h2(o[0] - h[0], o[1] - h[1]), pk_h2(o[2] - h[2], o[3] - h[3]) };
    ((uint2*)hi)[t] = H;
    ((uint2*)lo)[t] = L;
}

// combined: all 5 weight splits + zero all 6 stat buffer pairs.
__global__ void splitzero_kernel(
        const float* W2, __half* W2h, __half* W2l,
        const float* WA1, __half* WA1h, __half* WA1l,
        const float* WA2, __half* WA2h, __half* WA2l,
        const float* WB1, __half* WB1h, __half* WB1l,
        const float* WB2, __half* WB2h, __half* WB2l,
        float* sum, float* ss) {
    int t = blockIdx.x * 256 + threadIdx.x;
    if (t < 4096)          split4(W2,  W2h,  W2l,  t);
    else if (t < 69632)    split4(WA1, WA1h, WA1l, t - 4096);
    else if (t < 135168)   split4(WA2, WA2h, WA2l, t - 69632);
    else if (t < 397312)   split4(WB1, WB1h, WB1l, t - 135168);
    else if (t < 659456)   split4(WB2, WB2h, WB2l, t - 397312);
    else if (t < 660992)   ((float4*)sum)[t - 659456] = make_float4(0.f, 0.f, 0.f, 0.f);
    else if (t < 662528)   ((float4*)ss)[t - 660992]  = make_float4(0.f, 0.f, 0.f, 0.f);
}

__global__ void lin1_kernel(const float* __restrict__ xyz, const float* __restrict__ W1,
                            float* __restrict__ out) {
    int t = blockIdx.x * blockDim.x + threadIdx.x;
    int r = t >> 6, o = t & 63;
    float x0 = xyz[r * 3 + 0], x1 = xyz[r * 3 + 1], x2 = xyz[r * 3 + 2];
    out[t] = x0 * W1[o * 3 + 0] + x1 * W1[o * 3 + 1] + x2 * W1[o * 3 + 2];
}

__global__ void colstats_kernel(const float* __restrict__ x, int M, int C,
                                float* __restrict__ sum, float* __restrict__ ss) {
    int c = blockIdx.y * blockDim.x + threadIdx.x;
    if (c >= C) return;
    size_t r0 = (size_t)blockIdx.x * 512;
    const float* p = x + r0 * C + c;
    float s = 0.f, q = 0.f;
    for (int r = 0; r < 512; r++) { float v = p[(size_t)r * C]; s += v; q += v * v; }
    atomicAdd(&sum[c], s);
    atomicAdd(&ss[c], q);
}

// BN + ReLU + hi/lo fp16 split (reads fp32 once, writes fp16 pair).
__global__ void bnrelu_split_kernel(const float* __restrict__ x,
                                    const float* __restrict__ sum, const float* __restrict__ ss,
                                    const float* __restrict__ g, const float* __restrict__ bta,
                                    __half* __restrict__ hi, __half* __restrict__ lo,
                                    int Mstat, int Mrows, int C) {
    int t = blockIdx.x * blockDim.x + threadIdx.x;
    int C4 = C >> 2;
    if (t >= Mrows * C4) return;
    int c = (t % C4) << 2;
    float invM = 1.0f / (float)Mstat;
    float4 v = ((const float4*)x)[t];
    float vv[4] = { v.x, v.y, v.z, v.w };
    float o[4];
#pragma unroll
    for (int i = 0; i < 4; i++) {
        float m = sum[c + i] * invM;
        float var = ss[c + i] * invM - m * m;
        float sc = g[c + i] * rsqrtf(var + BN_EPS);
        o[i] = fmaxf((vv[i] - m) * sc + bta[c + i], 0.f);
    }
    float h[4];
#pragma unroll
    for (int i = 0; i < 4; i++) h[i] = __half2float(__float2half_rn(o[i]));
    uint2 H = { pk_h2(o[0], o[1]), pk_h2(o[2], o[3]) };
    uint2 L = { pk_h2(o[0] - h[0], o[1] - h[1]), pk_h2(o[2] - h[2], o[3] - h[3]) };
    ((uint2*)hi)[t] = H;
    ((uint2*)lo)[t] = L;
}

// kNN: k=8 smallest (stable ties, matches top_k(-d2))
__global__ void knn_kernel(const float* __restrict__ xyz, int* __restrict__ idx) {
    __shared__ float sx[1024], sy[1024], sz[1024], sq[1024];
    int b = blockIdx.y, tid = threadIdx.x;
    for (int i = tid; i < 1024; i += 256) {
        float x = xyz[((b << 10) + i) * 3 + 0];
        float y = xyz[((b << 10) + i) * 3 + 1];
        float z = xyz[((b << 10) + i) * 3 + 2];
        sx[i] = x; sy[i] = y; sz[i] = z;
        sq[i] = x * x + y * y + z * z;
    }
    __syncthreads();
    int n = blockIdx.x * 256 + tid;
    float qx = sx[n], qy = sy[n], qz = sz[n], qs = sq[n];
    float bd[8]; int bi[8];
#pragma unroll
    for (int j = 0; j < 8; j++) { bd[j] = 3.4e38f; bi[j] = 0; }
    for (int m = 0; m < 1024; m++) {
        float d2 = qs + sq[m] - 2.f * (qx * sx[m] + qy * sy[m] + qz * sz[m]);
        if (d2 < bd[7]) {
            bd[7] = d2; bi[7] = m;
#pragma unroll
            for (int j = 7; j > 0; j--) {
                if (bd[j] < bd[j - 1]) {
                    float td = bd[j]; bd[j] = bd[j - 1]; bd[j - 1] = td;
                    int ti = bi[j]; bi[j] = bi[j - 1]; bi[j - 1] = ti;
                }
            }
        }
    }
#pragma unroll
    for (int j = 0; j < 8; j++) idx[((b << 10) + n) * 8 + j] = bi[j];
}

// expand stats only: o = Q[idx]-Qc+Rc, column sum/sumsq.
__global__ void expand_stats_kernel(const float4* __restrict__ Q, const float4* __restrict__ R,
                                    const int* __restrict__ idx, int C4,
                                    float* __restrict__ gsum, float* __restrict__ gss) {
    __shared__ int sidx[256];
    int c4 = blockIdx.y * 128 + threadIdx.x;
    int r0 = blockIdx.x * 256;
    for (int i = threadIdx.x; i < 256; i += 128) sidx[i] = idx[r0 + i];
    __syncthreads();
    int bn0 = r0 >> 3;
    int b = bn0 >> 10;
    float s[4] = {0.f, 0.f, 0.f, 0.f}, q[4] = {0.f, 0.f, 0.f, 0.f};
    for (int gg = 0; gg < 32; gg++) {
        int bn = bn0 + gg;
        float4 qc = Q[(size_t)bn * C4 + c4];
        float4 rr = R[(size_t)bn * C4 + c4];
        float bx = rr.x - qc.x, by = rr.y - qc.y, bz = rr.z - qc.z, bw = rr.w - qc.w;
#pragma unroll
        for (int k = 0; k < 8; k++) {
            int src = (b << 10) + sidx[gg * 8 + k];
            float4 qa = Q[(size_t)src * C4 + c4];
            float ox = qa.x + bx, oy = qa.y + by, oz = qa.z + bz, ow = qa.w + bw;
            s[0] += ox; s[1] += oy; s[2] += oz; s[3] += ow;
            q[0] += ox * ox; q[1] += oy * oy; q[2] += oz * oz; q[3] += ow * ow;
        }
    }
    int c = c4 << 2;
#pragma unroll
    for (int i = 0; i < 4; i++) { atomicAdd(&gsum[c + i], s[i]); atomicAdd(&gss[c + i], q[i]); }
}

// expand recompute + BN + ReLU + fp16 split (WRITE_LO=false -> hi only).
template <bool WRITE_LO>
__global__ void expand_bnrelu_split_kernel(
        const float4* __restrict__ Q, const float4* __restrict__ R,
        const int* __restrict__ idx, int C4,
        const float* __restrict__ sum, const float* __restrict__ ss,
        const float* __restrict__ g, const float* __restrict__ bta,
        __half* __restrict__ hi, __half* __restrict__ lo) {
    __shared__ int sidx[256];
    int c4 = blockIdx.y * 128 + threadIdx.x;
    int r0 = blockIdx.x * 256;
    for (int i = threadIdx.x; i < 256; i += 128) sidx[i] = idx[r0 + i];
    __syncthreads();
    int bn0 = r0 >> 3;
    int b = bn0 >> 10;
    const float invM = 1.0f / 65536.0f;
    int c = c4 << 2;
    float m[4], sc[4], bb[4];
#pragma unroll
    for (int i = 0; i < 4; i++) {
        m[i] = sum[c + i] * invM;
        float var = ss[c + i] * invM - m[i] * m[i];
        sc[i] = g[c + i] * rsqrtf(var + BN_EPS);
        bb[i] = bta[c + i];
    }
    for (int gg = 0; gg < 32; gg++) {
        int bn = bn0 + gg;
        float4 qc = Q[(size_t)bn * C4 + c4];
        float4 rr = R[(size_t)bn * C4 + c4];
        float bx = rr.x - qc.x, by = rr.y - qc.y, bz = rr.z - qc.z, bw = rr.w - qc.w;
#pragma unroll
        for (int k = 0; k < 8; k++) {
            int row = bn * 8 + k;
            int src = (b << 10) + sidx[gg * 8 + k];
            float4 qa = Q[(size_t)src * C4 + c4];
            float o[4] = { qa.x + bx, qa.y + by, qa.z + bz, qa.w + bw };
            float h[4];
#pragma unroll
            for (int i = 0; i < 4; i++) {
                o[i] = fmaxf((o[i] - m[i]) * sc[i] + bb[i], 0.f);
                h[i] = __half2float(__float2half_rn(o[i]));
            }
            uint2 H = { pk_h2(o[0], o[1]), pk_h2(o[2], o[3]) };
            ((uint2*)hi)[(size_t)row * C4 + c4] = H;
            if (WRITE_LO) {
                uint2 L = { pk_h2(o[0] - h[0], o[1] - h[1]),
                            pk_h2(o[2] - h[2], o[3] - h[3]) };
                ((uint2*)lo)[(size_t)row * C4 + c4] = L;
            }
        }
    }
}

// finish: BN+ReLU of raw max (stats over 65536 raw rows) -> fp16 PAIR (l0)
__global__ void finish_split_kernel(const float* __restrict__ mx,
                                    const float* __restrict__ sum, const float* __restrict__ ss,
                                    const float* __restrict__ g, const float* __restrict__ bta,
                                    __half* __restrict__ hi, __half* __restrict__ lo, int C) {
    int t = blockIdx.x * blockDim.x + threadIdx.x;
    int C4 = C >> 2;
    if (t >= 8192 * C4) return;
    int c = (t % C4) << 2;
    const float invM = 1.0f / 65536.0f;
    float4 v = ((const float4*)mx)[t];
    float vv[4] = { v.x, v.y, v.z, v.w };
    float o[4], h[4];
#pragma unroll
    for (int i = 0; i < 4; i++) {
        float m = sum[c + i] * invM;
        float var = ss[c + i] * invM - m * m;
        float sc = g[c + i] * rsqrtf(var + BN_EPS);
        o[i] = fmaxf((vv[i] - m) * sc + bta[c + i], 0.f);
        h[i] = __half2float(__float2half_rn(o[i]));
    }
    uint2 H = { pk_h2(o[0], o[1]), pk_h2(o[2], o[3]) };
    uint2 L = { pk_h2(o[0] - h[0], o[1] - h[1]), pk_h2(o[2] - h[2], o[3] - h[3]) };
    ((uint2*)hi)[t] = H;
    ((uint2*)lo)[t] = L;
}

// finish: BN+ReLU of raw max + transpose to (B, C, N). C=1024.
__global__ void finish_out_t_kernel(const float* __restrict__ mx,
                                    const float* __restrict__ sum, const float* __restrict__ ss,
                                    const float* __restrict__ g, const float* __restrict__ bta,
                                    float* __restrict__ out) {
    __shared__ float tile[32][33];
    int b = blockIdx.z;
    int n0 = blockIdx.x * 32;
    int c0 = blockIdx.y * 32;
    int c = c0 + threadIdx.x;
    const float invM = 1.0f / 65536.0f;
    float m = sum[c] * invM;
    float var = ss[c] * invM - m * m;
    float sc = g[c] * rsqrtf(var + BN_EPS);
    float bb = bta[c];
#pragma unroll
    for (int j = 0; j < 4; j++) {
        int nl = threadIdx.y + j * 8;
        int bn = (b << 10) + n0 + nl;
        float v = mx[(size_t)bn * 1024 + c];
        tile[threadIdx.x][nl] = fmaxf((v - m) * sc + bb, 0.f);
    }
    __syncthreads();
#pragma unroll
    for (int j = 0; j < 4; j++) {
        int cl = threadIdx.y + j * 8;
        out[((size_t)b * 1024 + c0 + cl) * 1024 + n0 + threadIdx.x] = tile[cl][threadIdx.x];
    }
}

// ================= host orchestration ===========================================
extern "C" void kernel_launch(void* const* d_in, const int* in_sizes, int n_in,
                              void* d_out, int out_size) {
    const float* xyz = (const float*)d_in[0];
    const float* W1  = (const float*)d_in[1];
    const float* g1  = (const float*)d_in[2];
    const float* b1  = (const float*)d_in[3];
    const float* W2  = (const float*)d_in[4];
    const float* g2  = (const float*)d_in[5];
    const float* b2  = (const float*)d_in[6];
    const float* WA1 = (const float*)d_in[7];
    const float* gA1 = (const float*)d_in[8];
    const float* bA1 = (const float*)d_in[9];
    const float* WA2 = (const float*)d_in[10];
    const float* gA2 = (const float*)d_in[11];
    const float* bA2 = (const float*)d_in[12];
    const float* WB1 = (const float*)d_in[13];
    const float* gB1 = (const float*)d_in[14];
    const float* bB1 = (const float*)d_in[15];
    const float* WB2 = (const float*)d_in[16];
    const float* gB2 = (const float*)d_in[17];
    const float* bB2 = (const float*)d_in[18];
    float* out = (float*)d_out;

    float *h1, *h2, *Q, *R, *mx, *sumb, *ssb;
    __half *h1h, *h1l, *h2h, *h2l, *l0h, *l0l, *Ah, *Al;
    __half *W2h, *W2l, *WA1h, *WA1l, *WA2h, *WA2l, *WB1h, *WB1l, *WB2h, *WB2l;
    int* idx;
    cudaGetSymbolAddress((void**)&h1, d_h1);   cudaGetSymbolAddress((void**)&h1h, d_h1h);
    cudaGetSymbolAddress((void**)&h1l, d_h1l); cudaGetSymbolAddress((void**)&h2, d_h2);
    cudaGetSymbolAddress((void**)&h2h, d_h2h); cudaGetSymbolAddress((void**)&h2l, d_h2l);
    cudaGetSymbolAddress((void**)&l0h, d_l0h); cudaGetSymbolAddress((void**)&l0l, d_l0l);
    cudaGetSymbolAddress((void**)&idx, d_idx); cudaGetSymbolAddress((void**)&Q, d_Q);
    cudaGetSymbolAddress((void**)&R, d_R);     cudaGetSymbolAddress((void**)&mx, d_mx);
    cudaGetSymbolAddress((void**)&Ah, d_Ah);   cudaGetSymbolAddress((void**)&Al, d_Al);
    cudaGetSymbolAddress((void**)&W2h, d_W2h);   cudaGetSymbolAddress((void**)&W2l, d_W2l);
    cudaGetSymbolAddress((void**)&WA1h, d_WA1h); cudaGetSymbolAddress((void**)&WA1l, d_WA1l);
    cudaGetSymbolAddress((void**)&WA2h, d_WA2h); cudaGetSymbolAddress((void**)&WA2l, d_WA2l);
    cudaGetSymbolAddress((void**)&WB1h, d_WB1h); cudaGetSymbolAddress((void**)&WB1l, d_WB1l);
    cudaGetSymbolAddress((void**)&WB2h, d_WB2h); cudaGetSymbolAddress((void**)&WB2l, d_WB2l);
    cudaGetSymbolAddress((void**)&sumb, d_sum);  cudaGetSymbolAddress((void**)&ssb, d_ss);

    // stat slices: 0=layer1, 1=layer2, 2=expandA, 3=gemm2A, 4=expandB, 5=gemm2B
    float* S[6];  float* Q_[6];
    for (int i = 0; i < 6; i++) { S[i] = sumb + 1024 * i; Q_[i] = ssb + 1024 * i; }

    cudaFuncSetAttribute(gemm_hmma_kernel<true>,
                         cudaFuncAttributeMaxDynamicSharedMemorySize, GC<true>::SMEM);
    cudaFuncSetAttribute(gemm_hmma_kernel<false>,
                         cudaFuncAttributeMaxDynamicSharedMemorySize, GC<false>::SMEM);
    cudaFuncSetAttribute((const void*)gemm_hmma2_kernel<true, false>,
                         cudaFuncAttributeMaxDynamicSharedMemorySize,
                         H2C<true, false>::SMEM);
    cudaFuncSetAttribute((const void*)gemm_hmma2_kernel<false, false>,
                         cudaFuncAttributeMaxDynamicSharedMemorySize,
                         H2C<false, false>::SMEM);
    const int T = 256;

    // (1) all weight splits + zero all stats
    splitzero_kernel<<<2588, T>>>(W2, W2h, W2l, WA1, WA1h, WA1l, WA2, WA2h, WA2l,
                                  WB1, WB1h, WB1l, WB2, WB2h, WB2l, sumb, ssb);
    // layer 1
    lin1_kernel<<<2048, T>>>(xyz, W1, h1);
    colstats_kernel<<<dim3(16, 1), T>>>(h1, 8192, 64, S[0], Q_[0]);
    bnrelu_split_kernel<<<512, T>>>(h1, S[0], Q_[0], g1, b1, h1h, h1l, 8192, 8192, 64);
    // layer 2 GEMM (full 3-product, fused stats)
    gemm_hmma_kernel<true><<<dim3(1, 64, 1), T, GC<true>::SMEM>>>(
        h1h, h1l, 64, W2h, W2l, nullptr, nullptr, 64,
        h2, nullptr, 256, 64, S[1], Q_[1]);
    // kNN
    knn_kernel<<<dim3(4, 8), T>>>(xyz, idx);
    bnrelu_split_kernel<<<2048, T>>>(h2, S[1], Q_[1], g2, b2, h2h, h2l, 8192, 8192, 256);

    // ---- local_op A: QR (Ah*Bh+Al*Bh), GEMM2-A (Ah*Bh+Al*Bh, 256x128) ----
    gemm_hmma_kernel<false><<<dim3(2, 64, 2), T, GC<false>::SMEM>>>(
        h2h, h2l, 256, WA1h, WA1l, WA1h + 256, WA1l + 256, 512,
        Q, R, 512, 256, nullptr, nullptr);
    expand_stats_kernel<<<dim3(256, 1), 128>>>((const float4*)Q, (const float4*)R, idx,
                                               128, S[2], Q_[2]);
    expand_bnrelu_split_kernel<true><<<dim3(256, 1), 128>>>(
        (const float4*)Q, (const float4*)R, idx, 128, S[2], Q_[2], gA1, bA1, Ah, Al);
    gemm_hmma2_kernel<true, false><<<dim3(4, 256), T, H2C<true, false>::SMEM>>>(
        Ah, Al, 512, WA2h, nullptr, 512, mx, 512, 512, S[3], Q_[3]);
    finish_split_kernel<<<4096, T>>>(mx, S[3], Q_[3], gA2, bA2, l0h, l0l, 512);

    // ---- local_op B: QR (Ah*Bh+Al*Bh), GEMM2-B (Ah*Bh only, 256x128) ----
    gemm_hmma_kernel<false><<<dim3(4, 64, 2), T, GC<false>::SMEM>>>(
        l0h, l0l, 512, WB1h, WB1l, WB1h + 512, WB1l + 512, 1024,
        Q, R, 1024, 512, nullptr, nullptr);
    expand_stats_kernel<<<dim3(256, 2), 128>>>((const float4*)Q, (const float4*)R, idx,
                                               256, S[4], Q_[4]);
    expand_bnrelu_split_kernel<false><<<dim3(256, 2), 128>>>(
        (const float4*)Q, (const float4*)R, idx, 256, S[4], Q_[4], gB1, bB1, Ah, nullptr);
    gemm_hmma2_kernel<false, false><<<dim3(8, 256), T, H2C<false, false>::SMEM>>>(
        Ah, nullptr, 1024, WB2h, nullptr, 1024, mx, 1024, 1024, S[5], Q_[5]);
    finish_out_t_kernel<<<dim3(32, 32, 8), dim3(32, 8)>>>(mx, S[5], Q_[5], gB2, bB2, out);
}